// round 1
// baseline (speedup 1.0000x reference)
#include <cuda_runtime.h>
#include <math.h>

#define NN 50000
#define EE 800000
#define ET (EE + NN)          // edges incl. self-loops
#define HCMAX 726             // max heads*channels (layer 3: 6*121)
#define HMAX 6

// ---------------- device scratch (allocation-free) ----------------
__device__ float g_feat[(size_t)NN * HCMAX];   // h = x @ W
__device__ float g_acc [(size_t)NN * HCMAX];   // segment-sum accumulator
__device__ float g_x   [(size_t)NN * 256];     // layer activations (ping)
__device__ float g_res [(size_t)NN * 256];     // residual branch (layer 2)
__device__ float g_als [NN * HMAX];
__device__ float g_ald [NN * HMAX];
__device__ float g_m   [NN * HMAX];
__device__ float g_s   [NN * HMAX];
__device__ float g_alpha[(size_t)ET * HMAX];

// ---------------- helpers ----------------
__device__ __forceinline__ void atomicMaxFloat(float* addr, float val) {
    // signed-max / unsigned-min trick (valid for non-NaN floats)
    if (val >= 0.0f) atomicMax((int*)addr, __float_as_int(val));
    else             atomicMin((unsigned int*)addr, __float_as_uint(val));
}

// ---------------- GEMM: C[M,Nc] = A[M,K] @ B[K,Nc], fp32, 64x64 tile ----------------
__global__ void gemm64(const float* __restrict__ A, const float* __restrict__ B,
                       float* __restrict__ C, int M, int K, int Nc) {
    __shared__ float As[16][65];   // [k][m], padded
    __shared__ float Bs[16][64];   // [k][n]
    const int tx = threadIdx.x, ty = threadIdx.y;
    const int tid = ty * 16 + tx;
    const int bm = blockIdx.y * 64, bn = blockIdx.x * 64;
    float acc[4][4] = {};

    for (int k0 = 0; k0 < K; k0 += 16) {
#pragma unroll
        for (int r = 0; r < 4; r++) {
            int i  = tid + r * 256;
            int mm = i >> 4, kk = i & 15;
            int gr = bm + mm;
            As[kk][mm] = (gr < M) ? A[(size_t)gr * K + k0 + kk] : 0.0f;
        }
#pragma unroll
        for (int r = 0; r < 4; r++) {
            int i  = tid + r * 256;
            int kk = i >> 6, nn = i & 63;
            int gc = bn + nn;
            Bs[kk][nn] = (gc < Nc) ? B[(size_t)(k0 + kk) * Nc + gc] : 0.0f;
        }
        __syncthreads();
#pragma unroll
        for (int kk = 0; kk < 16; kk++) {
            float a[4], b[4];
#pragma unroll
            for (int i = 0; i < 4; i++) a[i] = As[kk][ty * 4 + i];
#pragma unroll
            for (int j = 0; j < 4; j++) b[j] = Bs[kk][tx * 4 + j];
#pragma unroll
            for (int i = 0; i < 4; i++)
#pragma unroll
                for (int j = 0; j < 4; j++)
                    acc[i][j] += a[i] * b[j];
        }
        __syncthreads();
    }
#pragma unroll
    for (int i = 0; i < 4; i++) {
        int gr = bm + ty * 4 + i;
        if (gr >= M) continue;
#pragma unroll
        for (int j = 0; j < 4; j++) {
            int gc = bn + tx * 4 + j;
            if (gc < Nc) C[(size_t)gr * Nc + gc] = acc[i][j];
        }
    }
}

// ---------------- attention logits: warp per (node, head) ----------------
__global__ void compute_al(const float* __restrict__ feat,
                           const float* __restrict__ a_src,
                           const float* __restrict__ a_dst,
                           float* __restrict__ als, float* __restrict__ ald,
                           int H, int C) {
    int w    = (blockIdx.x * blockDim.x + threadIdx.x) >> 5;
    int lane = threadIdx.x & 31;
    if (w >= NN * H) return;
    int n = w / H, h = w % H;
    const float* f  = feat + (size_t)n * H * C + (size_t)h * C;
    const float* as = a_src + h * C;
    const float* ad = a_dst + h * C;
    float s1 = 0.f, s2 = 0.f;
    for (int c = lane; c < C; c += 32) {
        float v = f[c];
        s1 += v * as[c];
        s2 += v * ad[c];
    }
#pragma unroll
    for (int o = 16; o; o >>= 1) {
        s1 += __shfl_down_sync(0xFFFFFFFFu, s1, o);
        s2 += __shfl_down_sync(0xFFFFFFFFu, s2, o);
    }
    if (lane == 0) { als[w] = s1; ald[w] = s2; }
}

// ---------------- init / zero ----------------
__global__ void init_ms(float* __restrict__ m, float* __restrict__ s, int n) {
    int i = blockIdx.x * blockDim.x + threadIdx.x;
    if (i < n) { m[i] = -1e30f; s[i] = 0.0f; }
}
__global__ void zerof(float* __restrict__ p, size_t n) {
    size_t i = (size_t)blockIdx.x * blockDim.x + threadIdx.x;
    size_t stride = (size_t)gridDim.x * blockDim.x;
    for (; i < n; i += stride) p[i] = 0.0f;
}

// ---------------- edge passes ----------------
__device__ __forceinline__ void edge_sd(int e, const int* __restrict__ src,
                                        const int* __restrict__ dst, int& s, int& d) {
    if (e < EE) { s = src[e]; d = dst[e]; }
    else        { s = e - EE; d = e - EE; }
}

__global__ void edge_max_k(const int* __restrict__ src, const int* __restrict__ dst,
                           const float* __restrict__ als, const float* __restrict__ ald,
                           float* __restrict__ m, int H) {
    long i = (long)blockIdx.x * blockDim.x + threadIdx.x;
    if (i >= (long)ET * H) return;
    int e = (int)(i / H), h = (int)(i % H);
    int s, d; edge_sd(e, src, dst, s, d);
    float v = als[s * H + h] + ald[d * H + h];
    v = v > 0.f ? v : 0.2f * v;
    atomicMaxFloat(&m[d * H + h], v);
}

__global__ void edge_exp_k(const int* __restrict__ src, const int* __restrict__ dst,
                           const float* __restrict__ als, const float* __restrict__ ald,
                           const float* __restrict__ m, float* __restrict__ ssum,
                           float* __restrict__ alpha, int H) {
    long i = (long)blockIdx.x * blockDim.x + threadIdx.x;
    if (i >= (long)ET * H) return;
    int e = (int)(i / H), h = (int)(i % H);
    int s, d; edge_sd(e, src, dst, s, d);
    float v = als[s * H + h] + ald[d * H + h];
    v = v > 0.f ? v : 0.2f * v;
    float ex = expf(v - m[d * H + h]);
    alpha[i] = ex;
    atomicAdd(&ssum[d * H + h], ex);
}

__global__ void edge_norm_k(const int* __restrict__ src, const int* __restrict__ dst,
                            const float* __restrict__ ssum, float* __restrict__ alpha, int H) {
    long i = (long)blockIdx.x * blockDim.x + threadIdx.x;
    if (i >= (long)ET * H) return;
    int e = (int)(i / H), h = (int)(i % H);
    int s, d; edge_sd(e, src, dst, s, d);
    alpha[i] = alpha[i] / (ssum[d * H + h] + 1e-16f);
}

// block per edge; threads cover H*C feature slots
__global__ void aggregate_k(const int* __restrict__ src, const int* __restrict__ dst,
                            const float* __restrict__ feat, const float* __restrict__ alpha,
                            float* __restrict__ acc, int H, int C) {
    int e = blockIdx.x;
    __shared__ int ss, dd;
    if (threadIdx.x == 0) {
        int s, d; edge_sd(e, src, dst, s, d);
        ss = s; dd = d;
    }
    __syncthreads();
    int HC = H * C;
    const float* fs = feat + (size_t)ss * HC;
    float* ad       = acc  + (size_t)dd * HC;
    const float* al = alpha + (size_t)e * H;
    for (int idx = threadIdx.x; idx < HC; idx += blockDim.x) {
        float a = al[idx / C];
        atomicAdd(&ad[idx], fs[idx] * a);
    }
}

// ---------------- epilogues ----------------
__global__ void finalize_concat(const float* __restrict__ acc, const float* __restrict__ res,
                                const float* __restrict__ bias, float* __restrict__ out, int HC) {
    long i = (long)blockIdx.x * blockDim.x + threadIdx.x;
    if (i >= (long)NN * HC) return;
    int j = (int)(i % HC);
    float v = acc[i] + bias[j];
    if (res) v += res[i];
    out[i] = v > 0.f ? v : (expf(v) - 1.0f);   // ELU
}

__global__ void finalize_mean(const float* __restrict__ acc, const float* __restrict__ bias,
                              float* __restrict__ out) {
    long i = (long)blockIdx.x * blockDim.x + threadIdx.x;
    if (i >= (long)NN * 121) return;
    int n = (int)(i / 121), o = (int)(i % 121);
    const float* a = acc + (size_t)n * 726;
    float s = 0.f;
#pragma unroll
    for (int h = 0; h < 6; h++) s += a[h * 121 + o];
    s = s * (1.0f / 6.0f) + bias[o];
    out[i] = 1.0f / (1.0f + expf(-s));
}

// ---------------- host driver ----------------
static void run_gat_layer(const float* xin, int Din,
                          const float* W, const float* a_src, const float* a_dst,
                          const float* bias, int H, int C,
                          const float* Wres,           // nullptr if none
                          bool mean_out,
                          const int* src, const int* dst,
                          float* p_feat, float* p_acc, float* p_als, float* p_ald,
                          float* p_m, float* p_s, float* p_alpha, float* p_res,
                          float* outp) {
    int HC = H * C;
    // 1) h = xin @ W
    {
        dim3 g((HC + 63) / 64, (NN + 63) / 64);
        gemm64<<<g, dim3(16, 16)>>>(xin, W, p_feat, NN, Din, HC);
    }
    // 1b) residual GEMM
    if (Wres) {
        dim3 g((256 + 63) / 64, (NN + 63) / 64);
        gemm64<<<g, dim3(16, 16)>>>(xin, Wres, p_res, NN, Din, 256);
    }
    // 2) attention logits
    {
        long threads = (long)NN * H * 32;
        compute_al<<<(unsigned)((threads + 255) / 256), 256>>>(p_feat, a_src, a_dst, p_als, p_ald, H, C);
    }
    // 3) init m/s and zero acc
    init_ms<<<(NN * H + 255) / 256, 256>>>(p_m, p_s, NN * H);
    {
        size_t n = (size_t)NN * HC;
        unsigned blocks = (unsigned)((n + 255) / 256);
        if (blocks > 65535u * 8u) blocks = 65535u * 8u;
        zerof<<<blocks, 256>>>(p_acc, n);
    }
    // 4) edge passes
    {
        long eh = (long)ET * H;
        unsigned g = (unsigned)((eh + 255) / 256);
        edge_max_k <<<g, 256>>>(src, dst, p_als, p_ald, p_m, H);
        edge_exp_k <<<g, 256>>>(src, dst, p_als, p_ald, p_m, p_s, p_alpha, H);
        edge_norm_k<<<g, 256>>>(src, dst, p_s, p_alpha, H);
    }
    // 5) aggregation
    aggregate_k<<<ET, 256>>>(src, dst, p_feat, p_alpha, p_acc, H, C);
    // 6) epilogue
    if (mean_out) {
        finalize_mean<<<(NN * 121 + 255) / 256, 256>>>(p_acc, bias, outp);
    } else {
        long n = (long)NN * HC;
        finalize_concat<<<(unsigned)((n + 255) / 256), 256>>>(p_acc, Wres ? p_res : nullptr, bias, outp, HC);
    }
}

extern "C" void kernel_launch(void* const* d_in, const int* in_sizes, int n_in,
                              void* d_out, int out_size) {
    const float* x     = (const float*)d_in[0];
    const int*   src   = (const int*)  d_in[1];
    const int*   dst   = (const int*)  d_in[2];
    const float* W1    = (const float*)d_in[3];
    const float* a1s   = (const float*)d_in[4];
    const float* a1d   = (const float*)d_in[5];
    const float* b1    = (const float*)d_in[6];
    const float* W2    = (const float*)d_in[7];
    const float* a2s   = (const float*)d_in[8];
    const float* a2d   = (const float*)d_in[9];
    const float* b2    = (const float*)d_in[10];
    const float* Wres2 = (const float*)d_in[11];
    const float* W3    = (const float*)d_in[12];
    const float* a3s   = (const float*)d_in[13];
    const float* a3d   = (const float*)d_in[14];
    const float* b3    = (const float*)d_in[15];
    float* out = (float*)d_out;

    float *p_feat, *p_acc, *p_x, *p_res, *p_als, *p_ald, *p_m, *p_s, *p_alpha;
    cudaGetSymbolAddress((void**)&p_feat,  g_feat);
    cudaGetSymbolAddress((void**)&p_acc,   g_acc);
    cudaGetSymbolAddress((void**)&p_x,     g_x);
    cudaGetSymbolAddress((void**)&p_res,   g_res);
    cudaGetSymbolAddress((void**)&p_als,   g_als);
    cudaGetSymbolAddress((void**)&p_ald,   g_ald);
    cudaGetSymbolAddress((void**)&p_m,     g_m);
    cudaGetSymbolAddress((void**)&p_s,     g_s);
    cudaGetSymbolAddress((void**)&p_alpha, g_alpha);

    // Layer 1: IN=128 -> 4 heads x 64, concat, ELU
    run_gat_layer(x, 128, W1, a1s, a1d, b1, 4, 64, nullptr, false,
                  src, dst, p_feat, p_acc, p_als, p_ald, p_m, p_s, p_alpha, p_res, p_x);
    // Layer 2: 256 -> 4 heads x 64, concat, +residual, ELU
    run_gat_layer(p_x, 256, W2, a2s, a2d, b2, 4, 64, Wres2, false,
                  src, dst, p_feat, p_acc, p_als, p_ald, p_m, p_s, p_alpha, p_res, p_x);
    // Layer 3: 256 -> 6 heads x 121, mean over heads, sigmoid -> d_out
    run_gat_layer(p_x, 256, W3, a3s, a3d, b3, 6, 121, nullptr, true,
                  src, dst, p_feat, p_acc, p_als, p_ald, p_m, p_s, p_alpha, p_res, out);
}

// round 2
// speedup vs baseline: 2.0334x; 2.0334x over previous
#include <cuda_runtime.h>
#include <math.h>

#define NN 50000
#define EE 800000
#define ET (EE + NN)

// ---------------- device scratch (allocation-free) ----------------
__device__ float g_feat[(size_t)NN * 726];
__device__ float g_acc [(size_t)NN * 726];
__device__ float g_x   [(size_t)NN * 256];
__device__ float g_res [(size_t)NN * 256];
__device__ float g_als [NN * 6];
__device__ float g_ald [NN * 6];
__device__ float g_s   [NN * 6];
__device__ float g_alpha[(size_t)ET * 6];

// ---------------- SGEMM: C[M,Nc] = A[M,K] @ B[K,Nc], 128x128x16 tiles ----------------
__global__ void __launch_bounds__(256) sgemm128(
    const float* __restrict__ A, const float* __restrict__ B,
    float* __restrict__ C, int M, int K, int Nc) {
    __shared__ float As[16][128];
    __shared__ float Bs[16][128];
    const int tid = threadIdx.x;
    const int tx = tid & 15, ty = tid >> 4;
    const int bm = blockIdx.y * 128, bn = blockIdx.x * 128;
    const int arow = tid >> 2, acol4 = tid & 3;   // A: 128 rows x 4 float4
    const int brow0 = tid >> 6, bcol2 = tid & 63; // B: 16 rows x 64 float2
    float acc[8][8] = {};

    for (int k0 = 0; k0 < K; k0 += 16) {
#pragma unroll
        for (int p = 0; p < 2; p++) {
            int r = arow + 64 * p;
            int gr = bm + r;
            float4 v = make_float4(0.f, 0.f, 0.f, 0.f);
            if (gr < M) v = *(const float4*)(A + (size_t)gr * K + k0 + acol4 * 4);
            As[acol4 * 4 + 0][r] = v.x;
            As[acol4 * 4 + 1][r] = v.y;
            As[acol4 * 4 + 2][r] = v.z;
            As[acol4 * 4 + 3][r] = v.w;
        }
#pragma unroll
        for (int p = 0; p < 4; p++) {
            int r = brow0 + 4 * p;
            int c = bcol2 * 2;
            int gc = bn + c;
            float2 v = make_float2(0.f, 0.f);
            if (gc + 1 < Nc)      v = *(const float2*)(B + (size_t)(k0 + r) * Nc + gc);
            else if (gc < Nc)     v.x = B[(size_t)(k0 + r) * Nc + gc];
            Bs[r][c]     = v.x;
            Bs[r][c + 1] = v.y;
        }
        __syncthreads();
#pragma unroll
        for (int kk = 0; kk < 16; kk++) {
            float a[8], b[8];
#pragma unroll
            for (int i = 0; i < 8; i++) a[i] = As[kk][ty * 8 + i];
#pragma unroll
            for (int j = 0; j < 8; j++) b[j] = Bs[kk][tx * 8 + j];
#pragma unroll
            for (int i = 0; i < 8; i++)
#pragma unroll
                for (int j = 0; j < 8; j++)
                    acc[i][j] += a[i] * b[j];
        }
        __syncthreads();
    }
#pragma unroll
    for (int i = 0; i < 8; i++) {
        int gr = bm + ty * 8 + i;
        if (gr >= M) continue;
#pragma unroll
        for (int j = 0; j < 8; j++) {
            int gc = bn + tx * 8 + j;
            if (gc < Nc) C[(size_t)gr * Nc + gc] = acc[i][j];
        }
    }
}

// ---------------- attention logits: warp per (node, head) ----------------
__global__ void compute_al(const float* __restrict__ feat,
                           const float* __restrict__ a_src,
                           const float* __restrict__ a_dst,
                           float* __restrict__ als, float* __restrict__ ald,
                           int H, int C) {
    int w    = (blockIdx.x * blockDim.x + threadIdx.x) >> 5;
    int lane = threadIdx.x & 31;
    if (w >= NN * H) return;
    int n = w / H, h = w % H;
    const float* f  = feat + (size_t)n * H * C + (size_t)h * C;
    const float* as = a_src + h * C;
    const float* ad = a_dst + h * C;
    float s1 = 0.f, s2 = 0.f;
    for (int c = lane; c < C; c += 32) {
        float v = f[c];
        s1 += v * as[c];
        s2 += v * ad[c];
    }
#pragma unroll
    for (int o = 16; o; o >>= 1) {
        s1 += __shfl_down_sync(0xFFFFFFFFu, s1, o);
        s2 += __shfl_down_sync(0xFFFFFFFFu, s2, o);
    }
    if (lane == 0) { als[w] = s1; ald[w] = s2; }
}

// ---------------- zero (vectorized) ----------------
__global__ void zero4(float4* __restrict__ p, long n4) {
    long i = (long)blockIdx.x * blockDim.x + threadIdx.x;
    if (i < n4) p[i] = make_float4(0.f, 0.f, 0.f, 0.f);
}

// ---------------- layers 1/2: fused exp + segment-sum + aggregate ----------------
// 256 threads = 4 edges x 64 lanes (1 float4 per lane over HC=256)
__global__ void __launch_bounds__(256) agg12(
    const int* __restrict__ src, const int* __restrict__ dst,
    const float* __restrict__ als, const float* __restrict__ ald,
    const float* __restrict__ feat, float* __restrict__ ssum,
    float* __restrict__ acc) {
    int le = threadIdx.x >> 6;
    int t  = threadIdx.x & 63;
    long e = (long)blockIdx.x * 4 + le;
    __shared__ float w[4][4];
    int s = 0, d = 0;
    bool valid = e < ET;
    if (valid) {
        if (e < EE) { s = src[e]; d = dst[e]; }
        else        { s = (int)(e - EE); d = s; }
        if (t < 4) {
            float v = als[s * 4 + t] + ald[d * 4 + t];
            v = v > 0.f ? v : 0.2f * v;
            float ex = __expf(v);
            w[le][t] = ex;
            atomicAdd(&ssum[d * 4 + t], ex);
        }
    }
    __syncthreads();
    if (valid) {
        float4 v = *(const float4*)(feat + (size_t)s * 256 + t * 4);
        float ww = w[le][t >> 4];
        float* p = acc + (size_t)d * 256 + t * 4;
        asm volatile("red.global.add.v4.f32 [%0], {%1,%2,%3,%4};"
                     :: "l"(p), "f"(v.x * ww), "f"(v.y * ww),
                        "f"(v.z * ww), "f"(v.w * ww) : "memory");
    }
}

// ---------------- layer 3: exp pass ----------------
__global__ void exp3(const int* __restrict__ src, const int* __restrict__ dst,
                     const float* __restrict__ als, const float* __restrict__ ald,
                     float* __restrict__ ssum, float* __restrict__ alpha) {
    long i = (long)blockIdx.x * blockDim.x + threadIdx.x;
    if (i >= (long)ET * 6) return;
    int e = (int)(i / 6), h = (int)(i % 6);
    int s, d;
    if (e < EE) { s = src[e]; d = dst[e]; } else { s = e - EE; d = s; }
    float v = als[s * 6 + h] + ald[d * 6 + h];
    v = v > 0.f ? v : 0.2f * v;
    float ex = __expf(v);
    alpha[i] = ex;
    atomicAdd(&ssum[d * 6 + h], ex);
}

// ---------------- layer 3: aggregate in head-mean space ----------------
// 256 threads = 2 edges x 128 lanes
__global__ void __launch_bounds__(256) agg3(
    const int* __restrict__ src, const int* __restrict__ dst,
    const float* __restrict__ alpha, const float* __restrict__ ssum,
    const float* __restrict__ feat, float* __restrict__ acc) {
    int le = threadIdx.x >> 7;
    int t  = threadIdx.x & 127;
    long e = (long)blockIdx.x * 2 + le;
    __shared__ float w[2][6];
    int s = 0, d = 0;
    bool valid = e < ET;
    if (valid) {
        if (e < EE) { s = src[e]; d = dst[e]; }
        else        { s = (int)(e - EE); d = s; }
        if (t < 6)
            w[le][t] = alpha[e * 6 + t] / (ssum[d * 6 + t] + 1e-16f);
    }
    __syncthreads();
    if (valid && t < 121) {
        const float* f = feat + (size_t)s * 726 + t;
        float sum = 0.f;
#pragma unroll
        for (int h = 0; h < 6; h++) sum += w[le][h] * f[h * 121];
        atomicAdd(&acc[(size_t)d * 121 + t], sum);
    }
}

// ---------------- epilogues ----------------
__global__ void finalize12(const float4* __restrict__ acc4, const float4* __restrict__ res4,
                           const float* __restrict__ ssum, const float4* __restrict__ bias4,
                           float4* __restrict__ out4) {
    long i = (long)blockIdx.x * blockDim.x + threadIdx.x;
    if (i >= (long)NN * 64) return;
    int n = (int)(i >> 6);
    int c4 = (int)(i & 63);
    int h = c4 >> 4;
    float inv = 1.f / (ssum[n * 4 + h] + 1e-16f);
    float4 a = acc4[i];
    float4 b = bias4[c4];
    float4 v;
    v.x = a.x * inv + b.x;
    v.y = a.y * inv + b.y;
    v.z = a.z * inv + b.z;
    v.w = a.w * inv + b.w;
    if (res4) {
        float4 r = res4[i];
        v.x += r.x; v.y += r.y; v.z += r.z; v.w += r.w;
    }
    v.x = v.x > 0.f ? v.x : (__expf(v.x) - 1.f);
    v.y = v.y > 0.f ? v.y : (__expf(v.y) - 1.f);
    v.z = v.z > 0.f ? v.z : (__expf(v.z) - 1.f);
    v.w = v.w > 0.f ? v.w : (__expf(v.w) - 1.f);
    out4[i] = v;
}

__global__ void finalize3(const float* __restrict__ acc, const float* __restrict__ bias,
                          float* __restrict__ out) {
    long i = (long)blockIdx.x * blockDim.x + threadIdx.x;
    if (i >= (long)NN * 121) return;
    int o = (int)(i % 121);
    float v = acc[i] * (1.f / 6.f) + bias[o];
    out[i] = 1.f / (1.f + __expf(-v));
}

// ---------------- host driver ----------------
static void layer12(const float* xin, int K,
                    const float* W, const float* as_, const float* ad_,
                    const float* bias, const float* Wres,
                    const int* src, const int* dst,
                    float* feat, float* acc, float* als, float* ald,
                    float* ssum, float* res, float* out) {
    dim3 g(2, (NN + 127) / 128);
    sgemm128<<<g, 256>>>(xin, W, feat, NN, K, 256);
    if (Wres) sgemm128<<<g, 256>>>(xin, Wres, res, NN, K, 256);
    compute_al<<<(NN * 4 * 32 + 255) / 256, 256>>>(feat, as_, ad_, als, ald, 4, 64);
    zero4<<<(NN * 64 + 255) / 256, 256>>>((float4*)acc, (long)NN * 64);
    zero4<<<(NN * 6 / 4 + 255) / 256, 256>>>((float4*)ssum, (long)NN * 6 / 4);
    agg12<<<(ET + 3) / 4, 256>>>(src, dst, als, ald, feat, ssum, acc);
    finalize12<<<(NN * 64 + 255) / 256, 256>>>((const float4*)acc,
        Wres ? (const float4*)res : (const float4*)nullptr,
        ssum, (const float4*)bias, (float4*)out);
}

extern "C" void kernel_launch(void* const* d_in, const int* in_sizes, int n_in,
                              void* d_out, int out_size) {
    const float* x     = (const float*)d_in[0];
    const int*   src   = (const int*)  d_in[1];
    const int*   dst   = (const int*)  d_in[2];
    const float* W1    = (const float*)d_in[3];
    const float* a1s   = (const float*)d_in[4];
    const float* a1d   = (const float*)d_in[5];
    const float* b1    = (const float*)d_in[6];
    const float* W2    = (const float*)d_in[7];
    const float* a2s   = (const float*)d_in[8];
    const float* a2d   = (const float*)d_in[9];
    const float* b2    = (const float*)d_in[10];
    const float* Wres2 = (const float*)d_in[11];
    const float* W3    = (const float*)d_in[12];
    const float* a3s   = (const float*)d_in[13];
    const float* a3d   = (const float*)d_in[14];
    const float* b3    = (const float*)d_in[15];
    float* out = (float*)d_out;

    float *p_feat, *p_acc, *p_x, *p_res, *p_als, *p_ald, *p_s, *p_alpha;
    cudaGetSymbolAddress((void**)&p_feat,  g_feat);
    cudaGetSymbolAddress((void**)&p_acc,   g_acc);
    cudaGetSymbolAddress((void**)&p_x,     g_x);
    cudaGetSymbolAddress((void**)&p_res,   g_res);
    cudaGetSymbolAddress((void**)&p_als,   g_als);
    cudaGetSymbolAddress((void**)&p_ald,   g_ald);
    cudaGetSymbolAddress((void**)&p_s,     g_s);
    cudaGetSymbolAddress((void**)&p_alpha, g_alpha);

    // Layer 1: 128 -> 4x64 concat, ELU
    layer12(x, 128, W1, a1s, a1d, b1, nullptr, src, dst,
            p_feat, p_acc, p_als, p_ald, p_s, p_res, p_x);
    // Layer 2: 256 -> 4x64 concat + residual, ELU
    layer12(p_x, 256, W2, a2s, a2d, b2, Wres2, src, dst,
            p_feat, p_acc, p_als, p_ald, p_s, p_res, p_x);

    // Layer 3: 256 -> 6 heads x 121, mean over heads, sigmoid
    {
        dim3 g((726 + 127) / 128, (NN + 127) / 128);
        sgemm128<<<g, 256>>>(p_x, W3, p_feat, NN, 256, 726);
        compute_al<<<(NN * 6 * 32 + 255) / 256, 256>>>(p_feat, a3s, a3d, p_als, p_ald, 6, 121);
        zero4<<<((NN * 121) / 4 + 255) / 256, 256>>>((float4*)p_acc, (long)NN * 121 / 4);
        zero4<<<(NN * 6 / 4 + 255) / 256, 256>>>((float4*)p_s, (long)NN * 6 / 4);
        {
            long eh = (long)ET * 6;
            exp3<<<(unsigned)((eh + 255) / 256), 256>>>(src, dst, p_als, p_ald, p_s, p_alpha);
        }
        agg3<<<(ET + 1) / 2, 256>>>(src, dst, p_alpha, p_s, p_feat, p_acc);
        finalize3<<<(NN * 121 + 255) / 256, 256>>>(p_acc, b3, out);
    }
}

// round 3
// speedup vs baseline: 2.4189x; 1.1896x over previous
#include <cuda_runtime.h>
#include <math.h>

#define NN 50000
#define EE 800000
#define ET (EE + NN)

// ---------------- device scratch (allocation-free) ----------------
__device__ float g_feat[(size_t)NN * 256];    // layers 1/2: h = x @ W
__device__ float g_x   [(size_t)NN * 256];    // layer activations
__device__ float g_res [(size_t)NN * 256];    // residual branch
__device__ float g_y   [(size_t)NN * 1536];   // layer 3: aggregated input space [N,6,256]
__device__ float g_acc [(size_t)NN * 128];    // layer 3 GEMM out (padded 121->128)
__device__ float g_als [NN * 6];
__device__ float g_ald [NN * 6];
__device__ float g_Wt  [2 * 256 * 6];         // W3_h @ a3_{src,dst}
__device__ float g_Bp  [1536 * 128];          // permuted W3 (head-mean folded), padded
__device__ int   g_csr [ET];                  // src node per CSR slot (sorted by dst)
__device__ int   g_rowptr[NN + 1];
__device__ int   g_cur [NN];
__device__ int   g_bsum[256];

// ================= CSR build =================
__global__ void zeroi(int* __restrict__ p, int n) {
    int i = blockIdx.x * blockDim.x + threadIdx.x;
    if (i < n) p[i] = 0;
}
__global__ void hist_k(const int* __restrict__ dst, int* __restrict__ cur) {
    int e = blockIdx.x * blockDim.x + threadIdx.x;
    if (e >= ET) return;
    int d = (e < EE) ? dst[e] : e - EE;
    atomicAdd(&cur[d], 1);
}
__global__ void scan1(const int* __restrict__ deg, int* __restrict__ bsum) {
    __shared__ int sh[256];
    int i = blockIdx.x * 256 + threadIdx.x;
    sh[threadIdx.x] = (i < NN) ? deg[i] : 0;
    __syncthreads();
    for (int o = 128; o; o >>= 1) {
        if (threadIdx.x < o) sh[threadIdx.x] += sh[threadIdx.x + o];
        __syncthreads();
    }
    if (threadIdx.x == 0) bsum[blockIdx.x] = sh[0];
}
__global__ void scan2(int* __restrict__ bsum, int nb) {
    if (threadIdx.x == 0 && blockIdx.x == 0) {
        int acc = 0;
        for (int i = 0; i < nb; i++) { int t = bsum[i]; bsum[i] = acc; acc += t; }
    }
}
__global__ void scan3(const int* __restrict__ deg, const int* __restrict__ bsum,
                      int* __restrict__ rowptr, int* __restrict__ cur) {
    __shared__ int sh[256];
    int i = blockIdx.x * 256 + threadIdx.x;
    int v = (i < NN) ? deg[i] : 0;
    sh[threadIdx.x] = v;
    __syncthreads();
    for (int o = 1; o < 256; o <<= 1) {
        int t = (threadIdx.x >= o) ? sh[threadIdx.x - o] : 0;
        __syncthreads();
        sh[threadIdx.x] += t;
        __syncthreads();
    }
    int excl = sh[threadIdx.x] - v + bsum[blockIdx.x];
    if (i < NN) { rowptr[i] = excl; cur[i] = excl; }
    if (i == NN - 1) rowptr[NN] = excl + v;
}
__global__ void scatter_k(const int* __restrict__ src, const int* __restrict__ dst,
                          int* __restrict__ cur, int* __restrict__ csr) {
    int e = blockIdx.x * blockDim.x + threadIdx.x;
    if (e >= ET) return;
    int s, d;
    if (e < EE) { s = src[e]; d = dst[e]; } else { s = e - EE; d = s; }
    int pos = atomicAdd(&cur[d], 1);
    csr[pos] = s;
}

// ================= SGEMM 128x128x16 =================
__global__ void __launch_bounds__(256) sgemm128(
    const float* __restrict__ A, const float* __restrict__ B,
    float* __restrict__ C, int M, int K, int Nc) {
    __shared__ float As[16][128];
    __shared__ float Bs[16][128];
    const int tid = threadIdx.x;
    const int tx = tid & 15, ty = tid >> 4;
    const int bm = blockIdx.y * 128, bn = blockIdx.x * 128;
    const int arow = tid >> 2, acol4 = tid & 3;
    const int brow0 = tid >> 6, bcol2 = tid & 63;
    float acc[8][8] = {};

    for (int k0 = 0; k0 < K; k0 += 16) {
#pragma unroll
        for (int p = 0; p < 2; p++) {
            int r = arow + 64 * p;
            int gr = bm + r;
            float4 v = make_float4(0.f, 0.f, 0.f, 0.f);
            if (gr < M) v = *(const float4*)(A + (size_t)gr * K + k0 + acol4 * 4);
            As[acol4 * 4 + 0][r] = v.x;
            As[acol4 * 4 + 1][r] = v.y;
            As[acol4 * 4 + 2][r] = v.z;
            As[acol4 * 4 + 3][r] = v.w;
        }
#pragma unroll
        for (int p = 0; p < 4; p++) {
            int r = brow0 + 4 * p;
            int c = bcol2 * 2;
            int gc = bn + c;
            float2 v = make_float2(0.f, 0.f);
            if (gc + 1 < Nc)  v = *(const float2*)(B + (size_t)(k0 + r) * Nc + gc);
            else if (gc < Nc) v.x = B[(size_t)(k0 + r) * Nc + gc];
            Bs[r][c]     = v.x;
            Bs[r][c + 1] = v.y;
        }
        __syncthreads();
#pragma unroll
        for (int kk = 0; kk < 16; kk++) {
            float a[8], b[8];
#pragma unroll
            for (int i = 0; i < 8; i++) a[i] = As[kk][ty * 8 + i];
#pragma unroll
            for (int j = 0; j < 8; j++) b[j] = Bs[kk][tx * 8 + j];
#pragma unroll
            for (int i = 0; i < 8; i++)
#pragma unroll
                for (int j = 0; j < 8; j++)
                    acc[i][j] += a[i] * b[j];
        }
        __syncthreads();
    }
#pragma unroll
    for (int i = 0; i < 8; i++) {
        int gr = bm + ty * 8 + i;
        if (gr >= M) continue;
#pragma unroll
        for (int j = 0; j < 8; j++) {
            int gc = bn + tx * 8 + j;
            if (gc < Nc) C[(size_t)gr * Nc + gc] = acc[i][j];
        }
    }
}

// ================= attention logits (layers 1/2): warp per (node, head) =================
__global__ void compute_al(const float* __restrict__ feat,
                           const float* __restrict__ a_src,
                           const float* __restrict__ a_dst,
                           float* __restrict__ als, float* __restrict__ ald,
                           int H, int C) {
    int w    = (blockIdx.x * blockDim.x + threadIdx.x) >> 5;
    int lane = threadIdx.x & 31;
    if (w >= NN * H) return;
    int n = w / H, h = w % H;
    const float* f  = feat + (size_t)n * H * C + (size_t)h * C;
    const float* as = a_src + h * C;
    const float* ad = a_dst + h * C;
    float s1 = 0.f, s2 = 0.f;
    for (int c = lane; c < C; c += 32) {
        float v = f[c];
        s1 += v * as[c];
        s2 += v * ad[c];
    }
#pragma unroll
    for (int o = 16; o; o >>= 1) {
        s1 += __shfl_down_sync(0xFFFFFFFFu, s1, o);
        s2 += __shfl_down_sync(0xFFFFFFFFu, s2, o);
    }
    if (lane == 0) { als[w] = s1; ald[w] = s2; }
}

// ================= layers 1/2: fully fused gather-aggregate =================
// 2 warps per node; each warp owns 128 cols; lanes 0/16 compute head weights.
__global__ void __launch_bounds__(256) agg_fused12(
    const int* __restrict__ rowptr, const int* __restrict__ csr,
    const float* __restrict__ feat, const float* __restrict__ als,
    const float* __restrict__ ald, const float* __restrict__ bias,
    const float* __restrict__ res, float* __restrict__ out) {
    int gw   = blockIdx.x * 8 + (threadIdx.x >> 5);
    int lane = threadIdx.x & 31;
    int n = gw >> 1, half = gw & 1;
    if (n >= NN) return;
    int col = half * 128 + lane * 4;
    int hl  = half * 2 + (lane >= 16);   // head computed by this lane (used on lanes 0/16)
    float aldh = 0.f;
    if (lane == 0 || lane == 16) aldh = ald[n * 4 + hl];
    int beg = rowptr[n], end = rowptr[n + 1];
    float4 acc = make_float4(0.f, 0.f, 0.f, 0.f);
    float denom = 0.f;
    for (int p = beg; p < end; p++) {
        int s = __ldg(&csr[p]);
        float wv = 0.f;
        if (lane == 0 || lane == 16) {
            float v = als[s * 4 + hl] + aldh;
            v = v > 0.f ? v : 0.2f * v;
            wv = __expf(v);
        }
        float w = __shfl_sync(0xFFFFFFFFu, wv, (lane < 16) ? 0 : 16);
        float4 f = *(const float4*)(feat + (size_t)s * 256 + col);
        acc.x += f.x * w; acc.y += f.y * w; acc.z += f.z * w; acc.w += f.w * w;
        denom += w;
    }
    float inv = 1.f / (denom + 1e-16f);
    float4 b = *(const float4*)(bias + col);
    float4 v;
    v.x = acc.x * inv + b.x;
    v.y = acc.y * inv + b.y;
    v.z = acc.z * inv + b.z;
    v.w = acc.w * inv + b.w;
    if (res) {
        float4 r = *(const float4*)(res + (size_t)n * 256 + col);
        v.x += r.x; v.y += r.y; v.z += r.z; v.w += r.w;
    }
    v.x = v.x > 0.f ? v.x : (__expf(v.x) - 1.f);
    v.y = v.y > 0.f ? v.y : (__expf(v.y) - 1.f);
    v.z = v.z > 0.f ? v.z : (__expf(v.z) - 1.f);
    v.w = v.w > 0.f ? v.w : (__expf(v.w) - 1.f);
    *(float4*)(out + (size_t)n * 256 + col) = v;
}

// ================= layer 3 tiny pre-GEMMs =================
// Wt[side][k][h] = sum_o W3[k, h*121+o] * a3_{side}[h, o]
__global__ void build_wt(const float* __restrict__ W3, const float* __restrict__ a3s,
                         const float* __restrict__ a3d, float* __restrict__ Wt) {
    int i = blockIdx.x * blockDim.x + threadIdx.x;
    if (i >= 2 * 256 * 6) return;
    int side = i / (256 * 6);
    int r = i % (256 * 6);
    int k = r / 6, h = r % 6;
    const float* av = side ? a3d : a3s;
    float s = 0.f;
    for (int o = 0; o < 121; o++)
        s += W3[(size_t)k * 726 + h * 121 + o] * av[h * 121 + o];
    Wt[(size_t)side * 1536 + k * 6 + h] = s;
}
// Bp[h*256+k][o] = W3[k][h*121+o] / 6  (padded to 128 cols)
__global__ void build_bp(const float* __restrict__ W3, float* __restrict__ Bp) {
    int i = blockIdx.x * blockDim.x + threadIdx.x;
    if (i >= 1536 * 128) return;
    int row = i / 128, o = i % 128;
    int h = row / 256, k = row % 256;
    Bp[i] = (o < 121) ? W3[(size_t)k * 726 + h * 121 + o] * (1.f / 6.f) : 0.f;
}
// als/ald = x @ Wt : warp per node, 12 outputs
__global__ void __launch_bounds__(256) al3_k(
    const float* __restrict__ x, const float* __restrict__ Wt,
    float* __restrict__ als, float* __restrict__ ald) {
    int gw   = blockIdx.x * 8 + (threadIdx.x >> 5);
    int lane = threadIdx.x & 31;
    if (gw >= NN) return;
    const float4* xp = (const float4*)(x + (size_t)gw * 256);
    float4 a = xp[lane * 2], b = xp[lane * 2 + 1];
    float xv[8] = {a.x, a.y, a.z, a.w, b.x, b.y, b.z, b.w};
#pragma unroll
    for (int j = 0; j < 12; j++) {
        const float* W = Wt + (j >= 6 ? 1536 : 0);
        int jj = j % 6;
        float sum = 0.f;
#pragma unroll
        for (int i = 0; i < 8; i++)
            sum += xv[i] * W[(lane * 8 + i) * 6 + jj];
#pragma unroll
        for (int o = 16; o; o >>= 1) sum += __shfl_down_sync(0xFFFFFFFFu, sum, o);
        if (lane == 0) {
            if (j < 6) als[gw * 6 + jj] = sum;
            else       ald[gw * 6 + jj] = sum;
        }
    }
}

// ================= layer 3: fused gather in input space =================
// 2 warps per node; lane owns 4 input cols x 6 heads; lanes 0-5 compute weights.
__global__ void __launch_bounds__(256) agg_fused3(
    const int* __restrict__ rowptr, const int* __restrict__ csr,
    const float* __restrict__ x, const float* __restrict__ als,
    const float* __restrict__ ald, float* __restrict__ y) {
    int gw   = blockIdx.x * 8 + (threadIdx.x >> 5);
    int lane = threadIdx.x & 31;
    int n = gw >> 1, half = gw & 1;
    if (n >= NN) return;
    int col = half * 128 + lane * 4;
    float4 acc[6];
    float den[6];
#pragma unroll
    for (int h = 0; h < 6; h++) { acc[h] = make_float4(0.f, 0.f, 0.f, 0.f); den[h] = 0.f; }
    float aldl = (lane < 6) ? ald[n * 6 + lane] : 0.f;
    int beg = rowptr[n], end = rowptr[n + 1];
    for (int p = beg; p < end; p++) {
        int s = __ldg(&csr[p]);
        float wv = 0.f;
        if (lane < 6) {
            float v = als[s * 6 + lane] + aldl;
            v = v > 0.f ? v : 0.2f * v;
            wv = __expf(v);
        }
        float4 f = *(const float4*)(x + (size_t)s * 256 + col);
#pragma unroll
        for (int h = 0; h < 6; h++) {
            float w = __shfl_sync(0xFFFFFFFFu, wv, h);
            den[h] += w;
            acc[h].x += f.x * w; acc[h].y += f.y * w;
            acc[h].z += f.z * w; acc[h].w += f.w * w;
        }
    }
#pragma unroll
    for (int h = 0; h < 6; h++) {
        float inv = 1.f / (den[h] + 1e-16f);
        float4 v;
        v.x = acc[h].x * inv; v.y = acc[h].y * inv;
        v.z = acc[h].z * inv; v.w = acc[h].w * inv;
        *(float4*)(y + ((size_t)n * 6 + h) * 256 + col) = v;
    }
}

// ================= final sigmoid =================
__global__ void finalize3(const float* __restrict__ acc, const float* __restrict__ bias,
                          float* __restrict__ out) {
    long i = (long)blockIdx.x * blockDim.x + threadIdx.x;
    if (i >= (long)NN * 121) return;
    int n = (int)(i / 121), o = (int)(i % 121);
    float v = acc[(size_t)n * 128 + o] + bias[o];
    out[i] = 1.f / (1.f + __expf(-v));
}

// ================= host driver =================
extern "C" void kernel_launch(void* const* d_in, const int* in_sizes, int n_in,
                              void* d_out, int out_size) {
    const float* x     = (const float*)d_in[0];
    const int*   src   = (const int*)  d_in[1];
    const int*   dst   = (const int*)  d_in[2];
    const float* W1    = (const float*)d_in[3];
    const float* a1s   = (const float*)d_in[4];
    const float* a1d   = (const float*)d_in[5];
    const float* b1    = (const float*)d_in[6];
    const float* W2    = (const float*)d_in[7];
    const float* a2s   = (const float*)d_in[8];
    const float* a2d   = (const float*)d_in[9];
    const float* b2    = (const float*)d_in[10];
    const float* Wres2 = (const float*)d_in[11];
    const float* W3    = (const float*)d_in[12];
    const float* a3s   = (const float*)d_in[13];
    const float* a3d   = (const float*)d_in[14];
    const float* b3    = (const float*)d_in[15];
    float* out = (float*)d_out;

    float *p_feat, *p_x, *p_res, *p_y, *p_acc, *p_als, *p_ald, *p_Wt, *p_Bp;
    int *p_csr, *p_rowptr, *p_cur, *p_bsum;
    cudaGetSymbolAddress((void**)&p_feat,   g_feat);
    cudaGetSymbolAddress((void**)&p_x,      g_x);
    cudaGetSymbolAddress((void**)&p_res,    g_res);
    cudaGetSymbolAddress((void**)&p_y,      g_y);
    cudaGetSymbolAddress((void**)&p_acc,    g_acc);
    cudaGetSymbolAddress((void**)&p_als,    g_als);
    cudaGetSymbolAddress((void**)&p_ald,    g_ald);
    cudaGetSymbolAddress((void**)&p_Wt,     g_Wt);
    cudaGetSymbolAddress((void**)&p_Bp,     g_Bp);
    cudaGetSymbolAddress((void**)&p_csr,    g_csr);
    cudaGetSymbolAddress((void**)&p_rowptr, g_rowptr);
    cudaGetSymbolAddress((void**)&p_cur,    g_cur);
    cudaGetSymbolAddress((void**)&p_bsum,   g_bsum);

    // ---- CSR build ----
    zeroi<<<(NN + 255) / 256, 256>>>(p_cur, NN);
    hist_k<<<(ET + 255) / 256, 256>>>(dst, p_cur);
    scan1<<<196, 256>>>(p_cur, p_bsum);
    scan2<<<1, 32>>>(p_bsum, 196);
    scan3<<<196, 256>>>(p_cur, p_bsum, p_rowptr, p_cur);
    scatter_k<<<(ET + 255) / 256, 256>>>(src, dst, p_cur, p_csr);

    // ---- layer-3 weight prep ----
    build_wt<<<(2 * 256 * 6 + 255) / 256, 256>>>(W3, a3s, a3d, p_Wt);
    build_bp<<<(1536 * 128 + 255) / 256, 256>>>(W3, p_Bp);

    // ---- Layer 1: 128 -> 4x64 concat, ELU ----
    {
        dim3 g(2, (NN + 127) / 128);
        sgemm128<<<g, 256>>>(x, W1, p_feat, NN, 128, 256);
        compute_al<<<(NN * 4 * 32 + 255) / 256, 256>>>(p_feat, a1s, a1d, p_als, p_ald, 4, 64);
        agg_fused12<<<(NN * 2 + 7) / 8, 256>>>(p_rowptr, p_csr, p_feat, p_als, p_ald, b1, nullptr, p_x);
    }
    // ---- Layer 2: 256 -> 4x64 concat + residual, ELU ----
    {
        dim3 g(2, (NN + 127) / 128);
        sgemm128<<<g, 256>>>(p_x, W2, p_feat, NN, 256, 256);
        sgemm128<<<g, 256>>>(p_x, Wres2, p_res, NN, 256, 256);
        compute_al<<<(NN * 4 * 32 + 255) / 256, 256>>>(p_feat, a2s, a2d, p_als, p_ald, 4, 64);
        agg_fused12<<<(NN * 2 + 7) / 8, 256>>>(p_rowptr, p_csr, p_feat, p_als, p_ald, b2, p_res, p_x);
    }
    // ---- Layer 3: aggregate in input space, then one K=1536 GEMM ----
    {
        al3_k<<<(NN + 7) / 8, 256>>>(p_x, p_Wt, p_als, p_ald);
        agg_fused3<<<(NN * 2 + 7) / 8, 256>>>(p_rowptr, p_csr, p_x, p_als, p_ald, p_y);
        dim3 g(1, (NN + 127) / 128);
        sgemm128<<<g, 256>>>(p_y, p_Bp, p_acc, NN, 1536, 128);
        finalize3<<<(NN * 121 + 255) / 256, 256>>>(p_acc, b3, out);
    }
}

// round 5
// speedup vs baseline: 3.3703x; 1.3933x over previous
#include <cuda_runtime.h>
#include <cuda_bf16.h>
#include <math.h>
#include <stdint.h>

#define NN 50000
#define EE 800000
#define ET (EE + NN)

// ---------------- device scratch (allocation-free) ----------------
__device__ float g_feat[(size_t)NN * 256];
__device__ float g_x   [(size_t)NN * 256];
__device__ float g_res [(size_t)NN * 256];
__device__ float g_y   [(size_t)NN * 1536];
__device__ float g_acc [(size_t)NN * 128];
__device__ float g_als [NN * 6];
__device__ float g_ald [NN * 6];
__device__ float g_Wt  [2 * 256 * 6];
__device__ int   g_csr [ET];
__device__ int   g_rowptr[NN + 1];
__device__ int   g_cur [NN];
__device__ int   g_bsum[256];
// K-major bf16 hi/lo weights
__device__ __nv_bfloat16 g_w1t_hi[256 * 128],  g_w1t_lo[256 * 128];
__device__ __nv_bfloat16 g_w2t_hi[256 * 256],  g_w2t_lo[256 * 256];
__device__ __nv_bfloat16 g_wrt_hi[256 * 256],  g_wrt_lo[256 * 256];
__device__ __nv_bfloat16 g_bpt_hi[128 * 1536], g_bpt_lo[128 * 1536];

// ---------------- split helpers ----------------
__device__ __forceinline__ uint32_t pack_hi(float x, float y, float& rx, float& ry) {
    uint32_t h;
    asm("cvt.rn.bf16x2.f32 %0, %1, %2;" : "=r"(h) : "f"(y), "f"(x));
    rx = x - __uint_as_float(h << 16);
    ry = y - __uint_as_float(h & 0xFFFF0000u);
    return h;
}
__device__ __forceinline__ uint32_t pack2(float x, float y) {
    uint32_t h;
    asm("cvt.rn.bf16x2.f32 %0, %1, %2;" : "=r"(h) : "f"(y), "f"(x));
    return h;
}
__device__ __forceinline__ void mma16816(float* c, const uint32_t* a, const uint32_t* b) {
    asm volatile(
        "mma.sync.aligned.m16n8k16.row.col.f32.bf16.bf16.f32 "
        "{%0,%1,%2,%3}, {%4,%5,%6,%7}, {%8,%9}, {%0,%1,%2,%3};"
        : "+f"(c[0]), "+f"(c[1]), "+f"(c[2]), "+f"(c[3])
        : "r"(a[0]), "r"(a[1]), "r"(a[2]), "r"(a[3]), "r"(b[0]), "r"(b[1]));
}

// ================= HMMA GEMM: C[M,Nc] = A[M,K] @ (Bt[Nc,K])^T =================
// A fp32 (split inline to bf16 hi/lo); Bt bf16 hi/lo K-major.
// Tile 128x128, K-chunk 32. 8 warps: 2(M) x 4(N), warp tile 64x32.
#define SSTR 17   // uint32 per smem row (32 bf16 data + 2 pad)
__global__ void __launch_bounds__(256) mma_gemm(
    const float* __restrict__ A,
    const __nv_bfloat16* __restrict__ Bth, const __nv_bfloat16* __restrict__ Btl,
    float* __restrict__ C, int M, int K, int Nc) {
    __shared__ uint32_t sAh[128 * SSTR], sAl[128 * SSTR];
    __shared__ uint32_t sBh[128 * SSTR], sBl[128 * SSTR];
    const int tid = threadIdx.x, wid = tid >> 5, lane = tid & 31;
    const int wm = wid & 1, wn = wid >> 1;
    const int bm = blockIdx.y * 128, bn = blockIdx.x * 128;
    const int g = lane >> 2, tg = lane & 3;

    float acc[4][4][4];
#pragma unroll
    for (int i = 0; i < 4; i++)
#pragma unroll
        for (int j = 0; j < 4; j++)
#pragma unroll
            for (int q = 0; q < 4; q++) acc[i][j][q] = 0.f;

    const int lrow = tid >> 1, lhalf = (tid & 1) * 16;
    const int gr = bm + lrow;     // A row loaded by this thread
    const int gn = bn + lrow;     // B row loaded by this thread

    for (int k0 = 0; k0 < K; k0 += 32) {
        // ---- A: fp32 -> bf16 hi/lo split ----
        {
            const float4* ap = (const float4*)(A + (size_t)gr * K + k0 + lhalf);
            uint32_t* dh = sAh + lrow * SSTR + (lhalf >> 1);
            uint32_t* dl = sAl + lrow * SSTR + (lhalf >> 1);
#pragma unroll
            for (int i = 0; i < 4; i++) {
                float4 v = (gr < M) ? ap[i] : make_float4(0.f, 0.f, 0.f, 0.f);
                float r0, r1, r2, r3;
                uint32_t h0 = pack_hi(v.x, v.y, r0, r1);
                uint32_t h1 = pack_hi(v.z, v.w, r2, r3);
                dh[2 * i] = h0;            dh[2 * i + 1] = h1;
                dl[2 * i] = pack2(r0, r1); dl[2 * i + 1] = pack2(r2, r3);
            }
        }
        // ---- B: copy preconverted bf16 hi/lo ----
        {
            const uint32_t* bh = (const uint32_t*)(Bth + (size_t)gn * K + k0 + lhalf);
            const uint32_t* bl = (const uint32_t*)(Btl + (size_t)gn * K + k0 + lhalf);
            uint32_t* dh = sBh + lrow * SSTR + (lhalf >> 1);
            uint32_t* dl = sBl + lrow * SSTR + (lhalf >> 1);
#pragma unroll
            for (int i = 0; i < 8; i++) { dh[i] = bh[i]; dl[i] = bl[i]; }
        }
        __syncthreads();

#pragma unroll
        for (int ks = 0; ks < 2; ks++) {
            const int kb = ks * 8;
            uint32_t ah[4][4], al[4][4], bh[4][2], bl[4][2];
#pragma unroll
            for (int mi = 0; mi < 4; mi++) {
                int r0 = wm * 64 + mi * 16 + g;
                const uint32_t* ph = sAh + r0 * SSTR + kb + tg;
                const uint32_t* pl = sAl + r0 * SSTR + kb + tg;
                ah[mi][0] = ph[0]; ah[mi][1] = ph[8 * SSTR];
                ah[mi][2] = ph[4]; ah[mi][3] = ph[8 * SSTR + 4];
                al[mi][0] = pl[0]; al[mi][1] = pl[8 * SSTR];
                al[mi][2] = pl[4]; al[mi][3] = pl[8 * SSTR + 4];
            }
#pragma unroll
            for (int nj = 0; nj < 4; nj++) {
                int n0 = wn * 32 + nj * 8 + g;
                const uint32_t* ph = sBh + n0 * SSTR + kb + tg;
                const uint32_t* pl = sBl + n0 * SSTR + kb + tg;
                bh[nj][0] = ph[0]; bh[nj][1] = ph[4];
                bl[nj][0] = pl[0]; bl[nj][1] = pl[4];
            }
#pragma unroll
            for (int mi = 0; mi < 4; mi++)
#pragma unroll
                for (int nj = 0; nj < 4; nj++) {
                    mma16816(acc[mi][nj], ah[mi], bh[nj]);
                    mma16816(acc[mi][nj], ah[mi], bl[nj]);
                    mma16816(acc[mi][nj], al[mi], bh[nj]);
                }
        }
        __syncthreads();
    }

    // ---- store ----
#pragma unroll
    for (int mi = 0; mi < 4; mi++) {
        int row = bm + wm * 64 + mi * 16 + g;
#pragma unroll
        for (int nj = 0; nj < 4; nj++) {
            int col = bn + wn * 32 + nj * 8 + tg * 2;
            if (row < M)
                *(float2*)(C + (size_t)row * Nc + col) = make_float2(acc[mi][nj][0], acc[mi][nj][1]);
            if (row + 8 < M)
                *(float2*)(C + (size_t)(row + 8) * Nc + col) = make_float2(acc[mi][nj][2], acc[mi][nj][3]);
        }
    }
}

// ================= weight prep: transpose + bf16 split =================
__global__ void wsplit(const float* __restrict__ W, __nv_bfloat16* __restrict__ hi,
                       __nv_bfloat16* __restrict__ lo, int K, int Nc) {
    long i = (long)blockIdx.x * blockDim.x + threadIdx.x;
    if (i >= (long)K * Nc) return;
    int n = (int)(i / K), k = (int)(i % K);
    float v = W[(size_t)k * Nc + n];
    __nv_bfloat16 h = __float2bfloat16(v);
    hi[i] = h;
    lo[i] = __float2bfloat16(v - __bfloat162float(h));
}
__global__ void bsplit3(const float* __restrict__ W3, __nv_bfloat16* __restrict__ hi,
                        __nv_bfloat16* __restrict__ lo) {
    long i = (long)blockIdx.x * blockDim.x + threadIdx.x;
    if (i >= 128L * 1536) return;
    int n = (int)(i / 1536), kk = (int)(i % 1536);
    int h_ = kk >> 8, k = kk & 255;
    float v = (n < 121) ? W3[(size_t)k * 726 + h_ * 121 + n] * (1.f / 6.f) : 0.f;
    __nv_bfloat16 h = __float2bfloat16(v);
    hi[i] = h;
    lo[i] = __float2bfloat16(v - __bfloat162float(h));
}

// ================= CSR build =================
__global__ void zeroi(int* __restrict__ p, int n) {
    int i = blockIdx.x * blockDim.x + threadIdx.x;
    if (i < n) p[i] = 0;
}
__global__ void hist_k(const int* __restrict__ dst, int* __restrict__ cur) {
    int e = blockIdx.x * blockDim.x + threadIdx.x;
    if (e >= ET) return;
    int d = (e < EE) ? dst[e] : e - EE;
    atomicAdd(&cur[d], 1);
}
__global__ void scan1(const int* __restrict__ deg, int* __restrict__ bsum) {
    __shared__ int sh[256];
    int i = blockIdx.x * 256 + threadIdx.x;
    sh[threadIdx.x] = (i < NN) ? deg[i] : 0;
    __syncthreads();
    for (int o = 128; o; o >>= 1) {
        if (threadIdx.x < o) sh[threadIdx.x] += sh[threadIdx.x + o];
        __syncthreads();
    }
    if (threadIdx.x == 0) bsum[blockIdx.x] = sh[0];
}
__global__ void scan2(int* __restrict__ bsum, int nb) {
    if (threadIdx.x == 0 && blockIdx.x == 0) {
        int acc = 0;
        for (int i = 0; i < nb; i++) { int t = bsum[i]; bsum[i] = acc; acc += t; }
    }
}
__global__ void scan3(const int* __restrict__ deg, const int* __restrict__ bsum,
                      int* __restrict__ rowptr, int* __restrict__ cur) {
    __shared__ int sh[256];
    int i = blockIdx.x * 256 + threadIdx.x;
    int v = (i < NN) ? deg[i] : 0;
    sh[threadIdx.x] = v;
    __syncthreads();
    for (int o = 1; o < 256; o <<= 1) {
        int t = (threadIdx.x >= o) ? sh[threadIdx.x - o] : 0;
        __syncthreads();
        sh[threadIdx.x] += t;
        __syncthreads();
    }
    int excl = sh[threadIdx.x] - v + bsum[blockIdx.x];
    if (i < NN) { rowptr[i] = excl; cur[i] = excl; }
    if (i == NN - 1) rowptr[NN] = excl + v;
}
__global__ void scatter_k(const int* __restrict__ src, const int* __restrict__ dst,
                          int* __restrict__ cur, int* __restrict__ csr) {
    int e = blockIdx.x * blockDim.x + threadIdx.x;
    if (e >= ET) return;
    int s, d;
    if (e < EE) { s = src[e]; d = dst[e]; } else { s = e - EE; d = s; }
    int pos = atomicAdd(&cur[d], 1);
    csr[pos] = s;
}

// ================= attention logits (layers 1/2) =================
__global__ void compute_al(const float* __restrict__ feat,
                           const float* __restrict__ a_src,
                           const float* __restrict__ a_dst,
                           float* __restrict__ als, float* __restrict__ ald,
                           int H, int C) {
    int w    = (blockIdx.x * blockDim.x + threadIdx.x) >> 5;
    int lane = threadIdx.x & 31;
    if (w >= NN * H) return;
    int n = w / H, h = w % H;
    const float* f  = feat + (size_t)n * H * C + (size_t)h * C;
    const float* as = a_src + h * C;
    const float* ad = a_dst + h * C;
    float s1 = 0.f, s2 = 0.f;
    for (int c = lane; c < C; c += 32) {
        float v = f[c];
        s1 += v * as[c];
        s2 += v * ad[c];
    }
#pragma unroll
    for (int o = 16; o; o >>= 1) {
        s1 += __shfl_down_sync(0xFFFFFFFFu, s1, o);
        s2 += __shfl_down_sync(0xFFFFFFFFu, s2, o);
    }
    if (lane == 0) { als[w] = s1; ald[w] = s2; }
}

// ================= layers 1/2: fused gather-aggregate =================
__global__ void __launch_bounds__(256) agg_fused12(
    const int* __restrict__ rowptr, const int* __restrict__ csr,
    const float* __restrict__ feat, const float* __restrict__ als,
    const float* __restrict__ ald, const float* __restrict__ bias,
    const float* __restrict__ res, float* __restrict__ out) {
    int gw   = blockIdx.x * 8 + (threadIdx.x >> 5);
    int lane = threadIdx.x & 31;
    int n = gw >> 1, half = gw & 1;
    if (n >= NN) return;
    int col = half * 128 + lane * 4;
    int hl  = half * 2 + (lane >= 16);
    float aldh = 0.f;
    if (lane == 0 || lane == 16) aldh = ald[n * 4 + hl];
    int beg = rowptr[n], end = rowptr[n + 1];
    float4 acc = make_float4(0.f, 0.f, 0.f, 0.f);
    float denom = 0.f;
    for (int p = beg; p < end; p++) {
        int s = __ldg(&csr[p]);
        float wv = 0.f;
        if (lane == 0 || lane == 16) {
            float v = als[s * 4 + hl] + aldh;
            v = v > 0.f ? v : 0.2f * v;
            wv = __expf(v);
        }
        float w = __shfl_sync(0xFFFFFFFFu, wv, (lane < 16) ? 0 : 16);
        float4 f = *(const float4*)(feat + (size_t)s * 256 + col);
        acc.x += f.x * w; acc.y += f.y * w; acc.z += f.z * w; acc.w += f.w * w;
        denom += w;
    }
    float inv = 1.f / (denom + 1e-16f);
    float4 b = *(const float4*)(bias + col);
    float4 v;
    v.x = acc.x * inv + b.x;
    v.y = acc.y * inv + b.y;
    v.z = acc.z * inv + b.z;
    v.w = acc.w * inv + b.w;
    if (res) {
        float4 r = *(const float4*)(res + (size_t)n * 256 + col);
        v.x += r.x; v.y += r.y; v.z += r.z; v.w += r.w;
    }
    v.x = v.x > 0.f ? v.x : (__expf(v.x) - 1.f);
    v.y = v.y > 0.f ? v.y : (__expf(v.y) - 1.f);
    v.z = v.z > 0.f ? v.z : (__expf(v.z) - 1.f);
    v.w = v.w > 0.f ? v.w : (__expf(v.w) - 1.f);
    *(float4*)(out + (size_t)n * 256 + col) = v;
}

// ================= layer 3 attention-weight prep =================
__global__ void build_wt(const float* __restrict__ W3, const float* __restrict__ a3s,
                         const float* __restrict__ a3d, float* __restrict__ Wt) {
    int i = blockIdx.x * blockDim.x + threadIdx.x;
    if (i >= 2 * 256 * 6) return;
    int side = i / (256 * 6);
    int r = i % (256 * 6);
    int k = r / 6, h = r % 6;
    const float* av = side ? a3d : a3s;
    float s = 0.f;
    for (int o = 0; o < 121; o++)
        s += W3[(size_t)k * 726 + h * 121 + o] * av[h * 121 + o];
    Wt[(size_t)side * 1536 + k * 6 + h] = s;
}
__global__ void __launch_bounds__(256) al3_k(
    const float* __restrict__ x, const float* __restrict__ Wt,
    float* __restrict__ als, float* __restrict__ ald) {
    int gw   = blockIdx.x * 8 + (threadIdx.x >> 5);
    int lane = threadIdx.x & 31;
    if (gw >= NN) return;
    const float4* xp = (const float4*)(x + (size_t)gw * 256);
    float4 a = xp[lane * 2], b = xp[lane * 2 + 1];
    float xv[8] = {a.x, a.y, a.z, a.w, b.x, b.y, b.z, b.w};
#pragma unroll
    for (int j = 0; j < 12; j++) {
        const float* W = Wt + (j >= 6 ? 1536 : 0);
        int jj = j % 6;
        float sum = 0.f;
#pragma unroll
        for (int i = 0; i < 8; i++)
            sum += xv[i] * W[(lane * 8 + i) * 6 + jj];
#pragma unroll
        for (int o = 16; o; o >>= 1) sum += __shfl_down_sync(0xFFFFFFFFu, sum, o);
        if (lane == 0) {
            if (j < 6) als[gw * 6 + jj] = sum;
            else       ald[gw * 6 + jj] = sum;
        }
    }
}

// ================= layer 3: fused gather in input space =================
__global__ void __launch_bounds__(256) agg_fused3(
    const int* __restrict__ rowptr, const int* __restrict__ csr,
    const float* __restrict__ x, const float* __restrict__ als,
    const float* __restrict__ ald, float* __restrict__ y) {
    int gw   = blockIdx.x * 8 + (threadIdx.x >> 5);
    int lane = threadIdx.x & 31;
    int n = gw >> 1, half = gw & 1;
    if (n >= NN) return;
    int col = half * 128 + lane * 4;
    float4 acc[6];
    float den[6];
#pragma unroll
    for (int h = 0; h < 6; h++) { acc[h] = make_float4(0.f, 0.f, 0.f, 0.f); den[h] = 0.f; }
    float aldl = (lane < 6) ? ald[n * 6 + lane] : 0.f;
    int beg = rowptr[n], end = rowptr[n + 1];
    for (int p = beg; p < end; p++) {
        int s = __ldg(&csr[p]);
        float wv = 0.f;
        if (lane < 6) {
            float v = als[s * 6 + lane] + aldl;
            v = v > 0.f ? v : 0.2f * v;
            wv = __expf(v);
        }
        float4 f = *(const float4*)(x + (size_t)s * 256 + col);
#pragma unroll
        for (int h = 0; h < 6; h++) {
            float w = __shfl_sync(0xFFFFFFFFu, wv, h);
            den[h] += w;
            acc[h].x += f.x * w; acc[h].y += f.y * w;
            acc[h].z += f.z * w; acc[h].w += f.w * w;
        }
    }
#pragma unroll
    for (int h = 0; h < 6; h++) {
        float inv = 1.f / (den[h] + 1e-16f);
        float4 v;
        v.x = acc[h].x * inv; v.y = acc[h].y * inv;
        v.z = acc[h].z * inv; v.w = acc[h].w * inv;
        *(float4*)(y + ((size_t)n * 6 + h) * 256 + col) = v;
    }
}

// ================= final sigmoid =================
__global__ void finalize3(const float* __restrict__ acc, const float* __restrict__ bias,
                          float* __restrict__ out) {
    long i = (long)blockIdx.x * blockDim.x + threadIdx.x;
    if (i >= (long)NN * 121) return;
    int n = (int)(i / 121), o = (int)(i % 121);
    float v = acc[(size_t)n * 128 + o] + bias[o];
    out[i] = 1.f / (1.f + __expf(-v));
}

// ================= host driver =================
extern "C" void kernel_launch(void* const* d_in, const int* in_sizes, int n_in,
                              void* d_out, int out_size) {
    const float* x     = (const float*)d_in[0];
    const int*   src   = (const int*)  d_in[1];
    const int*   dst   = (const int*)  d_in[2];
    const float* W1    = (const float*)d_in[3];
    const float* a1s   = (const float*)d_in[4];
    const float* a1d   = (const float*)d_in[5];
    const float* b1    = (const float*)d_in[6];
    const float* W2    = (const float*)d_in[7];
    const float* a2s   = (const float*)d_in[8];
    const float* a2d   = (const float*)d_in[9];
    const float* b2    = (const float*)d_in[10];
    const float* Wres2 = (const float*)d_in[11];
    const float* W3    = (const float*)d_in[12];
    const float* a3s   = (const float*)d_in[13];
    const float* a3d   = (const float*)d_in[14];
    const float* b3    = (const float*)d_in[15];
    float* out = (float*)d_out;

    float *p_feat, *p_x, *p_res, *p_y, *p_acc, *p_als, *p_ald, *p_Wt;
    int *p_csr, *p_rowptr, *p_cur, *p_bsum;
    __nv_bfloat16 *w1h, *w1l, *w2h, *w2l, *wrh, *wrl, *bph, *bpl;
    cudaGetSymbolAddress((void**)&p_feat,   g_feat);
    cudaGetSymbolAddress((void**)&p_x,      g_x);
    cudaGetSymbolAddress((void**)&p_res,    g_res);
    cudaGetSymbolAddress((void**)&p_y,      g_y);
    cudaGetSymbolAddress((void**)&p_acc,    g_acc);
    cudaGetSymbolAddress((void**)&p_als,    g_als);
    cudaGetSymbolAddress((void**)&p_ald,    g_ald);
    cudaGetSymbolAddress((void**)&p_Wt,     g_Wt);
    cudaGetSymbolAddress((void**)&p_csr,    g_csr);
    cudaGetSymbolAddress((void**)&p_rowptr, g_rowptr);
    cudaGetSymbolAddress((void**)&p_cur,    g_cur);
    cudaGetSymbolAddress((void**)&p_bsum,   g_bsum);
    cudaGetSymbolAddress((void**)&w1h, g_w1t_hi);  cudaGetSymbolAddress((void**)&w1l, g_w1t_lo);
    cudaGetSymbolAddress((void**)&w2h, g_w2t_hi);  cudaGetSymbolAddress((void**)&w2l, g_w2t_lo);
    cudaGetSymbolAddress((void**)&wrh, g_wrt_hi);  cudaGetSymbolAddress((void**)&wrl, g_wrt_lo);
    cudaGetSymbolAddress((void**)&bph, g_bpt_hi);  cudaGetSymbolAddress((void**)&bpl, g_bpt_lo);

    // ---- CSR build ----
    zeroi<<<(NN + 255) / 256, 256>>>(p_cur, NN);
    hist_k<<<(ET + 255) / 256, 256>>>(dst, p_cur);
    scan1<<<196, 256>>>(p_cur, p_bsum);
    scan2<<<1, 32>>>(p_bsum, 196);
    scan3<<<196, 256>>>(p_cur, p_bsum, p_rowptr, p_cur);
    scatter_k<<<(ET + 255) / 256, 256>>>(src, dst, p_cur, p_csr);

    // ---- weight prep ----
    wsplit<<<(256 * 128 + 255) / 256, 256>>>(W1, w1h, w1l, 128, 256);
    wsplit<<<(256 * 256 + 255) / 256, 256>>>(W2, w2h, w2l, 256, 256);
    wsplit<<<(256 * 256 + 255) / 256, 256>>>(Wres2, wrh, wrl, 256, 256);
    bsplit3<<<(128 * 1536 + 255) / 256, 256>>>(W3, bph, bpl);
    build_wt<<<(2 * 256 * 6 + 255) / 256, 256>>>(W3, a3s, a3d, p_Wt);

    // ---- Layer 1: 128 -> 4x64 concat, ELU ----
    {
        dim3 g(2, (NN + 127) / 128);
        mma_gemm<<<g, 256>>>(x, w1h, w1l, p_feat, NN, 128, 256);
        compute_al<<<(NN * 4 * 32 + 255) / 256, 256>>>(p_feat, a1s, a1d, p_als, p_ald, 4, 64);
        agg_fused12<<<(NN * 2 + 7) / 8, 256>>>(p_rowptr, p_csr, p_feat, p_als, p_ald, b1, nullptr, p_x);
    }
    // ---- Layer 2: 256 -> 4x64 concat + residual, ELU ----
    {
        dim3 g(2, (NN + 127) / 128);
        mma_gemm<<<g, 256>>>(p_x, w2h, w2l, p_feat, NN, 256, 256);
        mma_gemm<<<g, 256>>>(p_x, wrh, wrl, p_res, NN, 256, 256);
        compute_al<<<(NN * 4 * 32 + 255) / 256, 256>>>(p_feat, a2s, a2d, p_als, p_ald, 4, 64);
        agg_fused12<<<(NN * 2 + 7) / 8, 256>>>(p_rowptr, p_csr, p_feat, p_als, p_ald, b2, p_res, p_x);
    }
    // ---- Layer 3 ----
    {
        al3_k<<<(NN + 7) / 8, 256>>>(p_x, p_Wt, p_als, p_ald);
        agg_fused3<<<(NN * 2 + 7) / 8, 256>>>(p_rowptr, p_csr, p_x, p_als, p_ald, p_y);
        dim3 g(1, (NN + 127) / 128);
        mma_gemm<<<g, 256>>>(p_y, bph, bpl, p_acc, NN, 1536, 128);
        finalize3<<<(NN * 121 + 255) / 256, 256>>>(p_acc, b3, out);
    }
}

// round 6
// speedup vs baseline: 3.4729x; 1.0304x over previous
#include <cuda_runtime.h>
#include <cuda_bf16.h>
#include <cuda_fp16.h>
#include <math.h>
#include <stdint.h>

#define NN 50000
#define EE 800000
#define ET (EE + NN)

// ---------------- device scratch (allocation-free) ----------------
__device__ __half g_feat[(size_t)NN * 512];   // layer1: [N,256]; layer2: [N,512] (cols 256+ = residual)
__device__ __half g_x   [(size_t)NN * 256];   // activations (fp16)
__device__ __half g_y   [(size_t)NN * 1536];  // layer3 aggregated input space
__device__ float  g_acc [(size_t)NN * 128];   // layer3 GEMM out (padded)
__device__ float  g_als [NN * 6];
__device__ float  g_ald [NN * 6];
__device__ float  g_Wt  [2 * 256 * 6];
__device__ int    g_csr [ET];
__device__ int    g_rowptr[NN + 1];
__device__ int    g_cur [NN];
__device__ int    g_bsum[256];
// K-major bf16 hi/lo weights
__device__ __nv_bfloat16 g_w1t_hi[256 * 128],  g_w1t_lo[256 * 128];
__device__ __nv_bfloat16 g_w2t_hi[512 * 256],  g_w2t_lo[512 * 256];   // W2 rows 0-255, Wres2 rows 256-511
__device__ __nv_bfloat16 g_bpt_hi[128 * 1536], g_bpt_lo[128 * 1536];

// ---------------- split / pack helpers ----------------
__device__ __forceinline__ uint32_t pack_hi(float x, float y, float& rx, float& ry) {
    uint32_t h;
    asm("cvt.rn.bf16x2.f32 %0, %1, %2;" : "=r"(h) : "f"(y), "f"(x));
    rx = x - __uint_as_float(h << 16);
    ry = y - __uint_as_float(h & 0xFFFF0000u);
    return h;
}
__device__ __forceinline__ uint32_t pack2(float x, float y) {
    uint32_t h;
    asm("cvt.rn.bf16x2.f32 %0, %1, %2;" : "=r"(h) : "f"(y), "f"(x));
    return h;
}
__device__ __forceinline__ void mma16816(float* c, const uint32_t* a, const uint32_t* b) {
    asm volatile(
        "mma.sync.aligned.m16n8k16.row.col.f32.bf16.bf16.f32 "
        "{%0,%1,%2,%3}, {%4,%5,%6,%7}, {%8,%9}, {%0,%1,%2,%3};"
        : "+f"(c[0]), "+f"(c[1]), "+f"(c[2]), "+f"(c[3])
        : "r"(a[0]), "r"(a[1]), "r"(a[2]), "r"(a[3]), "r"(b[0]), "r"(b[1]));
}
// load 16 elements of A row, split into 8 bf16x2 hi + 8 lo words
__device__ __forceinline__ void load_split16(const float* ap, bool valid,
                                             uint32_t* dh, uint32_t* dl) {
#pragma unroll
    for (int i = 0; i < 4; i++) {
        float4 v = valid ? ((const float4*)ap)[i] : make_float4(0.f, 0.f, 0.f, 0.f);
        float r0, r1, r2, r3;
        dh[2 * i]     = pack_hi(v.x, v.y, r0, r1);
        dh[2 * i + 1] = pack_hi(v.z, v.w, r2, r3);
        dl[2 * i]     = pack2(r0, r1);
        dl[2 * i + 1] = pack2(r2, r3);
    }
}
__device__ __forceinline__ void load_split16(const __half* ap, bool valid,
                                             uint32_t* dh, uint32_t* dl) {
    const uint4* p = (const uint4*)ap;
    uint4 ra = valid ? p[0] : make_uint4(0, 0, 0, 0);
    uint4 rb = valid ? p[1] : make_uint4(0, 0, 0, 0);
    uint32_t w[8] = {ra.x, ra.y, ra.z, ra.w, rb.x, rb.y, rb.z, rb.w};
#pragma unroll
    for (int i = 0; i < 8; i++) {
        float2 f = __half22float2(*(__half2*)&w[i]);
        float r0, r1;
        dh[i] = pack_hi(f.x, f.y, r0, r1);
        dl[i] = pack2(r0, r1);
    }
}
__device__ __forceinline__ void store_c2(float* C, size_t idx, float a, float b) {
    *(float2*)(C + idx) = make_float2(a, b);
}
__device__ __forceinline__ void store_c2(__half* C, size_t idx, float a, float b) {
    *(__half2*)(C + idx) = __floats2half2_rn(a, b);
}

// ================= HMMA GEMM: C[M,Nc] = A[M,K] @ (Bt[Nc,K])^T =================
// Tile 128x128, K-chunk 32. 8 warps: 2(M) x 4(N). bf16 3-term split, fp32 accum.
#define SSTR 17
template <typename AT, typename CT>
__global__ void __launch_bounds__(256) mma_gemm(
    const AT* __restrict__ A,
    const __nv_bfloat16* __restrict__ Bth, const __nv_bfloat16* __restrict__ Btl,
    CT* __restrict__ C, int M, int K, int Nc) {
    __shared__ uint32_t sAh[128 * SSTR], sAl[128 * SSTR];
    __shared__ uint32_t sBh[128 * SSTR], sBl[128 * SSTR];
    const int tid = threadIdx.x, wid = tid >> 5, lane = tid & 31;
    const int wm = wid & 1, wn = wid >> 1;
    const int bm = blockIdx.y * 128, bn = blockIdx.x * 128;
    const int g = lane >> 2, tg = lane & 3;

    float acc[4][4][4];
#pragma unroll
    for (int i = 0; i < 4; i++)
#pragma unroll
        for (int j = 0; j < 4; j++)
#pragma unroll
            for (int q = 0; q < 4; q++) acc[i][j][q] = 0.f;

    const int lrow = tid >> 1, lhalf = (tid & 1) * 16;
    const int gr = bm + lrow;
    const int gn = bn + lrow;

    for (int k0 = 0; k0 < K; k0 += 32) {
        load_split16(A + (size_t)gr * K + k0 + lhalf, gr < M,
                     sAh + lrow * SSTR + (lhalf >> 1), sAl + lrow * SSTR + (lhalf >> 1));
        {
            const uint32_t* bh = (const uint32_t*)(Bth + (size_t)gn * K + k0 + lhalf);
            const uint32_t* bl = (const uint32_t*)(Btl + (size_t)gn * K + k0 + lhalf);
            uint32_t* dh = sBh + lrow * SSTR + (lhalf >> 1);
            uint32_t* dl = sBl + lrow * SSTR + (lhalf >> 1);
#pragma unroll
            for (int i = 0; i < 8; i++) { dh[i] = bh[i]; dl[i] = bl[i]; }
        }
        __syncthreads();

#pragma unroll
        for (int ks = 0; ks < 2; ks++) {
            const int kb = ks * 8;
            uint32_t ah[4][4], al[4][4], bh[4][2], bl[4][2];
#pragma unroll
            for (int mi = 0; mi < 4; mi++) {
                int r0 = wm * 64 + mi * 16 + g;
                const uint32_t* ph = sAh + r0 * SSTR + kb + tg;
                const uint32_t* pl = sAl + r0 * SSTR + kb + tg;
                ah[mi][0] = ph[0]; ah[mi][1] = ph[8 * SSTR];
                ah[mi][2] = ph[4]; ah[mi][3] = ph[8 * SSTR + 4];
                al[mi][0] = pl[0]; al[mi][1] = pl[8 * SSTR];
                al[mi][2] = pl[4]; al[mi][3] = pl[8 * SSTR + 4];
            }
#pragma unroll
            for (int nj = 0; nj < 4; nj++) {
                int n0 = wn * 32 + nj * 8 + g;
                const uint32_t* ph = sBh + n0 * SSTR + kb + tg;
                const uint32_t* pl = sBl + n0 * SSTR + kb + tg;
                bh[nj][0] = ph[0]; bh[nj][1] = ph[4];
                bl[nj][0] = pl[0]; bl[nj][1] = pl[4];
            }
#pragma unroll
            for (int mi = 0; mi < 4; mi++)
#pragma unroll
                for (int nj = 0; nj < 4; nj++) {
                    mma16816(acc[mi][nj], ah[mi], bh[nj]);
                    mma16816(acc[mi][nj], ah[mi], bl[nj]);
                    mma16816(acc[mi][nj], al[mi], bh[nj]);
                }
        }
        __syncthreads();
    }

#pragma unroll
    for (int mi = 0; mi < 4; mi++) {
        int row = bm + wm * 64 + mi * 16 + g;
#pragma unroll
        for (int nj = 0; nj < 4; nj++) {
            int col = bn + wn * 32 + nj * 8 + tg * 2;
            if (row < M)     store_c2(C, (size_t)row * Nc + col, acc[mi][nj][0], acc[mi][nj][1]);
            if (row + 8 < M) store_c2(C, (size_t)(row + 8) * Nc + col, acc[mi][nj][2], acc[mi][nj][3]);
        }
    }
}

// ================= weight prep =================
__global__ void wsplit(const float* __restrict__ W, __nv_bfloat16* __restrict__ hi,
                       __nv_bfloat16* __restrict__ lo, int K, int Nc) {
    long i = (long)blockIdx.x * blockDim.x + threadIdx.x;
    if (i >= (long)K * Nc) return;
    int n = (int)(i / K), k = (int)(i % K);
    float v = W[(size_t)k * Nc + n];
    __nv_bfloat16 h = __float2bfloat16(v);
    hi[i] = h;
    lo[i] = __float2bfloat16(v - __bfloat162float(h));
}
__global__ void bsplit3(const float* __restrict__ W3, __nv_bfloat16* __restrict__ hi,
                        __nv_bfloat16* __restrict__ lo) {
    long i = (long)blockIdx.x * blockDim.x + threadIdx.x;
    if (i >= 128L * 1536) return;
    int n = (int)(i / 1536), kk = (int)(i % 1536);
    int h_ = kk >> 8, k = kk & 255;
    float v = (n < 121) ? W3[(size_t)k * 726 + h_ * 121 + n] * (1.f / 6.f) : 0.f;
    __nv_bfloat16 h = __float2bfloat16(v);
    hi[i] = h;
    lo[i] = __float2bfloat16(v - __bfloat162float(h));
}

// ================= CSR build =================
__global__ void zeroi(int* __restrict__ p, int n) {
    int i = blockIdx.x * blockDim.x + threadIdx.x;
    if (i < n) p[i] = 0;
}
__global__ void hist_k(const int* __restrict__ dst, int* __restrict__ cur) {
    int e = blockIdx.x * blockDim.x + threadIdx.x;
    if (e >= ET) return;
    int d = (e < EE) ? dst[e] : e - EE;
    atomicAdd(&cur[d], 1);
}
__global__ void scan1(const int* __restrict__ deg, int* __restrict__ bsum) {
    __shared__ int sh[256];
    int i = blockIdx.x * 256 + threadIdx.x;
    sh[threadIdx.x] = (i < NN) ? deg[i] : 0;
    __syncthreads();
    for (int o = 128; o; o >>= 1) {
        if (threadIdx.x < o) sh[threadIdx.x] += sh[threadIdx.x + o];
        __syncthreads();
    }
    if (threadIdx.x == 0) bsum[blockIdx.x] = sh[0];
}
__global__ void scan2(int* __restrict__ bsum, int nb) {
    __shared__ int sh[256];
    int t = threadIdx.x;
    int v = (t < nb) ? bsum[t] : 0;
    sh[t] = v;
    __syncthreads();
    for (int o = 1; o < 256; o <<= 1) {
        int x2 = (t >= o) ? sh[t - o] : 0;
        __syncthreads();
        sh[t] += x2;
        __syncthreads();
    }
    if (t < nb) bsum[t] = sh[t] - v;   // exclusive
}
__global__ void scan3(const int* __restrict__ deg, const int* __restrict__ bsum,
                      int* __restrict__ rowptr, int* __restrict__ cur) {
    __shared__ int sh[256];
    int i = blockIdx.x * 256 + threadIdx.x;
    int v = (i < NN) ? deg[i] : 0;
    sh[threadIdx.x] = v;
    __syncthreads();
    for (int o = 1; o < 256; o <<= 1) {
        int t = (threadIdx.x >= o) ? sh[threadIdx.x - o] : 0;
        __syncthreads();
        sh[threadIdx.x] += t;
        __syncthreads();
    }
    int excl = sh[threadIdx.x] - v + bsum[blockIdx.x];
    if (i < NN) { rowptr[i] = excl; cur[i] = excl; }
    if (i == NN - 1) rowptr[NN] = excl + v;
}
__global__ void scatter_k(const int* __restrict__ src, const int* __restrict__ dst,
                          int* __restrict__ cur, int* __restrict__ csr) {
    int e = blockIdx.x * blockDim.x + threadIdx.x;
    if (e >= ET) return;
    int s, d;
    if (e < EE) { s = src[e]; d = dst[e]; } else { s = e - EE; d = s; }
    int pos = atomicAdd(&cur[d], 1);
    csr[pos] = s;
}

// ================= attention logits (layers 1/2), fp16 feat =================
__global__ void compute_al(const __half* __restrict__ feat, int fstride,
                           const float* __restrict__ a_src,
                           const float* __restrict__ a_dst,
                           float* __restrict__ als, float* __restrict__ ald,
                           int H, int C) {
    int w    = (blockIdx.x * blockDim.x + threadIdx.x) >> 5;
    int lane = threadIdx.x & 31;
    if (w >= NN * H) return;
    int n = w / H, h = w % H;
    const __half* f = feat + (size_t)n * fstride + (size_t)h * C;
    const float* as = a_src + h * C;
    const float* ad = a_dst + h * C;
    float s1 = 0.f, s2 = 0.f;
    for (int c = lane; c < C; c += 32) {
        float v = __half2float(f[c]);
        s1 += v * as[c];
        s2 += v * ad[c];
    }
#pragma unroll
    for (int o = 16; o; o >>= 1) {
        s1 += __shfl_down_sync(0xFFFFFFFFu, s1, o);
        s2 += __shfl_down_sync(0xFFFFFFFFu, s2, o);
    }
    if (lane == 0) { als[w] = s1; ald[w] = s2; }
}

// ================= layers 1/2: fused gather-aggregate (fp16 feat) =================
__global__ void __launch_bounds__(256) agg_fused12(
    const int* __restrict__ rowptr, const int* __restrict__ csr,
    const __half* __restrict__ feat, int fstride,
    const float* __restrict__ als, const float* __restrict__ ald,
    const float* __restrict__ bias, int has_res, __half* __restrict__ out) {
    int gw   = blockIdx.x * 8 + (threadIdx.x >> 5);
    int lane = threadIdx.x & 31;
    int n = gw >> 1, half_ = gw & 1;
    if (n >= NN) return;
    int col = half_ * 128 + lane * 4;
    int hl  = half_ * 2 + (lane >= 16);
    float aldh = 0.f;
    if (lane == 0 || lane == 16) aldh = ald[n * 4 + hl];
    int beg = rowptr[n], end = rowptr[n + 1];
    float4 acc = make_float4(0.f, 0.f, 0.f, 0.f);
    float denom = 0.f;
    int p = beg;
    for (; p + 2 <= end; p += 2) {
        int s0 = __ldg(&csr[p]), s1 = __ldg(&csr[p + 1]);
        float wv0 = 0.f, wv1 = 0.f;
        if (lane == 0 || lane == 16) {
            float v0 = als[s0 * 4 + hl] + aldh; v0 = v0 > 0.f ? v0 : 0.2f * v0;
            float v1 = als[s1 * 4 + hl] + aldh; v1 = v1 > 0.f ? v1 : 0.2f * v1;
            wv0 = __expf(v0); wv1 = __expf(v1);
        }
        uint2 r0 = *(const uint2*)(feat + (size_t)s0 * fstride + col);
        uint2 r1 = *(const uint2*)(feat + (size_t)s1 * fstride + col);
        float w0 = __shfl_sync(0xFFFFFFFFu, wv0, (lane < 16) ? 0 : 16);
        float w1 = __shfl_sync(0xFFFFFFFFu, wv1, (lane < 16) ? 0 : 16);
        float2 a0 = __half22float2(*(__half2*)&r0.x), b0 = __half22float2(*(__half2*)&r0.y);
        float2 a1 = __half22float2(*(__half2*)&r1.x), b1 = __half22float2(*(__half2*)&r1.y);
        acc.x += a0.x * w0 + a1.x * w1;
        acc.y += a0.y * w0 + a1.y * w1;
        acc.z += b0.x * w0 + b1.x * w1;
        acc.w += b0.y * w0 + b1.y * w1;
        denom += w0 + w1;
    }
    if (p < end) {
        int s = __ldg(&csr[p]);
        float wv = 0.f;
        if (lane == 0 || lane == 16) {
            float v = als[s * 4 + hl] + aldh;
            v = v > 0.f ? v : 0.2f * v;
            wv = __expf(v);
        }
        float w = __shfl_sync(0xFFFFFFFFu, wv, (lane < 16) ? 0 : 16);
        uint2 r = *(const uint2*)(feat + (size_t)s * fstride + col);
        float2 a = __half22float2(*(__half2*)&r.x), b = __half22float2(*(__half2*)&r.y);
        acc.x += a.x * w; acc.y += a.y * w; acc.z += b.x * w; acc.w += b.y * w;
        denom += w;
    }
    float inv = 1.f / (denom + 1e-16f);
    float4 bb = *(const float4*)(bias + col);
    float4 v;
    v.x = acc.x * inv + bb.x;
    v.y = acc.y * inv + bb.y;
    v.z = acc.z * inv + bb.z;
    v.w = acc.w * inv + bb.w;
    if (has_res) {
        uint2 rr = *(const uint2*)(feat + (size_t)n * fstride + 256 + col);
        float2 ra = __half22float2(*(__half2*)&rr.x), rb = __half22float2(*(__half2*)&rr.y);
        v.x += ra.x; v.y += ra.y; v.z += rb.x; v.w += rb.y;
    }
    v.x = v.x > 0.f ? v.x : (__expf(v.x) - 1.f);
    v.y = v.y > 0.f ? v.y : (__expf(v.y) - 1.f);
    v.z = v.z > 0.f ? v.z : (__expf(v.z) - 1.f);
    v.w = v.w > 0.f ? v.w : (__expf(v.w) - 1.f);
    __half2 o0 = __floats2half2_rn(v.x, v.y);
    __half2 o1 = __floats2half2_rn(v.z, v.w);
    *(uint2*)(out + (size_t)n * 256 + col) = make_uint2(*(uint32_t*)&o0, *(uint32_t*)&o1);
}

// ================= layer 3 attention-weight prep =================
__global__ void build_wt(const float* __restrict__ W3, const float* __restrict__ a3s,
                         const float* __restrict__ a3d, float* __restrict__ Wt) {
    int i = blockIdx.x * blockDim.x + threadIdx.x;
    if (i >= 2 * 256 * 6) return;
    int side = i / (256 * 6);
    int r = i % (256 * 6);
    int k = r / 6, h = r % 6;
    const float* av = side ? a3d : a3s;
    float s = 0.f;
    for (int o = 0; o < 121; o++)
        s += W3[(size_t)k * 726 + h * 121 + o] * av[h * 121 + o];
    Wt[(size_t)side * 1536 + k * 6 + h] = s;
}
__global__ void __launch_bounds__(256) al3_k(
    const __half* __restrict__ x, const float* __restrict__ Wt,
    float* __restrict__ als, float* __restrict__ ald) {
    int gw   = blockIdx.x * 8 + (threadIdx.x >> 5);
    int lane = threadIdx.x & 31;
    if (gw >= NN) return;
    const uint4* xp = (const uint4*)(x + (size_t)gw * 256);
    uint4 raw = xp[lane];    // 8 halves
    uint32_t w[4] = {raw.x, raw.y, raw.z, raw.w};
    float xv[8];
#pragma unroll
    for (int i = 0; i < 4; i++) {
        float2 f = __half22float2(*(__half2*)&w[i]);
        xv[2 * i] = f.x; xv[2 * i + 1] = f.y;
    }
#pragma unroll
    for (int j = 0; j < 12; j++) {
        const float* W = Wt + (j >= 6 ? 1536 : 0);
        int jj = j % 6;
        float sum = 0.f;
#pragma unroll
        for (int i = 0; i < 8; i++)
            sum += xv[i] * W[(lane * 8 + i) * 6 + jj];
#pragma unroll
        for (int o = 16; o; o >>= 1) sum += __shfl_down_sync(0xFFFFFFFFu, sum, o);
        if (lane == 0) {
            if (j < 6) als[gw * 6 + jj] = sum;
            else       ald[gw * 6 + jj] = sum;
        }
    }
}

// ================= layer 3: fused gather in input space (fp16) =================
__global__ void __launch_bounds__(256) agg_fused3(
    const int* __restrict__ rowptr, const int* __restrict__ csr,
    const __half* __restrict__ x, const float* __restrict__ als,
    const float* __restrict__ ald, __half* __restrict__ y) {
    int gw   = blockIdx.x * 8 + (threadIdx.x >> 5);
    int lane = threadIdx.x & 31;
    int n = gw >> 1, half_ = gw & 1;
    if (n >= NN) return;
    int col = half_ * 128 + lane * 4;
    float4 acc[6];
    float den[6];
#pragma unroll
    for (int h = 0; h < 6; h++) { acc[h] = make_float4(0.f, 0.f, 0.f, 0.f); den[h] = 0.f; }
    float aldl = (lane < 6) ? ald[n * 6 + lane] : 0.f;
    int beg = rowptr[n], end = rowptr[n + 1];
    for (int p = beg; p < end; p++) {
        int s = __ldg(&csr[p]);
        float wv = 0.f;
        if (lane < 6) {
            float v = als[s * 6 + lane] + aldl;
            v = v > 0.f ? v : 0.2f * v;
            wv = __expf(v);
        }
        uint2 r = *(const uint2*)(x + (size_t)s * 256 + col);
        float2 fa = __half22float2(*(__half2*)&r.x), fb = __half22float2(*(__half2*)&r.y);
#pragma unroll
        for (int h = 0; h < 6; h++) {
            float w = __shfl_sync(0xFFFFFFFFu, wv, h);
            den[h] += w;
            acc[h].x += fa.x * w; acc[h].y += fa.y * w;
            acc[h].z += fb.x * w; acc[h].w += fb.y * w;
        }
    }
#pragma unroll
    for (int h = 0; h < 6; h++) {
        float inv = 1.f / (den[h] + 1e-16f);
        __half2 o0 = __floats2half2_rn(acc[h].x * inv, acc[h].y * inv);
        __half2 o1 = __floats2half2_rn(acc[h].z * inv, acc[h].w * inv);
        *(uint2*)(y + ((size_t)n * 6 + h) * 256 + col) =
            make_uint2(*(uint32_t*)&o0, *(uint32_t*)&o1);
    }
}

// ================= final sigmoid =================
__global__ void finalize3(const float* __restrict__ acc, const float* __restrict__ bias,
                          float* __restrict__ out) {
    long i = (long)blockIdx.x * blockDim.x + threadIdx.x;
    if (i >= (long)NN * 121) return;
    int n = (int)(i / 121), o = (int)(i % 121);
    float v = acc[(size_t)n * 128 + o] + bias[o];
    out[i] = 1.f / (1.f + __expf(-v));
}

// ================= host driver =================
extern "C" void kernel_launch(void* const* d_in, const int* in_sizes, int n_in,
                              void* d_out, int out_size) {
    const float* x     = (const float*)d_in[0];
    const int*   src   = (const int*)  d_in[1];
    const int*   dst   = (const int*)  d_in[2];
    const float* W1    = (const float*)d_in[3];
    const float* a1s   = (const float*)d_in[4];
    const float* a1d   = (const float*)d_in[5];
    const float* b1    = (const float*)d_in[6];
    const float* W2    = (const float*)d_in[7];
    const float* a2s   = (const float*)d_in[8];
    const float* a2d   = (const float*)d_in[9];
    const float* b2    = (const float*)d_in[10];
    const float* Wres2 = (const float*)d_in[11];
    const float* W3    = (const float*)d_in[12];
    const float* a3s   = (const float*)d_in[13];
    const float* a3d   = (const float*)d_in[14];
    const float* b3    = (const float*)d_in[15];
    float* out = (float*)d_out;

    __half *p_feat, *p_x, *p_y;
    float *p_acc, *p_als, *p_ald, *p_Wt;
    int *p_csr, *p_rowptr, *p_cur, *p_bsum;
    __nv_bfloat16 *w1h, *w1l, *w2h, *w2l, *bph, *bpl;
    cudaGetSymbolAddress((void**)&p_feat,   g_feat);
    cudaGetSymbolAddress((void**)&p_x,      g_x);
    cudaGetSymbolAddress((void**)&p_y,      g_y);
    cudaGetSymbolAddress((void**)&p_acc,    g_acc);
    cudaGetSymbolAddress((void**)&p_als,    g_als);
    cudaGetSymbolAddress((void**)&p_ald,    g_ald);
    cudaGetSymbolAddress((void**)&p_Wt,     g_Wt);
    cudaGetSymbolAddress((void**)&p_csr,    g_csr);
    cudaGetSymbolAddress((void**)&p_rowptr, g_rowptr);
    cudaGetSymbolAddress((void**)&p_cur,    g_cur);
    cudaGetSymbolAddress((void**)&p_bsum,   g_bsum);
    cudaGetSymbolAddress((void**)&w1h, g_w1t_hi);  cudaGetSymbolAddress((void**)&w1l, g_w1t_lo);
    cudaGetSymbolAddress((void**)&w2h, g_w2t_hi);  cudaGetSymbolAddress((void**)&w2l, g_w2t_lo);
    cudaGetSymbolAddress((void**)&bph, g_bpt_hi);  cudaGetSymbolAddress((void**)&bpl, g_bpt_lo);

    // ---- CSR build ----
    zeroi<<<(NN + 255) / 256, 256>>>(p_cur, NN);
    hist_k<<<(ET + 255) / 256, 256>>>(dst, p_cur);
    scan1<<<196, 256>>>(p_cur, p_bsum);
    scan2<<<1, 256>>>(p_bsum, 196);
    scan3<<<196, 256>>>(p_cur, p_bsum, p_rowptr, p_cur);
    scatter_k<<<(ET + 255) / 256, 256>>>(src, dst, p_cur, p_csr);

    // ---- weight prep ----
    wsplit<<<(256 * 128 + 255) / 256, 256>>>(W1, w1h, w1l, 128, 256);
    wsplit<<<(256 * 256 + 255) / 256, 256>>>(W2, w2h, w2l, 256, 256);
    wsplit<<<(256 * 256 + 255) / 256, 256>>>(Wres2, w2h + 256 * 256, w2l + 256 * 256, 256, 256);
    bsplit3<<<(128 * 1536 + 255) / 256, 256>>>(W3, bph, bpl);
    build_wt<<<(2 * 256 * 6 + 255) / 256, 256>>>(W3, a3s, a3d, p_Wt);

    // ---- Layer 1: 128 -> 4x64 concat, ELU ----
    {
        dim3 g(2, (NN + 127) / 128);
        mma_gemm<float, __half><<<g, 256>>>(x, w1h, w1l, p_feat, NN, 128, 256);
        compute_al<<<(NN * 4 * 32 + 255) / 256, 256>>>(p_feat, 256, a1s, a1d, p_als, p_ald, 4, 64);
        agg_fused12<<<(NN * 2 + 7) / 8, 256>>>(p_rowptr, p_csr, p_feat, 256, p_als, p_ald, b1, 0, p_x);
    }
    // ---- Layer 2: 256 -> 4x64 concat + residual (merged GEMM Nc=512), ELU ----
    {
        dim3 g(4, (NN + 127) / 128);
        mma_gemm<__half, __half><<<g, 256>>>(p_x, w2h, w2l, p_feat, NN, 256, 512);
        compute_al<<<(NN * 4 * 32 + 255) / 256, 256>>>(p_feat, 512, a2s, a2d, p_als, p_ald, 4, 64);
        agg_fused12<<<(NN * 2 + 7) / 8, 256>>>(p_rowptr, p_csr, p_feat, 512, p_als, p_ald, b2, 1, p_x);
    }
    // ---- Layer 3: aggregate in input space, K=1536 GEMM, sigmoid ----
    {
        al3_k<<<(NN + 7) / 8, 256>>>(p_x, p_Wt, p_als, p_ald);
        agg_fused3<<<(NN * 2 + 7) / 8, 256>>>(p_rowptr, p_csr, p_x, p_als, p_ald, p_y);
        dim3 g(1, (NN + 127) / 128);
        mma_gemm<__half, float><<<g, 256>>>(p_y, bph, bpl, p_acc, NN, 1536, 128);
        finalize3<<<(NN * 121 + 255) / 256, 256>>>(p_acc, b3, out);
    }
}

// round 7
// speedup vs baseline: 4.9948x; 1.4382x over previous
#include <cuda_runtime.h>
#include <cuda_fp16.h>
#include <math.h>
#include <stdint.h>

#define NN 50000
#define EE 800000
#define ET (EE + NN)

// ---------------- device scratch (allocation-free) ----------------
__device__ __half g_x0  [(size_t)NN * 128];   // input x in fp16
__device__ __half g_feat[(size_t)NN * 512];   // layer1: [N,256]; layer2: [N,512] (cols 256+ = residual)
__device__ __half g_x   [(size_t)NN * 256];   // activations (fp16)
__device__ __half g_y   [(size_t)NN * 1536];  // layer3 aggregated input space
__device__ float  g_acc [(size_t)NN * 128];   // layer3 GEMM out (padded)
__device__ float  g_als [NN * 6];
__device__ float  g_ald [NN * 6];
__device__ float  g_Wt  [2 * 256 * 6];
__device__ int    g_csr [ET];
__device__ int    g_rowptr[NN + 1];
__device__ int    g_cur [NN];
__device__ int    g_bsum[256];
// K-major fp16 weights
__device__ __half g_w1t[256 * 128];
__device__ __half g_w2t[512 * 256];            // W2 rows 0-255, Wres2 rows 256-511
__device__ __half g_bpt[128 * 1536];

// ---------------- helpers ----------------
__device__ __forceinline__ void mma16816(float* c, const uint32_t* a, const uint32_t* b) {
    asm volatile(
        "mma.sync.aligned.m16n8k16.row.col.f32.f16.f16.f32 "
        "{%0,%1,%2,%3}, {%4,%5,%6,%7}, {%8,%9}, {%0,%1,%2,%3};"
        : "+f"(c[0]), "+f"(c[1]), "+f"(c[2]), "+f"(c[3])
        : "r"(a[0]), "r"(a[1]), "r"(a[2]), "r"(a[3]), "r"(b[0]), "r"(b[1]));
}
__device__ __forceinline__ void store_c2(float* C, size_t idx, float a, float b) {
    *(float2*)(C + idx) = make_float2(a, b);
}
__device__ __forceinline__ void store_c2(__half* C, size_t idx, float a, float b) {
    *(__half2*)(C + idx) = __floats2half2_rn(a, b);
}

// ================= HMMA GEMM: C[M,Nc] = A[M,K] @ (Bt[Nc,K])^T =================
// A, Bt fp16 (Bt K-major). Tile 128x128, K-chunk 64. 8 warps: 2(M) x 4(N).
#define SSTR 36   // uint32 per smem row: 32 data + 4 pad (16B-aligned, conflict-free)
template <typename CT>
__global__ void __launch_bounds__(256) mma_gemm(
    const __half* __restrict__ A, const __half* __restrict__ Bt,
    CT* __restrict__ C, int M, int K, int Nc) {
    __shared__ uint32_t sA[128 * SSTR], sB[128 * SSTR];
    const int tid = threadIdx.x, wid = tid >> 5, lane = tid & 31;
    const int wm = wid & 1, wn = wid >> 1;
    const int bm = blockIdx.y * 128, bn = blockIdx.x * 128;
    const int g = lane >> 2, tg = lane & 3;

    float acc[4][4][4];
#pragma unroll
    for (int i = 0; i < 4; i++)
#pragma unroll
        for (int j = 0; j < 4; j++)
#pragma unroll
            for (int q = 0; q < 4; q++) acc[i][j][q] = 0.f;

    const int lrow = tid >> 1;              // 128 rows, 2 threads per row
    const int lofs = (tid & 1) * 32;        // halves offset within chunk
    const int gr = bm + lrow;
    const int gn = bn + lrow;

    for (int k0 = 0; k0 < K; k0 += 64) {
        {
            const uint4* ap = (const uint4*)(A + (size_t)gr * K + k0 + lofs);
            const uint4* bp = (const uint4*)(Bt + (size_t)gn * K + k0 + lofs);
            uint4* da = (uint4*)(sA + lrow * SSTR + (lofs >> 1));
            uint4* db = (uint4*)(sB + lrow * SSTR + (lofs >> 1));
#pragma unroll
            for (int i = 0; i < 4; i++) {
                da[i] = (gr < M) ? ap[i] : make_uint4(0, 0, 0, 0);
                db[i] = bp[i];
            }
        }
        __syncthreads();

#pragma unroll
        for (int ks = 0; ks < 4; ks++) {
            const int kb = ks * 8;
            uint32_t af[4][4], bf[4][2];
#pragma unroll
            for (int mi = 0; mi < 4; mi++) {
                int r0 = wm * 64 + mi * 16 + g;
                const uint32_t* ph = sA + r0 * SSTR + kb + tg;
                af[mi][0] = ph[0]; af[mi][1] = ph[8 * SSTR];
                af[mi][2] = ph[4]; af[mi][3] = ph[8 * SSTR + 4];
            }
#pragma unroll
            for (int nj = 0; nj < 4; nj++) {
                int n0 = wn * 32 + nj * 8 + g;
                const uint32_t* ph = sB + n0 * SSTR + kb + tg;
                bf[nj][0] = ph[0]; bf[nj][1] = ph[4];
            }
#pragma unroll
            for (int mi = 0; mi < 4; mi++)
#pragma unroll
                for (int nj = 0; nj < 4; nj++)
                    mma16816(acc[mi][nj], af[mi], bf[nj]);
        }
        __syncthreads();
    }

#pragma unroll
    for (int mi = 0; mi < 4; mi++) {
        int row = bm + wm * 64 + mi * 16 + g;
#pragma unroll
        for (int nj = 0; nj < 4; nj++) {
            int col = bn + wn * 32 + nj * 8 + tg * 2;
            if (row < M)     store_c2(C, (size_t)row * Nc + col, acc[mi][nj][0], acc[mi][nj][1]);
            if (row + 8 < M) store_c2(C, (size_t)(row + 8) * Nc + col, acc[mi][nj][2], acc[mi][nj][3]);
        }
    }
}

// ================= prep kernels =================
__global__ void xhalf(const float* __restrict__ x, __half* __restrict__ o, long n) {
    long i = (long)blockIdx.x * blockDim.x + threadIdx.x;
    if (i < n) o[i] = __float2half(x[i]);
}
__global__ void whalf(const float* __restrict__ W, __half* __restrict__ o, int K, int Nc) {
    long i = (long)blockIdx.x * blockDim.x + threadIdx.x;
    if (i >= (long)K * Nc) return;
    int n = (int)(i / K), k = (int)(i % K);
    o[i] = __float2half(W[(size_t)k * Nc + n]);
}
__global__ void bhalf3(const float* __restrict__ W3, __half* __restrict__ o) {
    long i = (long)blockIdx.x * blockDim.x + threadIdx.x;
    if (i >= 128L * 1536) return;
    int n = (int)(i / 1536), kk = (int)(i % 1536);
    int h_ = kk >> 8, k = kk & 255;
    float v = (n < 121) ? W3[(size_t)k * 726 + h_ * 121 + n] * (1.f / 6.f) : 0.f;
    o[i] = __float2half(v);
}

// ================= CSR build =================
__global__ void zeroi(int* __restrict__ p, int n) {
    int i = blockIdx.x * blockDim.x + threadIdx.x;
    if (i < n) p[i] = 0;
}
__global__ void hist_k(const int* __restrict__ dst, int* __restrict__ cur) {
    int e = blockIdx.x * blockDim.x + threadIdx.x;
    if (e >= ET) return;
    int d = (e < EE) ? dst[e] : e - EE;
    atomicAdd(&cur[d], 1);
}
__global__ void scan1(const int* __restrict__ deg, int* __restrict__ bsum) {
    __shared__ int sh[256];
    int i = blockIdx.x * 256 + threadIdx.x;
    sh[threadIdx.x] = (i < NN) ? deg[i] : 0;
    __syncthreads();
    for (int o = 128; o; o >>= 1) {
        if (threadIdx.x < o) sh[threadIdx.x] += sh[threadIdx.x + o];
        __syncthreads();
    }
    if (threadIdx.x == 0) bsum[blockIdx.x] = sh[0];
}
__global__ void scan2(int* __restrict__ bsum, int nb) {
    __shared__ int sh[256];
    int t = threadIdx.x;
    int v = (t < nb) ? bsum[t] : 0;
    sh[t] = v;
    __syncthreads();
    for (int o = 1; o < 256; o <<= 1) {
        int x2 = (t >= o) ? sh[t - o] : 0;
        __syncthreads();
        sh[t] += x2;
        __syncthreads();
    }
    if (t < nb) bsum[t] = sh[t] - v;
}
__global__ void scan3(const int* __restrict__ deg, const int* __restrict__ bsum,
                      int* __restrict__ rowptr, int* __restrict__ cur) {
    __shared__ int sh[256];
    int i = blockIdx.x * 256 + threadIdx.x;
    int v = (i < NN) ? deg[i] : 0;
    sh[threadIdx.x] = v;
    __syncthreads();
    for (int o = 1; o < 256; o <<= 1) {
        int t = (threadIdx.x >= o) ? sh[threadIdx.x - o] : 0;
        __syncthreads();
        sh[threadIdx.x] += t;
        __syncthreads();
    }
    int excl = sh[threadIdx.x] - v + bsum[blockIdx.x];
    if (i < NN) { rowptr[i] = excl; cur[i] = excl; }
    if (i == NN - 1) rowptr[NN] = excl + v;
}
__global__ void scatter_k(const int* __restrict__ src, const int* __restrict__ dst,
                          int* __restrict__ cur, int* __restrict__ csr) {
    int e = blockIdx.x * blockDim.x + threadIdx.x;
    if (e >= ET) return;
    int s, d;
    if (e < EE) { s = src[e]; d = dst[e]; } else { s = e - EE; d = s; }
    int pos = atomicAdd(&cur[d], 1);
    csr[pos] = s;
}

// ================= attention logits (layers 1/2) =================
__global__ void compute_al(const __half* __restrict__ feat, int fstride,
                           const float* __restrict__ a_src,
                           const float* __restrict__ a_dst,
                           float* __restrict__ als, float* __restrict__ ald,
                           int H, int C) {
    int w    = (blockIdx.x * blockDim.x + threadIdx.x) >> 5;
    int lane = threadIdx.x & 31;
    if (w >= NN * H) return;
    int n = w / H, h = w % H;
    const __half* f = feat + (size_t)n * fstride + (size_t)h * C;
    const float* as = a_src + h * C;
    const float* ad = a_dst + h * C;
    float s1 = 0.f, s2 = 0.f;
    for (int c = lane; c < C; c += 32) {
        float v = __half2float(f[c]);
        s1 += v * as[c];
        s2 += v * ad[c];
    }
#pragma unroll
    for (int o = 16; o; o >>= 1) {
        s1 += __shfl_down_sync(0xFFFFFFFFu, s1, o);
        s2 += __shfl_down_sync(0xFFFFFFFFu, s2, o);
    }
    if (lane == 0) { als[w] = s1; ald[w] = s2; }
}

// ================= layers 1/2: fused gather-aggregate =================
__global__ void __launch_bounds__(256) agg_fused12(
    const int* __restrict__ rowptr, const int* __restrict__ csr,
    const __half* __restrict__ feat, int fstride,
    const float* __restrict__ als, const float* __restrict__ ald,
    const float* __restrict__ bias, int has_res, __half* __restrict__ out) {
    int gw   = blockIdx.x * 8 + (threadIdx.x >> 5);
    int lane = threadIdx.x & 31;
    int n = gw >> 1, half_ = gw & 1;
    if (n >= NN) return;
    int col = half_ * 128 + lane * 4;
    int hl  = half_ * 2 + (lane >= 16);
    float aldh = 0.f;
    if (lane == 0 || lane == 16) aldh = ald[n * 4 + hl];
    int beg = rowptr[n], end = rowptr[n + 1];
    float4 acc = make_float4(0.f, 0.f, 0.f, 0.f);
    float denom = 0.f;
    int p = beg;
    for (; p + 2 <= end; p += 2) {
        int s0 = __ldg(&csr[p]), s1 = __ldg(&csr[p + 1]);
        float wv0 = 0.f, wv1 = 0.f;
        if (lane == 0 || lane == 16) {
            float v0 = als[s0 * 4 + hl] + aldh; v0 = v0 > 0.f ? v0 : 0.2f * v0;
            float v1 = als[s1 * 4 + hl] + aldh; v1 = v1 > 0.f ? v1 : 0.2f * v1;
            wv0 = __expf(v0); wv1 = __expf(v1);
        }
        uint2 r0 = *(const uint2*)(feat + (size_t)s0 * fstride + col);
        uint2 r1 = *(const uint2*)(feat + (size_t)s1 * fstride + col);
        float w0 = __shfl_sync(0xFFFFFFFFu, wv0, (lane < 16) ? 0 : 16);
        float w1 = __shfl_sync(0xFFFFFFFFu, wv1, (lane < 16) ? 0 : 16);
        float2 a0 = __half22float2(*(__half2*)&r0.x), b0 = __half22float2(*(__half2*)&r0.y);
        float2 a1 = __half22float2(*(__half2*)&r1.x), b1 = __half22float2(*(__half2*)&r1.y);
        acc.x += a0.x * w0 + a1.x * w1;
        acc.y += a0.y * w0 + a1.y * w1;
        acc.z += b0.x * w0 + b1.x * w1;
        acc.w += b0.y * w0 + b1.y * w1;
        denom += w0 + w1;
    }
    if (p < end) {
        int s = __ldg(&csr[p]);
        float wv = 0.f;
        if (lane == 0 || lane == 16) {
            float v = als[s * 4 + hl] + aldh;
            v = v > 0.f ? v : 0.2f * v;
            wv = __expf(v);
        }
        float w = __shfl_sync(0xFFFFFFFFu, wv, (lane < 16) ? 0 : 16);
        uint2 r = *(const uint2*)(feat + (size_t)s * fstride + col);
        float2 a = __half22float2(*(__half2*)&r.x), b = __half22float2(*(__half2*)&r.y);
        acc.x += a.x * w; acc.y += a.y * w; acc.z += b.x * w; acc.w += b.y * w;
        denom += w;
    }
    float inv = 1.f / (denom + 1e-16f);
    float4 bb = *(const float4*)(bias + col);
    float4 v;
    v.x = acc.x * inv + bb.x;
    v.y = acc.y * inv + bb.y;
    v.z = acc.z * inv + bb.z;
    v.w = acc.w * inv + bb.w;
    if (has_res) {
        uint2 rr = *(const uint2*)(feat + (size_t)n * fstride + 256 + col);
        float2 ra = __half22float2(*(__half2*)&rr.x), rb = __half22float2(*(__half2*)&rr.y);
        v.x += ra.x; v.y += ra.y; v.z += rb.x; v.w += rb.y;
    }
    v.x = v.x > 0.f ? v.x : (__expf(v.x) - 1.f);
    v.y = v.y > 0.f ? v.y : (__expf(v.y) - 1.f);
    v.z = v.z > 0.f ? v.z : (__expf(v.z) - 1.f);
    v.w = v.w > 0.f ? v.w : (__expf(v.w) - 1.f);
    __half2 o0 = __floats2half2_rn(v.x, v.y);
    __half2 o1 = __floats2half2_rn(v.z, v.w);
    *(uint2*)(out + (size_t)n * 256 + col) = make_uint2(*(uint32_t*)&o0, *(uint32_t*)&o1);
}

// ================= layer 3 attention-weight prep =================
__global__ void build_wt(const float* __restrict__ W3, const float* __restrict__ a3s,
                         const float* __restrict__ a3d, float* __restrict__ Wt) {
    int i = blockIdx.x * blockDim.x + threadIdx.x;
    if (i >= 2 * 256 * 6) return;
    int side = i / (256 * 6);
    int r = i % (256 * 6);
    int k = r / 6, h = r % 6;
    const float* av = side ? a3d : a3s;
    float s = 0.f;
    for (int o = 0; o < 121; o++)
        s += W3[(size_t)k * 726 + h * 121 + o] * av[h * 121 + o];
    Wt[(size_t)side * 1536 + k * 6 + h] = s;
}
__global__ void __launch_bounds__(256) al3_k(
    const __half* __restrict__ x, const float* __restrict__ Wt,
    float* __restrict__ als, float* __restrict__ ald) {
    int gw   = blockIdx.x * 8 + (threadIdx.x >> 5);
    int lane = threadIdx.x & 31;
    if (gw >= NN) return;
    const uint4* xp = (const uint4*)(x + (size_t)gw * 256);
    uint4 raw = xp[lane];
    uint32_t w[4] = {raw.x, raw.y, raw.z, raw.w};
    float xv[8];
#pragma unroll
    for (int i = 0; i < 4; i++) {
        float2 f = __half22float2(*(__half2*)&w[i]);
        xv[2 * i] = f.x; xv[2 * i + 1] = f.y;
    }
#pragma unroll
    for (int j = 0; j < 12; j++) {
        const float* W = Wt + (j >= 6 ? 1536 : 0);
        int jj = j % 6;
        float sum = 0.f;
#pragma unroll
        for (int i = 0; i < 8; i++)
            sum += xv[i] * W[(lane * 8 + i) * 6 + jj];
#pragma unroll
        for (int o = 16; o; o >>= 1) sum += __shfl_down_sync(0xFFFFFFFFu, sum, o);
        if (lane == 0) {
            if (j < 6) als[gw * 6 + jj] = sum;
            else       ald[gw * 6 + jj] = sum;
        }
    }
}

// ================= layer 3: fused gather in input space =================
__global__ void __launch_bounds__(256) agg_fused3(
    const int* __restrict__ rowptr, const int* __restrict__ csr,
    const __half* __restrict__ x, const float* __restrict__ als,
    const float* __restrict__ ald, __half* __restrict__ y) {
    int gw   = blockIdx.x * 8 + (threadIdx.x >> 5);
    int lane = threadIdx.x & 31;
    int n = gw >> 1, half_ = gw & 1;
    if (n >= NN) return;
    int col = half_ * 128 + lane * 4;
    float4 acc[6];
    float den[6];
#pragma unroll
    for (int h = 0; h < 6; h++) { acc[h] = make_float4(0.f, 0.f, 0.f, 0.f); den[h] = 0.f; }
    float aldl = (lane < 6) ? ald[n * 6 + lane] : 0.f;
    int beg = rowptr[n], end = rowptr[n + 1];
    for (int p = beg; p < end; p++) {
        int s = __ldg(&csr[p]);
        float wv = 0.f;
        if (lane < 6) {
            float v = als[s * 6 + lane] + aldl;
            v = v > 0.f ? v : 0.2f * v;
            wv = __expf(v);
        }
        uint2 r = *(const uint2*)(x + (size_t)s * 256 + col);
        float2 fa = __half22float2(*(__half2*)&r.x), fb = __half22float2(*(__half2*)&r.y);
#pragma unroll
        for (int h = 0; h < 6; h++) {
            float w = __shfl_sync(0xFFFFFFFFu, wv, h);
            den[h] += w;
            acc[h].x += fa.x * w; acc[h].y += fa.y * w;
            acc[h].z += fb.x * w; acc[h].w += fb.y * w;
        }
    }
#pragma unroll
    for (int h = 0; h < 6; h++) {
        float inv = 1.f / (den[h] + 1e-16f);
        __half2 o0 = __floats2half2_rn(acc[h].x * inv, acc[h].y * inv);
        __half2 o1 = __floats2half2_rn(acc[h].z * inv, acc[h].w * inv);
        *(uint2*)(y + ((size_t)n * 6 + h) * 256 + col) =
            make_uint2(*(uint32_t*)&o0, *(uint32_t*)&o1);
    }
}

// ================= final sigmoid =================
__global__ void finalize3(const float* __restrict__ acc, const float* __restrict__ bias,
                          float* __restrict__ out) {
    long i = (long)blockIdx.x * blockDim.x + threadIdx.x;
    if (i >= (long)NN * 121) return;
    int n = (int)(i / 121), o = (int)(i % 121);
    float v = acc[(size_t)n * 128 + o] + bias[o];
    out[i] = 1.f / (1.f + __expf(-v));
}

// ================= host driver =================
extern "C" void kernel_launch(void* const* d_in, const int* in_sizes, int n_in,
                              void* d_out, int out_size) {
    const float* x     = (const float*)d_in[0];
    const int*   src   = (const int*)  d_in[1];
    const int*   dst   = (const int*)  d_in[2];
    const float* W1    = (const float*)d_in[3];
    const float* a1s   = (const float*)d_in[4];
    const float* a1d   = (const float*)d_in[5];
    const float* b1    = (const float*)d_in[6];
    const float* W2    = (const float*)d_in[7];
    const float* a2s   = (const float*)d_in[8];
    const float* a2d   = (const float*)d_in[9];
    const float* b2    = (const float*)d_in[10];
    const float* Wres2 = (const float*)d_in[11];
    const float* W3    = (const float*)d_in[12];
    const float* a3s   = (const float*)d_in[13];
    const float* a3d   = (const float*)d_in[14];
    const float* b3    = (const float*)d_in[15];
    float* out = (float*)d_out;

    __half *p_x0, *p_feat, *p_x, *p_y, *w1t, *w2t, *bpt;
    float *p_acc, *p_als, *p_ald, *p_Wt;
    int *p_csr, *p_rowptr, *p_cur, *p_bsum;
    cudaGetSymbolAddress((void**)&p_x0,     g_x0);
    cudaGetSymbolAddress((void**)&p_feat,   g_feat);
    cudaGetSymbolAddress((void**)&p_x,      g_x);
    cudaGetSymbolAddress((void**)&p_y,      g_y);
    cudaGetSymbolAddress((void**)&p_acc,    g_acc);
    cudaGetSymbolAddress((void**)&p_als,    g_als);
    cudaGetSymbolAddress((void**)&p_ald,    g_ald);
    cudaGetSymbolAddress((void**)&p_Wt,     g_Wt);
    cudaGetSymbolAddress((void**)&p_csr,    g_csr);
    cudaGetSymbolAddress((void**)&p_rowptr, g_rowptr);
    cudaGetSymbolAddress((void**)&p_cur,    g_cur);
    cudaGetSymbolAddress((void**)&p_bsum,   g_bsum);
    cudaGetSymbolAddress((void**)&w1t, g_w1t);
    cudaGetSymbolAddress((void**)&w2t, g_w2t);
    cudaGetSymbolAddress((void**)&bpt, g_bpt);

    // ---- CSR build ----
    zeroi<<<(NN + 255) / 256, 256>>>(p_cur, NN);
    hist_k<<<(ET + 255) / 256, 256>>>(dst, p_cur);
    scan1<<<196, 256>>>(p_cur, p_bsum);
    scan2<<<1, 256>>>(p_bsum, 196);
    scan3<<<196, 256>>>(p_cur, p_bsum, p_rowptr, p_cur);
    scatter_k<<<(ET + 255) / 256, 256>>>(src, dst, p_cur, p_csr);

    // ---- prep ----
    xhalf<<<((long)NN * 128 + 255) / 256, 256>>>(x, p_x0, (long)NN * 128);
    whalf<<<(256 * 128 + 255) / 256, 256>>>(W1, w1t, 128, 256);
    whalf<<<(256 * 256 + 255) / 256, 256>>>(W2, w2t, 256, 256);
    whalf<<<(256 * 256 + 255) / 256, 256>>>(Wres2, w2t + 256 * 256, 256, 256);
    bhalf3<<<(128 * 1536 + 255) / 256, 256>>>(W3, bpt);
    build_wt<<<(2 * 256 * 6 + 255) / 256, 256>>>(W3, a3s, a3d, p_Wt);

    // ---- Layer 1: 128 -> 4x64 concat, ELU ----
    {
        dim3 g(2, (NN + 127) / 128);
        mma_gemm<__half><<<g, 256>>>(p_x0, w1t, p_feat, NN, 128, 256);
        compute_al<<<(NN * 4 * 32 + 255) / 256, 256>>>(p_feat, 256, a1s, a1d, p_als, p_ald, 4, 64);
        agg_fused12<<<(NN * 2 + 7) / 8, 256>>>(p_rowptr, p_csr, p_feat, 256, p_als, p_ald, b1, 0, p_x);
    }
    // ---- Layer 2: 256 -> 4x64 concat + residual (merged Nc=512), ELU ----
    {
        dim3 g(4, (NN + 127) / 128);
        mma_gemm<__half><<<g, 256>>>(p_x, w2t, p_feat, NN, 256, 512);
        compute_al<<<(NN * 4 * 32 + 255) / 256, 256>>>(p_feat, 512, a2s, a2d, p_als, p_ald, 4, 64);
        agg_fused12<<<(NN * 2 + 7) / 8, 256>>>(p_rowptr, p_csr, p_feat, 512, p_als, p_ald, b2, 1, p_x);
    }
    // ---- Layer 3: aggregate in input space, K=1536 GEMM, sigmoid ----
    {
        al3_k<<<(NN + 7) / 8, 256>>>(p_x, p_Wt, p_als, p_ald);
        agg_fused3<<<(NN * 2 + 7) / 8, 256>>>(p_rowptr, p_csr, p_x, p_als, p_ald, p_y);
        dim3 g(1, (NN + 127) / 128);
        mma_gemm<float><<<g, 256>>>(p_y, bpt, p_acc, NN, 1536, 128);
        finalize3<<<(NN * 121 + 255) / 256, 256>>>(p_acc, b3, out);
    }
}

// round 8
// speedup vs baseline: 5.9850x; 1.1983x over previous
#include <cuda_runtime.h>
#include <cuda_fp16.h>
#include <math.h>
#include <stdint.h>

#define NN 50000
#define EE 800000
#define ET (EE + NN)

// ---------------- device scratch (allocation-free) ----------------
__device__ __half g_x0  [(size_t)NN * 128];
__device__ __half g_feat[(size_t)NN * 512];   // layer1: [N,256]; layer2: [N,512] (256+ = residual)
__device__ __half g_x   [(size_t)NN * 256];
__device__ __half g_y   [(size_t)NN * 1536];
__device__ float  g_acc [(size_t)NN * 128];
__device__ float  g_als [NN * 6];
__device__ float  g_ald [NN * 6];
__device__ float  g_Wt  [2 * 256 * 6];
__device__ int    g_csr [ET];
__device__ int    g_rowptr[NN + 1];
__device__ int    g_cur [NN];
__device__ int    g_bsum[256];
__device__ __half g_w1t[256 * 128];
__device__ __half g_w2t[512 * 256];
__device__ __half g_bpt[128 * 1536];

// ---------------- helpers ----------------
__device__ __forceinline__ void mma16816(float* c, const uint32_t* a, const uint32_t* b) {
    asm volatile(
        "mma.sync.aligned.m16n8k16.row.col.f32.f16.f16.f32 "
        "{%0,%1,%2,%3}, {%4,%5,%6,%7}, {%8,%9}, {%0,%1,%2,%3};"
        : "+f"(c[0]), "+f"(c[1]), "+f"(c[2]), "+f"(c[3])
        : "r"(a[0]), "r"(a[1]), "r"(a[2]), "r"(a[3]), "r"(b[0]), "r"(b[1]));
}
__device__ __forceinline__ void store_c2(float* C, size_t idx, float a, float b) {
    *(float2*)(C + idx) = make_float2(a, b);
}
__device__ __forceinline__ void store_c2(__half* C, size_t idx, float a, float b) {
    *(__half2*)(C + idx) = __floats2half2_rn(a, b);
}
#define CP_ASYNC16(sa, gp) asm volatile("cp.async.ca.shared.global [%0], [%1], 16;" :: "r"(sa), "l"(gp))
#define CP_COMMIT()        asm volatile("cp.async.commit_group;" ::: "memory")
#define CP_WAIT(n)         asm volatile("cp.async.wait_group %0;" :: "n"(n) : "memory")

// ================= HMMA GEMM, cp.async double-buffered =================
// C[M,Nc] = A[M,K] @ (Bt[Nc,K])^T. fp16 in, fp32 accum. Tile 128x128, K-chunk 32.
#define SSTR2 20   // words per smem row: 16 data + 4 pad (16B-aligned, conflict-free)
template <typename CT>
__global__ void __launch_bounds__(256) mma_gemm(
    const __half* __restrict__ A, const __half* __restrict__ Bt,
    CT* __restrict__ C, int M, int K, int Nc) {
    __shared__ uint32_t sh[4 * 128 * SSTR2];   // [stage][A/B][128][SSTR2] = 40 KB
    const int tid = threadIdx.x, wid = tid >> 5, lane = tid & 31;
    const int wm = wid & 1, wn = wid >> 1;
    const int bm = blockIdx.y * 128, bn = blockIdx.x * 128;
    const int g = lane >> 2, tg = lane & 3;

    float acc[4][4][4];
#pragma unroll
    for (int i = 0; i < 4; i++)
#pragma unroll
        for (int j = 0; j < 4; j++)
#pragma unroll
            for (int q = 0; q < 4; q++) acc[i][j][q] = 0.f;

    const int crow = tid >> 1, csegb = (tid & 1) * 2;
    const int grc = min(bm + crow, M - 1);
    const int gn  = bn + crow;
    const __half* arow_p = A  + (size_t)grc * K;
    const __half* brow_p = Bt + (size_t)gn  * K;
    const int nch = K >> 5;

    auto issue = [&](int st, int k0) {
        uint32_t sa = (uint32_t)__cvta_generic_to_shared(sh + st * 2 * 128 * SSTR2 + crow * SSTR2);
        uint32_t sb = sa + 128 * SSTR2 * 4;
        const __half* ap = arow_p + k0;
        const __half* bp = brow_p + k0;
#pragma unroll
        for (int i = 0; i < 2; i++) {
            int seg = csegb + i;
            CP_ASYNC16(sa + seg * 16, ap + seg * 8);
            CP_ASYNC16(sb + seg * 16, bp + seg * 8);
        }
        CP_COMMIT();
    };

    issue(0, 0);
    for (int ch = 0; ch < nch; ch++) {
        if (ch + 1 < nch) { issue((ch + 1) & 1, (ch + 1) << 5); CP_WAIT(1); }
        else              { CP_WAIT(0); }
        __syncthreads();
        const uint32_t* SA = sh + (ch & 1) * 2 * 128 * SSTR2;
        const uint32_t* SB = SA + 128 * SSTR2;
#pragma unroll
        for (int ks = 0; ks < 2; ks++) {
            const int kb = ks * 8;
            uint32_t af[4][4], bf[4][2];
#pragma unroll
            for (int mi = 0; mi < 4; mi++) {
                const uint32_t* ph = SA + (wm * 64 + mi * 16 + g) * SSTR2 + kb + tg;
                af[mi][0] = ph[0]; af[mi][1] = ph[8 * SSTR2];
                af[mi][2] = ph[4]; af[mi][3] = ph[8 * SSTR2 + 4];
            }
#pragma unroll
            for (int nj = 0; nj < 4; nj++) {
                const uint32_t* ph = SB + (wn * 32 + nj * 8 + g) * SSTR2 + kb + tg;
                bf[nj][0] = ph[0]; bf[nj][1] = ph[4];
            }
#pragma unroll
            for (int mi = 0; mi < 4; mi++)
#pragma unroll
                for (int nj = 0; nj < 4; nj++)
                    mma16816(acc[mi][nj], af[mi], bf[nj]);
        }
        __syncthreads();
    }

#pragma unroll
    for (int mi = 0; mi < 4; mi++) {
        int row = bm + wm * 64 + mi * 16 + g;
#pragma unroll
        for (int nj = 0; nj < 4; nj++) {
            int col = bn + wn * 32 + nj * 8 + tg * 2;
            if (row < M)     store_c2(C, (size_t)row * Nc + col, acc[mi][nj][0], acc[mi][nj][1]);
            if (row + 8 < M) store_c2(C, (size_t)(row + 8) * Nc + col, acc[mi][nj][2], acc[mi][nj][3]);
        }
    }
}

// ================= prep kernels =================
__global__ void xhalf(const float* __restrict__ x, __half* __restrict__ o, long n) {
    long i = (long)blockIdx.x * blockDim.x + threadIdx.x;
    if (i < n) o[i] = __float2half(x[i]);
}
__global__ void whalf(const float* __restrict__ W, __half* __restrict__ o, int K, int Nc) {
    long i = (long)blockIdx.x * blockDim.x + threadIdx.x;
    if (i >= (long)K * Nc) return;
    int n = (int)(i / K), k = (int)(i % K);
    o[i] = __float2half(W[(size_t)k * Nc + n]);
}
__global__ void bhalf3(const float* __restrict__ W3, __half* __restrict__ o) {
    long i = (long)blockIdx.x * blockDim.x + threadIdx.x;
    if (i >= 128L * 1536) return;
    int n = (int)(i / 1536), kk = (int)(i % 1536);
    int h_ = kk >> 8, k = kk & 255;
    float v = (n < 121) ? W3[(size_t)k * 726 + h_ * 121 + n] * (1.f / 6.f) : 0.f;
    o[i] = __float2half(v);
}

// ================= CSR build =================
__global__ void zeroi(int* __restrict__ p, int n) {
    int i = blockIdx.x * blockDim.x + threadIdx.x;
    if (i < n) p[i] = 0;
}
__global__ void hist_k(const int* __restrict__ dst, int* __restrict__ cur) {
    int e = blockIdx.x * blockDim.x + threadIdx.x;
    if (e >= ET) return;
    int d = (e < EE) ? dst[e] : e - EE;
    atomicAdd(&cur[d], 1);
}
__global__ void scan1(const int* __restrict__ deg, int* __restrict__ bsum) {
    __shared__ int sh[256];
    int i = blockIdx.x * 256 + threadIdx.x;
    sh[threadIdx.x] = (i < NN) ? deg[i] : 0;
    __syncthreads();
    for (int o = 128; o; o >>= 1) {
        if (threadIdx.x < o) sh[threadIdx.x] += sh[threadIdx.x + o];
        __syncthreads();
    }
    if (threadIdx.x == 0) bsum[blockIdx.x] = sh[0];
}
__global__ void scan2(int* __restrict__ bsum, int nb) {
    __shared__ int sh[256];
    int t = threadIdx.x;
    int v = (t < nb) ? bsum[t] : 0;
    sh[t] = v;
    __syncthreads();
    for (int o = 1; o < 256; o <<= 1) {
        int x2 = (t >= o) ? sh[t - o] : 0;
        __syncthreads();
        sh[t] += x2;
        __syncthreads();
    }
    if (t < nb) bsum[t] = sh[t] - v;
}
__global__ void scan3(const int* __restrict__ deg, const int* __restrict__ bsum,
                      int* __restrict__ rowptr, int* __restrict__ cur) {
    __shared__ int sh[256];
    int i = blockIdx.x * 256 + threadIdx.x;
    int v = (i < NN) ? deg[i] : 0;
    sh[threadIdx.x] = v;
    __syncthreads();
    for (int o = 1; o < 256; o <<= 1) {
        int t = (threadIdx.x >= o) ? sh[threadIdx.x - o] : 0;
        __syncthreads();
        sh[threadIdx.x] += t;
        __syncthreads();
    }
    int excl = sh[threadIdx.x] - v + bsum[blockIdx.x];
    if (i < NN) { rowptr[i] = excl; cur[i] = excl; }
    if (i == NN - 1) rowptr[NN] = excl + v;
}
__global__ void scatter_k(const int* __restrict__ src, const int* __restrict__ dst,
                          int* __restrict__ cur, int* __restrict__ csr) {
    int e = blockIdx.x * blockDim.x + threadIdx.x;
    if (e >= ET) return;
    int s, d;
    if (e < EE) { s = src[e]; d = dst[e]; } else { s = e - EE; d = s; }
    int pos = atomicAdd(&cur[d], 1);
    csr[pos] = s;
}

// ================= attention logits (layers 1/2): 1 warp per node =================
__global__ void __launch_bounds__(256) compute_al4(
    const __half* __restrict__ feat, int fstride,
    const float* __restrict__ a_src, const float* __restrict__ a_dst,
    float* __restrict__ als, float* __restrict__ ald) {
    int n    = blockIdx.x * 8 + (threadIdx.x >> 5);
    int lane = threadIdx.x & 31;
    if (n >= NN) return;
    int col = lane * 8, h = lane >> 3;
    uint4 r = *(const uint4*)(feat + (size_t)n * fstride + col);
    uint32_t w[4] = {r.x, r.y, r.z, r.w};
    float f[8];
#pragma unroll
    for (int i = 0; i < 4; i++) {
        float2 t = __half22float2(*(__half2*)&w[i]);
        f[2 * i] = t.x; f[2 * i + 1] = t.y;
    }
    int ao = h * 64 + (lane & 7) * 8;
    float4 as0 = *(const float4*)(a_src + ao), as1 = *(const float4*)(a_src + ao + 4);
    float4 ad0 = *(const float4*)(a_dst + ao), ad1 = *(const float4*)(a_dst + ao + 4);
    float s1 = f[0] * as0.x + f[1] * as0.y + f[2] * as0.z + f[3] * as0.w
             + f[4] * as1.x + f[5] * as1.y + f[6] * as1.z + f[7] * as1.w;
    float s2 = f[0] * ad0.x + f[1] * ad0.y + f[2] * ad0.z + f[3] * ad0.w
             + f[4] * ad1.x + f[5] * ad1.y + f[6] * ad1.z + f[7] * ad1.w;
#pragma unroll
    for (int o = 4; o; o >>= 1) {
        s1 += __shfl_down_sync(0xFFFFFFFFu, s1, o, 8);
        s2 += __shfl_down_sync(0xFFFFFFFFu, s2, o, 8);
    }
    if ((lane & 7) == 0) { als[n * 4 + h] = s1; ald[n * 4 + h] = s2; }
}

// ================= layers 1/2: fused gather-aggregate, 1 warp per node =================
__global__ void __launch_bounds__(256) agg_fused12(
    const int* __restrict__ rowptr, const int* __restrict__ csr,
    const __half* __restrict__ feat, int fstride,
    const float* __restrict__ als, const float* __restrict__ ald,
    const float* __restrict__ bias, int has_res, __half* __restrict__ out) {
    int n    = blockIdx.x * 8 + (threadIdx.x >> 5);
    int lane = threadIdx.x & 31;
    if (n >= NN) return;
    int col = lane * 8;
    int hl  = lane >> 3;                 // head owned by this lane's group
    bool wlane = (lane & 7) == 0;        // lanes 0,8,16,24 compute weights
    float aldh = wlane ? ald[n * 4 + hl] : 0.f;
    int beg = rowptr[n], end = rowptr[n + 1];
    float acc[8] = {0.f, 0.f, 0.f, 0.f, 0.f, 0.f, 0.f, 0.f};
    float denom = 0.f;
    int p = beg;
    for (; p + 2 <= end; p += 2) {
        int s0 = __ldg(&csr[p]), s1 = __ldg(&csr[p + 1]);
        float wv0 = 0.f, wv1 = 0.f;
        if (wlane) {
            float v0 = als[s0 * 4 + hl] + aldh; v0 = v0 > 0.f ? v0 : 0.2f * v0;
            float v1 = als[s1 * 4 + hl] + aldh; v1 = v1 > 0.f ? v1 : 0.2f * v1;
            wv0 = __expf(v0); wv1 = __expf(v1);
        }
        uint4 r0 = *(const uint4*)(feat + (size_t)s0 * fstride + col);
        uint4 r1 = *(const uint4*)(feat + (size_t)s1 * fstride + col);
        float w0 = __shfl_sync(0xFFFFFFFFu, wv0, lane & 24);
        float w1 = __shfl_sync(0xFFFFFFFFu, wv1, lane & 24);
        uint32_t q0[4] = {r0.x, r0.y, r0.z, r0.w};
        uint32_t q1[4] = {r1.x, r1.y, r1.z, r1.w};
#pragma unroll
        for (int i = 0; i < 4; i++) {
            float2 f0 = __half22float2(*(__half2*)&q0[i]);
            float2 f1 = __half22float2(*(__half2*)&q1[i]);
            acc[2 * i]     += f0.x * w0 + f1.x * w1;
            acc[2 * i + 1] += f0.y * w0 + f1.y * w1;
        }
        denom += w0 + w1;
    }
    if (p < end) {
        int s = __ldg(&csr[p]);
        float wv = 0.f;
        if (wlane) {
            float v = als[s * 4 + hl] + aldh;
            v = v > 0.f ? v : 0.2f * v;
            wv = __expf(v);
        }
        float w = __shfl_sync(0xFFFFFFFFu, wv, lane & 24);
        uint4 r = *(const uint4*)(feat + (size_t)s * fstride + col);
        uint32_t q[4] = {r.x, r.y, r.z, r.w};
#pragma unroll
        for (int i = 0; i < 4; i++) {
            float2 f = __half22float2(*(__half2*)&q[i]);
            acc[2 * i] += f.x * w; acc[2 * i + 1] += f.y * w;
        }
        denom += w;
    }
    float inv = 1.f / (denom + 1e-16f);
    float4 b0 = *(const float4*)(bias + col), b1 = *(const float4*)(bias + col + 4);
    float bb[8] = {b0.x, b0.y, b0.z, b0.w, b1.x, b1.y, b1.z, b1.w};
    float rr[8] = {0.f, 0.f, 0.f, 0.f, 0.f, 0.f, 0.f, 0.f};
    if (has_res) {
        uint4 r = *(const uint4*)(feat + (size_t)n * fstride + 256 + col);
        uint32_t q[4] = {r.x, r.y, r.z, r.w};
#pragma unroll
        for (int i = 0; i < 4; i++) {
            float2 f = __half22float2(*(__half2*)&q[i]);
            rr[2 * i] = f.x; rr[2 * i + 1] = f.y;
        }
    }
    uint32_t o[4];
#pragma unroll
    for (int i = 0; i < 4; i++) {
        float vx = acc[2 * i] * inv + bb[2 * i] + rr[2 * i];
        float vy = acc[2 * i + 1] * inv + bb[2 * i + 1] + rr[2 * i + 1];
        vx = vx > 0.f ? vx : (__expf(vx) - 1.f);
        vy = vy > 0.f ? vy : (__expf(vy) - 1.f);
        __half2 hv = __floats2half2_rn(vx, vy);
        o[i] = *(uint32_t*)&hv;
    }
    *(uint4*)(out + (size_t)n * 256 + col) = make_uint4(o[0], o[1], o[2], o[3]);
}

// ================= layer 3 attention-weight prep =================
__global__ void build_wt(const float* __restrict__ W3, const float* __restrict__ a3s,
                         const float* __restrict__ a3d, float* __restrict__ Wt) {
    int i = blockIdx.x * blockDim.x + threadIdx.x;
    if (i >= 2 * 256 * 6) return;
    int side = i / (256 * 6);
    int r = i % (256 * 6);
    int k = r / 6, h = r % 6;
    const float* av = side ? a3d : a3s;
    float s = 0.f;
    for (int o = 0; o < 121; o++)
        s += W3[(size_t)k * 726 + h * 121 + o] * av[h * 121 + o];
    Wt[(size_t)side * 1536 + k * 6 + h] = s;
}
__global__ void __launch_bounds__(256) al3_k(
    const __half* __restrict__ x, const float* __restrict__ Wt,
    float* __restrict__ als, float* __restrict__ ald) {
    int gw   = blockIdx.x * 8 + (threadIdx.x >> 5);
    int lane = threadIdx.x & 31;
    if (gw >= NN) return;
    const uint4* xp = (const uint4*)(x + (size_t)gw * 256);
    uint4 raw = xp[lane];
    uint32_t w[4] = {raw.x, raw.y, raw.z, raw.w};
    float xv[8];
#pragma unroll
    for (int i = 0; i < 4; i++) {
        float2 f = __half22float2(*(__half2*)&w[i]);
        xv[2 * i] = f.x; xv[2 * i + 1] = f.y;
    }
#pragma unroll
    for (int j = 0; j < 12; j++) {
        const float* W = Wt + (j >= 6 ? 1536 : 0);
        int jj = j % 6;
        float sum = 0.f;
#pragma unroll
        for (int i = 0; i < 8; i++)
            sum += xv[i] * W[(lane * 8 + i) * 6 + jj];
#pragma unroll
        for (int o = 16; o; o >>= 1) sum += __shfl_down_sync(0xFFFFFFFFu, sum, o);
        if (lane == 0) {
            if (j < 6) als[gw * 6 + jj] = sum;
            else       ald[gw * 6 + jj] = sum;
        }
    }
}

// ================= layer 3: fused gather, 1 warp per node =================
__global__ void __launch_bounds__(256) agg_fused3(
    const int* __restrict__ rowptr, const int* __restrict__ csr,
    const __half* __restrict__ x, const float* __restrict__ als,
    const float* __restrict__ ald, __half* __restrict__ y) {
    int n    = blockIdx.x * 8 + (threadIdx.x >> 5);
    int lane = threadIdx.x & 31;
    if (n >= NN) return;
    int col = lane * 8;
    float acc[6][8];
    float den[6];
#pragma unroll
    for (int h = 0; h < 6; h++) {
        den[h] = 0.f;
#pragma unroll
        for (int j = 0; j < 8; j++) acc[h][j] = 0.f;
    }
    float aldl = (lane < 6) ? ald[n * 6 + lane] : 0.f;
    int beg = rowptr[n], end = rowptr[n + 1];
    for (int p = beg; p < end; p++) {
        int s = __ldg(&csr[p]);
        float wv = 0.f;
        if (lane < 6) {
            float v = als[s * 6 + lane] + aldl;
            v = v > 0.f ? v : 0.2f * v;
            wv = __expf(v);
        }
        uint4 r = *(const uint4*)(x + (size_t)s * 256 + col);
        uint32_t q[4] = {r.x, r.y, r.z, r.w};
        float f[8];
#pragma unroll
        for (int i = 0; i < 4; i++) {
            float2 t = __half22float2(*(__half2*)&q[i]);
            f[2 * i] = t.x; f[2 * i + 1] = t.y;
        }
#pragma unroll
        for (int h = 0; h < 6; h++) {
            float w = __shfl_sync(0xFFFFFFFFu, wv, h);
            den[h] += w;
#pragma unroll
            for (int j = 0; j < 8; j++) acc[h][j] += f[j] * w;
        }
    }
#pragma unroll
    for (int h = 0; h < 6; h++) {
        float inv = 1.f / (den[h] + 1e-16f);
        uint32_t o[4];
#pragma unroll
        for (int i = 0; i < 4; i++) {
            __half2 hv = __floats2half2_rn(acc[h][2 * i] * inv, acc[h][2 * i + 1] * inv);
            o[i] = *(uint32_t*)&hv;
        }
        *(uint4*)(y + ((size_t)n * 6 + h) * 256 + col) = make_uint4(o[0], o[1], o[2], o[3]);
    }
}

// ================= final sigmoid =================
__global__ void finalize3(const float* __restrict__ acc, const float* __restrict__ bias,
                          float* __restrict__ out) {
    long i = (long)blockIdx.x * blockDim.x + threadIdx.x;
    if (i >= (long)NN * 121) return;
    int n = (int)(i / 121), o = (int)(i % 121);
    float v = acc[(size_t)n * 128 + o] + bias[o];
    out[i] = 1.f / (1.f + __expf(-v));
}

// ================= host driver =================
extern "C" void kernel_launch(void* const* d_in, const int* in_sizes, int n_in,
                              void* d_out, int out_size) {
    const float* x     = (const float*)d_in[0];
    const int*   src   = (const int*)  d_in[1];
    const int*   dst   = (const int*)  d_in[2];
    const float* W1    = (const float*)d_in[3];
    const float* a1s   = (const float*)d_in[4];
    const float* a1d   = (const float*)d_in[5];
    const float* b1    = (const float*)d_in[6];
    const float* W2    = (const float*)d_in[7];
    const float* a2s   = (const float*)d_in[8];
    const float* a2d   = (const float*)d_in[9];
    const float* b2    = (const float*)d_in[10];
    const float* Wres2 = (const float*)d_in[11];
    const float* W3    = (const float*)d_in[12];
    const float* a3s   = (const float*)d_in[13];
    const float* a3d   = (const float*)d_in[14];
    const float* b3    = (const float*)d_in[15];
    float* out = (float*)d_out;

    __half *p_x0, *p_feat, *p_x, *p_y, *w1t, *w2t, *bpt;
    float *p_acc, *p_als, *p_ald, *p_Wt;
    int *p_csr, *p_rowptr, *p_cur, *p_bsum;
    cudaGetSymbolAddress((void**)&p_x0,     g_x0);
    cudaGetSymbolAddress((void**)&p_feat,   g_feat);
    cudaGetSymbolAddress((void**)&p_x,      g_x);
    cudaGetSymbolAddress((void**)&p_y,      g_y);
    cudaGetSymbolAddress((void**)&p_acc,    g_acc);
    cudaGetSymbolAddress((void**)&p_als,    g_als);
    cudaGetSymbolAddress((void**)&p_ald,    g_ald);
    cudaGetSymbolAddress((void**)&p_Wt,     g_Wt);
    cudaGetSymbolAddress((void**)&p_csr,    g_csr);
    cudaGetSymbolAddress((void**)&p_rowptr, g_rowptr);
    cudaGetSymbolAddress((void**)&p_cur,    g_cur);
    cudaGetSymbolAddress((void**)&p_bsum,   g_bsum);
    cudaGetSymbolAddress((void**)&w1t, g_w1t);
    cudaGetSymbolAddress((void**)&w2t, g_w2t);
    cudaGetSymbolAddress((void**)&bpt, g_bpt);

    // ---- CSR build ----
    zeroi<<<(NN + 255) / 256, 256>>>(p_cur, NN);
    hist_k<<<(ET + 255) / 256, 256>>>(dst, p_cur);
    scan1<<<196, 256>>>(p_cur, p_bsum);
    scan2<<<1, 256>>>(p_bsum, 196);
    scan3<<<196, 256>>>(p_cur, p_bsum, p_rowptr, p_cur);
    scatter_k<<<(ET + 255) / 256, 256>>>(src, dst, p_cur, p_csr);

    // ---- prep ----
    xhalf<<<((long)NN * 128 + 255) / 256, 256>>>(x, p_x0, (long)NN * 128);
    whalf<<<(256 * 128 + 255) / 256, 256>>>(W1, w1t, 128, 256);
    whalf<<<(256 * 256 + 255) / 256, 256>>>(W2, w2t, 256, 256);
    whalf<<<(256 * 256 + 255) / 256, 256>>>(Wres2, w2t + 256 * 256, 256, 256);
    bhalf3<<<(128 * 1536 + 255) / 256, 256>>>(W3, bpt);
    build_wt<<<(2 * 256 * 6 + 255) / 256, 256>>>(W3, a3s, a3d, p_Wt);

    // ---- Layer 1 ----
    {
        dim3 g(2, (NN + 127) / 128);
        mma_gemm<__half><<<g, 256>>>(p_x0, w1t, p_feat, NN, 128, 256);
        compute_al4<<<(NN + 7) / 8, 256>>>(p_feat, 256, a1s, a1d, p_als, p_ald);
        agg_fused12<<<(NN + 7) / 8, 256>>>(p_rowptr, p_csr, p_feat, 256, p_als, p_ald, b1, 0, p_x);
    }
    // ---- Layer 2 (merged W2|Wres2, Nc=512) ----
    {
        dim3 g(4, (NN + 127) / 128);
        mma_gemm<__half><<<g, 256>>>(p_x, w2t, p_feat, NN, 256, 512);
        compute_al4<<<(NN + 7) / 8, 256>>>(p_feat, 512, a2s, a2d, p_als, p_ald);
        agg_fused12<<<(NN + 7) / 8, 256>>>(p_rowptr, p_csr, p_feat, 512, p_als, p_ald, b2, 1, p_x);
    }
    // ---- Layer 3 ----
    {
        al3_k<<<(NN + 7) / 8, 256>>>(p_x, p_Wt, p_als, p_ald);
        agg_fused3<<<(NN + 7) / 8, 256>>>(p_rowptr, p_csr, p_x, p_als, p_ald, p_y);
        dim3 g(1, (NN + 127) / 128);
        mma_gemm<float><<<g, 256>>>(p_y, bpt, p_acc, NN, 1536, 128);
        finalize3<<<(NN * 121 + 255) / 256, 256>>>(p_acc, b3, out);
    }
}

// round 9
// speedup vs baseline: 6.3203x; 1.0560x over previous
#include <cuda_runtime.h>
#include <cuda_fp16.h>
#include <math.h>
#include <stdint.h>

#define NN 50000
#define EE 800000
#define ET (EE + NN)

// ---------------- device scratch (allocation-free) ----------------
__device__ __half g_x0  [(size_t)NN * 128];
__device__ __half g_feat[(size_t)NN * 512];   // layer1: [N,256]; layer2: [N,512] (256+ = residual)
__device__ __half g_x   [(size_t)NN * 256];
__device__ __half g_y   [(size_t)NN * 1536];
__device__ float  g_als1[NN * 4], g_ald1[NN * 4];
__device__ float  g_als2[NN * 4], g_ald2[NN * 4];
__device__ float  g_als3[NN * 6], g_ald3[NN * 6];
__device__ float  g_Wt  [2 * 256 * 6];
__device__ int    g_csr [ET];
__device__ int    g_rowptr[NN + 1];
__device__ int    g_cur [NN];
__device__ int    g_bsum[256];
__device__ __half g_w1t[256 * 128];
__device__ __half g_w2t[512 * 256];
__device__ __half g_bpt[128 * 1536];

// ---------------- helpers ----------------
__device__ __forceinline__ void mma16816(float* c, const uint32_t* a, const uint32_t* b) {
    asm volatile(
        "mma.sync.aligned.m16n8k16.row.col.f32.f16.f16.f32 "
        "{%0,%1,%2,%3}, {%4,%5,%6,%7}, {%8,%9}, {%0,%1,%2,%3};"
        : "+f"(c[0]), "+f"(c[1]), "+f"(c[2]), "+f"(c[3])
        : "r"(a[0]), "r"(a[1]), "r"(a[2]), "r"(a[3]), "r"(b[0]), "r"(b[1]));
}
#define CP_ASYNC16(sa, gp) asm volatile("cp.async.ca.shared.global [%0], [%1], 16;" :: "r"(sa), "l"(gp))
#define CP_COMMIT()        asm volatile("cp.async.commit_group;" ::: "memory")
#define CP_WAIT(n)         asm volatile("cp.async.wait_group %0;" :: "n"(n) : "memory")

// ================= HMMA GEMM, cp.async double-buffered, fused epilogues =================
// MODE 1: CT=__half; store feat + fused attention-logit atomics (cols<256, H=4)
// MODE 2: CT=float;  store sigmoid(acc + bias[col]) to out[row*121+col], cols<121
#define SSTR2 20
template <int MODE, typename CT>
__global__ void __launch_bounds__(256) mma_gemm(
    const __half* __restrict__ A, const __half* __restrict__ Bt,
    CT* __restrict__ C, int M, int K, int Nc,
    const float* __restrict__ a_src, const float* __restrict__ a_dst,
    float* __restrict__ als, float* __restrict__ ald,
    const float* __restrict__ bias) {
    __shared__ uint32_t sh[4 * 128 * SSTR2];
    const int tid = threadIdx.x, wid = tid >> 5, lane = tid & 31;
    const int wm = wid & 1, wn = wid >> 1;
    const int bm = blockIdx.y * 128, bn = blockIdx.x * 128;
    const int g = lane >> 2, tg = lane & 3;

    float acc[4][4][4];
#pragma unroll
    for (int i = 0; i < 4; i++)
#pragma unroll
        for (int j = 0; j < 4; j++)
#pragma unroll
            for (int q = 0; q < 4; q++) acc[i][j][q] = 0.f;

    const int crow = tid >> 1, csegb = (tid & 1) * 2;
    const int grc = min(bm + crow, M - 1);
    const int gn  = bn + crow;
    const __half* arow_p = A  + (size_t)grc * K;
    const __half* brow_p = Bt + (size_t)gn  * K;
    const int nch = K >> 5;

    auto issue = [&](int st, int k0) {
        uint32_t sa = (uint32_t)__cvta_generic_to_shared(sh + st * 2 * 128 * SSTR2 + crow * SSTR2);
        uint32_t sb = sa + 128 * SSTR2 * 4;
        const __half* ap = arow_p + k0;
        const __half* bp = brow_p + k0;
#pragma unroll
        for (int i = 0; i < 2; i++) {
            int seg = csegb + i;
            CP_ASYNC16(sa + seg * 16, ap + seg * 8);
            CP_ASYNC16(sb + seg * 16, bp + seg * 8);
        }
        CP_COMMIT();
    };

    issue(0, 0);
    for (int ch = 0; ch < nch; ch++) {
        if (ch + 1 < nch) { issue((ch + 1) & 1, (ch + 1) << 5); CP_WAIT(1); }
        else              { CP_WAIT(0); }
        __syncthreads();
        const uint32_t* SA = sh + (ch & 1) * 2 * 128 * SSTR2;
        const uint32_t* SB = SA + 128 * SSTR2;
#pragma unroll
        for (int ks = 0; ks < 2; ks++) {
            const int kb = ks * 8;
            uint32_t af[4][4], bf[4][2];
#pragma unroll
            for (int mi = 0; mi < 4; mi++) {
                const uint32_t* ph = SA + (wm * 64 + mi * 16 + g) * SSTR2 + kb + tg;
                af[mi][0] = ph[0]; af[mi][1] = ph[8 * SSTR2];
                af[mi][2] = ph[4]; af[mi][3] = ph[8 * SSTR2 + 4];
            }
#pragma unroll
            for (int nj = 0; nj < 4; nj++) {
                const uint32_t* ph = SB + (wn * 32 + nj * 8 + g) * SSTR2 + kb + tg;
                bf[nj][0] = ph[0]; bf[nj][1] = ph[4];
            }
#pragma unroll
            for (int mi = 0; mi < 4; mi++)
#pragma unroll
                for (int nj = 0; nj < 4; nj++)
                    mma16816(acc[mi][nj], af[mi], bf[nj]);
        }
        __syncthreads();
    }

    if (MODE == 1) {
        // store feat (fp16)
#pragma unroll
        for (int mi = 0; mi < 4; mi++) {
            int row = bm + wm * 64 + mi * 16 + g;
#pragma unroll
            for (int nj = 0; nj < 4; nj++) {
                int col = bn + wn * 32 + nj * 8 + tg * 2;
                if (row < M)
                    *(__half2*)((__half*)C + (size_t)row * Nc + col) = __floats2half2_rn(acc[mi][nj][0], acc[mi][nj][1]);
                if (row + 8 < M)
                    *(__half2*)((__half*)C + (size_t)(row + 8) * Nc + col) = __floats2half2_rn(acc[mi][nj][2], acc[mi][nj][3]);
            }
        }
        // fused attention logits over cols < 256 (H=4, 64 cols per head)
        if (bn + wn * 32 < 256) {
            int h = (bn + wn * 32) >> 6;
            float asv[4][2], adv[4][2];
#pragma unroll
            for (int nj = 0; nj < 4; nj++) {
                int ac = (bn + wn * 32 + nj * 8 + tg * 2) & 63;
                asv[nj][0] = a_src[h * 64 + ac]; asv[nj][1] = a_src[h * 64 + ac + 1];
                adv[nj][0] = a_dst[h * 64 + ac]; adv[nj][1] = a_dst[h * 64 + ac + 1];
            }
#pragma unroll
            for (int mi = 0; mi < 4; mi++) {
                float s0 = 0.f, s1 = 0.f, d0 = 0.f, d1 = 0.f;
#pragma unroll
                for (int nj = 0; nj < 4; nj++) {
                    s0 += acc[mi][nj][0] * asv[nj][0] + acc[mi][nj][1] * asv[nj][1];
                    s1 += acc[mi][nj][2] * asv[nj][0] + acc[mi][nj][3] * asv[nj][1];
                    d0 += acc[mi][nj][0] * adv[nj][0] + acc[mi][nj][1] * adv[nj][1];
                    d1 += acc[mi][nj][2] * adv[nj][0] + acc[mi][nj][3] * adv[nj][1];
                }
#pragma unroll
                for (int off = 1; off < 4; off <<= 1) {
                    s0 += __shfl_xor_sync(0xFFFFFFFFu, s0, off);
                    s1 += __shfl_xor_sync(0xFFFFFFFFu, s1, off);
                    d0 += __shfl_xor_sync(0xFFFFFFFFu, d0, off);
                    d1 += __shfl_xor_sync(0xFFFFFFFFu, d1, off);
                }
                if (tg == 0) {
                    int r0 = bm + wm * 64 + mi * 16 + g;
                    if (r0 < M) { atomicAdd(&als[r0 * 4 + h], s0); atomicAdd(&ald[r0 * 4 + h], d0); }
                    if (r0 + 8 < M) { atomicAdd(&als[(r0 + 8) * 4 + h], s1); atomicAdd(&ald[(r0 + 8) * 4 + h], d1); }
                }
            }
        }
    } else {
        // MODE 2: sigmoid(acc + bias) -> out[row*121+col], cols<121
#pragma unroll
        for (int mi = 0; mi < 4; mi++) {
            int r0 = bm + wm * 64 + mi * 16 + g;
#pragma unroll
            for (int nj = 0; nj < 4; nj++) {
                int col = bn + wn * 32 + nj * 8 + tg * 2;
#pragma unroll
                for (int q = 0; q < 4; q++) {
                    int row = r0 + (q >> 1) * 8;
                    int cc  = col + (q & 1);
                    if (row < M && cc < 121) {
                        float v = acc[mi][nj][q] + bias[cc];
                        ((float*)C)[(size_t)row * 121 + cc] = 1.f / (1.f + __expf(-v));
                    }
                }
            }
        }
    }
}

// ================= fused prep: xhalf + 3x wsplit + bpt + Wt =================
#define N_X0  ((long)NN * 128)
#define N_W1  (256L * 128)
#define N_W2  (256L * 256)
#define N_BP  (128L * 1536)
#define N_WT  (2L * 256 * 6)
__global__ void prep_all(const float* __restrict__ x, const float* __restrict__ W1,
                         const float* __restrict__ W2, const float* __restrict__ Wres2,
                         const float* __restrict__ W3, const float* __restrict__ a3s,
                         const float* __restrict__ a3d,
                         __half* __restrict__ x0, __half* __restrict__ w1t,
                         __half* __restrict__ w2t, __half* __restrict__ bpt,
                         float* __restrict__ Wt) {
    long i = (long)blockIdx.x * blockDim.x + threadIdx.x;
    if (i < N_X0) { x0[i] = __float2half(x[i]); return; }
    i -= N_X0;
    if (i < N_W1) {
        int n = (int)(i / 128), k = (int)(i % 128);
        w1t[i] = __float2half(W1[(size_t)k * 256 + n]); return;
    }
    i -= N_W1;
    if (i < N_W2) {
        int n = (int)(i / 256), k = (int)(i % 256);
        w2t[i] = __float2half(W2[(size_t)k * 256 + n]); return;
    }
    i -= N_W2;
    if (i < N_W2) {
        int n = (int)(i / 256), k = (int)(i % 256);
        w2t[65536 + i] = __float2half(Wres2[(size_t)k * 256 + n]); return;
    }
    i -= N_W2;
    if (i < N_BP) {
        int n = (int)(i / 1536), kk = (int)(i % 1536);
        int h_ = kk >> 8, k = kk & 255;
        float v = (n < 121) ? W3[(size_t)k * 726 + h_ * 121 + n] * (1.f / 6.f) : 0.f;
        bpt[i] = __float2half(v); return;
    }
    i -= N_BP;
    if (i < N_WT) {
        int side = (int)(i / (256 * 6));
        int r = (int)(i % (256 * 6));
        int k = r / 6, h = r % 6;
        const float* av = side ? a3d : a3s;
        float s = 0.f;
        for (int o = 0; o < 121; o++)
            s += W3[(size_t)k * 726 + h * 121 + o] * av[h * 121 + o];
        Wt[(size_t)side * 1536 + k * 6 + h] = s;
    }
}
#define PREP_TOTAL (N_X0 + N_W1 + 2 * N_W2 + N_BP + N_WT)

// ================= zero: cur + als1/ald1/als2/ald2 =================
__global__ void zero_prep(int* __restrict__ cur, float* __restrict__ a1,
                          float* __restrict__ b1, float* __restrict__ a2,
                          float* __restrict__ b2) {
    int i = blockIdx.x * blockDim.x + threadIdx.x;
    if (i < NN) cur[i] = 0;
    if (i < NN * 4) { a1[i] = 0.f; b1[i] = 0.f; a2[i] = 0.f; b2[i] = 0.f; }
}

// ================= CSR build =================
__global__ void hist_k(const int* __restrict__ dst, int* __restrict__ cur) {
    int e = blockIdx.x * blockDim.x + threadIdx.x;
    if (e >= ET) return;
    int d = (e < EE) ? dst[e] : e - EE;
    atomicAdd(&cur[d], 1);
}
__global__ void scan1(const int* __restrict__ deg, int* __restrict__ bsum) {
    __shared__ int sh[256];
    int i = blockIdx.x * 256 + threadIdx.x;
    sh[threadIdx.x] = (i < NN) ? deg[i] : 0;
    __syncthreads();
    for (int o = 128; o; o >>= 1) {
        if (threadIdx.x < o) sh[threadIdx.x] += sh[threadIdx.x + o];
        __syncthreads();
    }
    if (threadIdx.x == 0) bsum[blockIdx.x] = sh[0];
}
__global__ void scan2(int* __restrict__ bsum, int nb) {
    __shared__ int sh[256];
    int t = threadIdx.x;
    int v = (t < nb) ? bsum[t] : 0;
    sh[t] = v;
    __syncthreads();
    for (int o = 1; o < 256; o <<= 1) {
        int x2 = (t >= o) ? sh[t - o] : 0;
        __syncthreads();
        sh[t] += x2;
        __syncthreads();
    }
    if (t < nb) bsum[t] = sh[t] - v;
}
__global__ void scan3(const int* __restrict__ deg, const int* __restrict__ bsum,
                      int* __restrict__ rowptr, int* __restrict__ cur) {
    __shared__ int sh[256];
    int i = blockIdx.x * 256 + threadIdx.x;
    int v = (i < NN) ? deg[i] : 0;
    sh[threadIdx.x] = v;
    __syncthreads();
    for (int o = 1; o < 256; o <<= 1) {
        int t = (threadIdx.x >= o) ? sh[threadIdx.x - o] : 0;
        __syncthreads();
        sh[threadIdx.x] += t;
        __syncthreads();
    }
    int excl = sh[threadIdx.x] - v + bsum[blockIdx.x];
    if (i < NN) { rowptr[i] = excl; cur[i] = excl; }
    if (i == NN - 1) rowptr[NN] = excl + v;
}
__global__ void scatter_k(const int* __restrict__ src, const int* __restrict__ dst,
                          int* __restrict__ cur, int* __restrict__ csr) {
    int e = blockIdx.x * blockDim.x + threadIdx.x;
    if (e >= ET) return;
    int s, d;
    if (e < EE) { s = src[e]; d = dst[e]; } else { s = e - EE; d = s; }
    int pos = atomicAdd(&cur[d], 1);
    csr[pos] = s;
}

// ================= layers 1/2: fused gather-aggregate (+optional L3 logits) =================
__global__ void __launch_bounds__(256) agg_fused12(
    const int* __restrict__ rowptr, const int* __restrict__ csr,
    const __half* __restrict__ feat, int fstride,
    const float* __restrict__ als, const float* __restrict__ ald,
    const float* __restrict__ bias, int has_res, __half* __restrict__ out,
    int do_l3, const float* __restrict__ Wt,
    float* __restrict__ als3, float* __restrict__ ald3) {
    int n    = blockIdx.x * 8 + (threadIdx.x >> 5);
    int lane = threadIdx.x & 31;
    if (n >= NN) return;
    int col = lane * 8;
    int hl  = lane >> 3;
    bool wlane = (lane & 7) == 0;
    float aldh = wlane ? ald[n * 4 + hl] : 0.f;
    int beg = rowptr[n], end = rowptr[n + 1];
    float acc[8] = {0.f, 0.f, 0.f, 0.f, 0.f, 0.f, 0.f, 0.f};
    float denom = 0.f;
    int p = beg;
    for (; p + 2 <= end; p += 2) {
        int s0 = __ldg(&csr[p]), s1 = __ldg(&csr[p + 1]);
        float wv0 = 0.f, wv1 = 0.f;
        if (wlane) {
            float v0 = als[s0 * 4 + hl] + aldh; v0 = v0 > 0.f ? v0 : 0.2f * v0;
            float v1 = als[s1 * 4 + hl] + aldh; v1 = v1 > 0.f ? v1 : 0.2f * v1;
            wv0 = __expf(v0); wv1 = __expf(v1);
        }
        uint4 r0 = *(const uint4*)(feat + (size_t)s0 * fstride + col);
        uint4 r1 = *(const uint4*)(feat + (size_t)s1 * fstride + col);
        float w0 = __shfl_sync(0xFFFFFFFFu, wv0, lane & 24);
        float w1 = __shfl_sync(0xFFFFFFFFu, wv1, lane & 24);
        uint32_t q0[4] = {r0.x, r0.y, r0.z, r0.w};
        uint32_t q1[4] = {r1.x, r1.y, r1.z, r1.w};
#pragma unroll
        for (int i = 0; i < 4; i++) {
            float2 f0 = __half22float2(*(__half2*)&q0[i]);
            float2 f1 = __half22float2(*(__half2*)&q1[i]);
            acc[2 * i]     += f0.x * w0 + f1.x * w1;
            acc[2 * i + 1] += f0.y * w0 + f1.y * w1;
        }
        denom += w0 + w1;
    }
    if (p < end) {
        int s = __ldg(&csr[p]);
        float wv = 0.f;
        if (wlane) {
            float v = als[s * 4 + hl] + aldh;
            v = v > 0.f ? v : 0.2f * v;
            wv = __expf(v);
        }
        float w = __shfl_sync(0xFFFFFFFFu, wv, lane & 24);
        uint4 r = *(const uint4*)(feat + (size_t)s * fstride + col);
        uint32_t q[4] = {r.x, r.y, r.z, r.w};
#pragma unroll
        for (int i = 0; i < 4; i++) {
            float2 f = __half22float2(*(__half2*)&q[i]);
            acc[2 * i] += f.x * w; acc[2 * i + 1] += f.y * w;
        }
        denom += w;
    }
    float inv = 1.f / (denom + 1e-16f);
    float4 b0 = *(const float4*)(bias + col), b1 = *(const float4*)(bias + col + 4);
    float bb[8] = {b0.x, b0.y, b0.z, b0.w, b1.x, b1.y, b1.z, b1.w};
    float rr[8] = {0.f, 0.f, 0.f, 0.f, 0.f, 0.f, 0.f, 0.f};
    if (has_res) {
        uint4 r = *(const uint4*)(feat + (size_t)n * fstride + 256 + col);
        uint32_t q[4] = {r.x, r.y, r.z, r.w};
#pragma unroll
        for (int i = 0; i < 4; i++) {
            float2 f = __half22float2(*(__half2*)&q[i]);
            rr[2 * i] = f.x; rr[2 * i + 1] = f.y;
        }
    }
    float v8[8];
    uint32_t o[4];
#pragma unroll
    for (int i = 0; i < 4; i++) {
        float vx = acc[2 * i] * inv + bb[2 * i] + rr[2 * i];
        float vy = acc[2 * i + 1] * inv + bb[2 * i + 1] + rr[2 * i + 1];
        vx = vx > 0.f ? vx : (__expf(vx) - 1.f);
        vy = vy > 0.f ? vy : (__expf(vy) - 1.f);
        v8[2 * i] = vx; v8[2 * i + 1] = vy;
        __half2 hv = __floats2half2_rn(vx, vy);
        o[i] = *(uint32_t*)&hv;
    }
    *(uint4*)(out + (size_t)n * 256 + col) = make_uint4(o[0], o[1], o[2], o[3]);

    if (do_l3) {
        // layer-3 logits: ps[j] = sum_c x[n,c] * Wt[side][c][j]
        float ps[12];
#pragma unroll
        for (int j = 0; j < 12; j++) ps[j] = 0.f;
#pragma unroll
        for (int i = 0; i < 8; i++) {
            const float* ws = Wt + (size_t)(col + i) * 6;
            const float* wd = ws + 1536;
            float xv = v8[i];
#pragma unroll
            for (int j = 0; j < 6; j++) {
                ps[j]     += xv * ws[j];
                ps[6 + j] += xv * wd[j];
            }
        }
#pragma unroll
        for (int j = 0; j < 12; j++)
#pragma unroll
            for (int off = 16; off; off >>= 1)
                ps[j] += __shfl_down_sync(0xFFFFFFFFu, ps[j], off);
        if (lane == 0) {
#pragma unroll
            for (int j = 0; j < 6; j++) {
                als3[n * 6 + j] = ps[j];
                ald3[n * 6 + j] = ps[6 + j];
            }
        }
    }
}

// ================= layer 3: fused gather, 1 warp per node =================
__global__ void __launch_bounds__(256) agg_fused3(
    const int* __restrict__ rowptr, const int* __restrict__ csr,
    const __half* __restrict__ x, const float* __restrict__ als,
    const float* __restrict__ ald, __half* __restrict__ y) {
    int n    = blockIdx.x * 8 + (threadIdx.x >> 5);
    int lane = threadIdx.x & 31;
    if (n >= NN) return;
    int col = lane * 8;
    float acc[6][8];
    float den[6];
#pragma unroll
    for (int h = 0; h < 6; h++) {
        den[h] = 0.f;
#pragma unroll
        for (int j = 0; j < 8; j++) acc[h][j] = 0.f;
    }
    float aldl = (lane < 6) ? ald[n * 6 + lane] : 0.f;
    int beg = rowptr[n], end = rowptr[n + 1];
    for (int p = beg; p < end; p++) {
        int s = __ldg(&csr[p]);
        float wv = 0.f;
        if (lane < 6) {
            float v = als[s * 6 + lane] + aldl;
            v = v > 0.f ? v : 0.2f * v;
            wv = __expf(v);
        }
        uint4 r = *(const uint4*)(x + (size_t)s * 256 + col);
        uint32_t q[4] = {r.x, r.y, r.z, r.w};
        float f[8];
#pragma unroll
        for (int i = 0; i < 4; i++) {
            float2 t = __half22float2(*(__half2*)&q[i]);
            f[2 * i] = t.x; f[2 * i + 1] = t.y;
        }
#pragma unroll
        for (int h = 0; h < 6; h++) {
            float w = __shfl_sync(0xFFFFFFFFu, wv, h);
            den[h] += w;
#pragma unroll
            for (int j = 0; j < 8; j++) acc[h][j] += f[j] * w;
        }
    }
#pragma unroll
    for (int h = 0; h < 6; h++) {
        float inv = 1.f / (den[h] + 1e-16f);
        uint32_t o[4];
#pragma unroll
        for (int i = 0; i < 4; i++) {
            __half2 hv = __floats2half2_rn(acc[h][2 * i] * inv, acc[h][2 * i + 1] * inv);
            o[i] = *(uint32_t*)&hv;
        }
        *(uint4*)(y + ((size_t)n * 6 + h) * 256 + col) = make_uint4(o[0], o[1], o[2], o[3]);
    }
}

// ================= host driver =================
extern "C" void kernel_launch(void* const* d_in, const int* in_sizes, int n_in,
                              void* d_out, int out_size) {
    const float* x     = (const float*)d_in[0];
    const int*   src   = (const int*)  d_in[1];
    const int*   dst   = (const int*)  d_in[2];
    const float* W1    = (const float*)d_in[3];
    const float* a1s   = (const float*)d_in[4];
    const float* a1d   = (const float*)d_in[5];
    const float* b1    = (const float*)d_in[6];
    const float* W2    = (const float*)d_in[7];
    const float* a2s   = (const float*)d_in[8];
    const float* a2d   = (const float*)d_in[9];
    const float* b2    = (const float*)d_in[10];
    const float* Wres2 = (const float*)d_in[11];
    const float* W3    = (const float*)d_in[12];
    const float* a3s   = (const float*)d_in[13];
    const float* a3d   = (const float*)d_in[14];
    const float* b3    = (const float*)d_in[15];
    float* out = (float*)d_out;

    __half *p_x0, *p_feat, *p_x, *p_y, *w1t, *w2t, *bpt;
    float *p_als1, *p_ald1, *p_als2, *p_ald2, *p_als3, *p_ald3, *p_Wt;
    int *p_csr, *p_rowptr, *p_cur, *p_bsum;
    cudaGetSymbolAddress((void**)&p_x0,     g_x0);
    cudaGetSymbolAddress((void**)&p_feat,   g_feat);
    cudaGetSymbolAddress((void**)&p_x,      g_x);
    cudaGetSymbolAddress((void**)&p_y,      g_y);
    cudaGetSymbolAddress((void**)&p_als1,   g_als1);
    cudaGetSymbolAddress((void**)&p_ald1,   g_ald1);
    cudaGetSymbolAddress((void**)&p_als2,   g_als2);
    cudaGetSymbolAddress((void**)&p_ald2,   g_ald2);
    cudaGetSymbolAddress((void**)&p_als3,   g_als3);
    cudaGetSymbolAddress((void**)&p_ald3,   g_ald3);
    cudaGetSymbolAddress((void**)&p_Wt,     g_Wt);
    cudaGetSymbolAddress((void**)&p_csr,    g_csr);
    cudaGetSymbolAddress((void**)&p_rowptr, g_rowptr);
    cudaGetSymbolAddress((void**)&p_cur,    g_cur);
    cudaGetSymbolAddress((void**)&p_bsum,   g_bsum);
    cudaGetSymbolAddress((void**)&w1t, g_w1t);
    cudaGetSymbolAddress((void**)&w2t, g_w2t);
    cudaGetSymbolAddress((void**)&bpt, g_bpt);

    // ---- zero + CSR build ----
    zero_prep<<<(NN * 4 + 255) / 256, 256>>>(p_cur, p_als1, p_ald1, p_als2, p_ald2);
    hist_k<<<(ET + 255) / 256, 256>>>(dst, p_cur);
    scan1<<<196, 256>>>(p_cur, p_bsum);
    scan2<<<1, 256>>>(p_bsum, 196);
    scan3<<<196, 256>>>(p_cur, p_bsum, p_rowptr, p_cur);
    scatter_k<<<(ET + 255) / 256, 256>>>(src, dst, p_cur, p_csr);

    // ---- fused prep ----
    prep_all<<<(unsigned)((PREP_TOTAL + 255) / 256), 256>>>(
        x, W1, W2, Wres2, W3, a3s, a3d, p_x0, w1t, w2t, bpt, p_Wt);

    // ---- Layer 1: GEMM + fused logits, then gather ----
    {
        dim3 g(2, (NN + 127) / 128);
        mma_gemm<1, __half><<<g, 256>>>(p_x0, w1t, p_feat, NN, 128, 256,
                                        a1s, a1d, p_als1, p_ald1, nullptr);
        agg_fused12<<<(NN + 7) / 8, 256>>>(p_rowptr, p_csr, p_feat, 256, p_als1, p_ald1,
                                           b1, 0, p_x, 0, nullptr, nullptr, nullptr);
    }
    // ---- Layer 2: merged GEMM (Nc=512) + fused logits, gather + fused L3 logits ----
    {
        dim3 g(4, (NN + 127) / 128);
        mma_gemm<1, __half><<<g, 256>>>(p_x, w2t, p_feat, NN, 256, 512,
                                        a2s, a2d, p_als2, p_ald2, nullptr);
        agg_fused12<<<(NN + 7) / 8, 256>>>(p_rowptr, p_csr, p_feat, 512, p_als2, p_ald2,
                                           b2, 1, p_x, 1, p_Wt, p_als3, p_ald3);
    }
    // ---- Layer 3: gather, GEMM + fused sigmoid ----
    {
        agg_fused3<<<(NN + 7) / 8, 256>>>(p_rowptr, p_csr, p_x, p_als3, p_ald3, p_y);
        dim3 g(1, (NN + 127) / 128);
        mma_gemm<2, float><<<g, 256>>>(p_y, bpt, out, NN, 1536, 128,
                                       nullptr, nullptr, nullptr, nullptr, b3);
    }
}

// round 10
// speedup vs baseline: 6.3671x; 1.0074x over previous
#include <cuda_runtime.h>
#include <cuda_fp16.h>
#include <math.h>
#include <stdint.h>

#define NN 50000
#define EE 800000
#define ET (EE + NN)

// ---------------- device scratch (allocation-free) ----------------
__device__ __half g_x0  [(size_t)NN * 128];
__device__ __half g_feat[(size_t)NN * 512];
__device__ __half g_x   [(size_t)NN * 256];
__device__ __half g_y   [(size_t)NN * 1536];
__device__ float  g_als1[NN * 4], g_ald1[NN * 4];
__device__ float  g_als2[NN * 4], g_ald2[NN * 4];
__device__ float  g_als3[NN * 6], g_ald3[NN * 6];
__device__ float  g_Wt  [2 * 256 * 6];
__device__ int    g_csr [ET];
__device__ int    g_rowptr[NN + 1];
__device__ int    g_cur [NN];
__device__ int    g_bsum[256];
__device__ __half g_w1t[256 * 128];
__device__ __half g_w2t[512 * 256];
__device__ __half g_bpt[128 * 1536];

// ---------------- helpers ----------------
__device__ __forceinline__ void mma16816(float* c, const uint32_t* a, const uint32_t* b) {
    asm volatile(
        "mma.sync.aligned.m16n8k16.row.col.f32.f16.f16.f32 "
        "{%0,%1,%2,%3}, {%4,%5,%6,%7}, {%8,%9}, {%0,%1,%2,%3};"
        : "+f"(c[0]), "+f"(c[1]), "+f"(c[2]), "+f"(c[3])
        : "r"(a[0]), "r"(a[1]), "r"(a[2]), "r"(a[3]), "r"(b[0]), "r"(b[1]));
}
#define CP_ASYNC16(sa, gp) asm volatile("cp.async.ca.shared.global [%0], [%1], 16;" :: "r"(sa), "l"(gp))
#define CP_COMMIT()        asm volatile("cp.async.commit_group;" ::: "memory")
#define CP_WAIT(n)         asm volatile("cp.async.wait_group %0;" :: "n"(n) : "memory")

// ================= HMMA GEMM, 3-stage cp.async pipeline, fused epilogues =================
// MODE 1: CT=__half; store feat + fused attention-logit atomics (cols<256, H=4)
// MODE 2: CT=float;  store sigmoid(acc + bias[col]) to out[row*121+col], cols<121
#define SSTR2 20
#define STAGE_W (2 * 128 * SSTR2)
#define TCG_DSMEM (3 * STAGE_W * 4)
template <int MODE, typename CT>
__global__ void __launch_bounds__(256) mma_gemm(
    const __half* __restrict__ A, const __half* __restrict__ Bt,
    CT* __restrict__ C, int M, int K, int Nc,
    const float* __restrict__ a_src, const float* __restrict__ a_dst,
    float* __restrict__ als, float* __restrict__ ald,
    const float* __restrict__ bias) {
    extern __shared__ uint32_t sh[];
    const int tid = threadIdx.x, wid = tid >> 5, lane = tid & 31;
    const int wm = wid & 1, wn = wid >> 1;
    const int bm = blockIdx.y * 128, bn = blockIdx.x * 128;
    const int g = lane >> 2, tg = lane & 3;

    float acc[4][4][4];
#pragma unroll
    for (int i = 0; i < 4; i++)
#pragma unroll
        for (int j = 0; j < 4; j++)
#pragma unroll
            for (int q = 0; q < 4; q++) acc[i][j][q] = 0.f;

    const int crow = tid >> 1, csegb = (tid & 1) * 2;
    const int grc = min(bm + crow, M - 1);
    const int gn  = bn + crow;
    const __half* arow_p = A  + (size_t)grc * K;
    const __half* brow_p = Bt + (size_t)gn  * K;
    const int nch = K >> 5;

    auto issue = [&](int st, int k0) {
        uint32_t sa = (uint32_t)__cvta_generic_to_shared(sh + st * STAGE_W + crow * SSTR2);
        uint32_t sb = sa + 128 * SSTR2 * 4;
        const __half* ap = arow_p + k0;
        const __half* bp = brow_p + k0;
#pragma unroll
        for (int i = 0; i < 2; i++) {
            int seg = csegb + i;
            CP_ASYNC16(sa + seg * 16, ap + seg * 8);
            CP_ASYNC16(sb + seg * 16, bp + seg * 8);
        }
        CP_COMMIT();
    };

    issue(0, 0);
    if (nch > 1) issue(1, 32);
    int wst = 2, rst = 0;
    for (int ch = 0; ch < nch; ch++) {
        if (ch + 1 < nch) CP_WAIT(1); else CP_WAIT(0);
        __syncthreads();
        if (ch + 2 < nch) {
            issue(wst, (ch + 2) << 5);
            if (++wst == 3) wst = 0;
        }
        const uint32_t* SA = sh + rst * STAGE_W;
        const uint32_t* SB = SA + 128 * SSTR2;
        if (++rst == 3) rst = 0;
#pragma unroll
        for (int ks = 0; ks < 2; ks++) {
            const int kb = ks * 8;
            uint32_t af[4][4], bf[4][2];
#pragma unroll
            for (int mi = 0; mi < 4; mi++) {
                const uint32_t* ph = SA + (wm * 64 + mi * 16 + g) * SSTR2 + kb + tg;
                af[mi][0] = ph[0]; af[mi][1] = ph[8 * SSTR2];
                af[mi][2] = ph[4]; af[mi][3] = ph[8 * SSTR2 + 4];
            }
#pragma unroll
            for (int nj = 0; nj < 4; nj++) {
                const uint32_t* ph = SB + (wn * 32 + nj * 8 + g) * SSTR2 + kb + tg;
                bf[nj][0] = ph[0]; bf[nj][1] = ph[4];
            }
#pragma unroll
            for (int mi = 0; mi < 4; mi++)
#pragma unroll
                for (int nj = 0; nj < 4; nj++)
                    mma16816(acc[mi][nj], af[mi], bf[nj]);
        }
    }

    if (MODE == 1) {
#pragma unroll
        for (int mi = 0; mi < 4; mi++) {
            int row = bm + wm * 64 + mi * 16 + g;
#pragma unroll
            for (int nj = 0; nj < 4; nj++) {
                int col = bn + wn * 32 + nj * 8 + tg * 2;
                if (row < M)
                    *(__half2*)((__half*)C + (size_t)row * Nc + col) = __floats2half2_rn(acc[mi][nj][0], acc[mi][nj][1]);
                if (row + 8 < M)
                    *(__half2*)((__half*)C + (size_t)(row + 8) * Nc + col) = __floats2half2_rn(acc[mi][nj][2], acc[mi][nj][3]);
            }
        }
        if (bn + wn * 32 < 256) {
            int h = (bn + wn * 32) >> 6;
            float asv[4][2], adv[4][2];
#pragma unroll
            for (int nj = 0; nj < 4; nj++) {
                int ac = (bn + wn * 32 + nj * 8 + tg * 2) & 63;
                asv[nj][0] = a_src[h * 64 + ac]; asv[nj][1] = a_src[h * 64 + ac + 1];
                adv[nj][0] = a_dst[h * 64 + ac]; adv[nj][1] = a_dst[h * 64 + ac + 1];
            }
#pragma unroll
            for (int mi = 0; mi < 4; mi++) {
                float s0 = 0.f, s1 = 0.f, d0 = 0.f, d1 = 0.f;
#pragma unroll
                for (int nj = 0; nj < 4; nj++) {
                    s0 += acc[mi][nj][0] * asv[nj][0] + acc[mi][nj][1] * asv[nj][1];
                    s1 += acc[mi][nj][2] * asv[nj][0] + acc[mi][nj][3] * asv[nj][1];
                    d0 += acc[mi][nj][0] * adv[nj][0] + acc[mi][nj][1] * adv[nj][1];
                    d1 += acc[mi][nj][2] * adv[nj][0] + acc[mi][nj][3] * adv[nj][1];
                }
#pragma unroll
                for (int off = 1; off < 4; off <<= 1) {
                    s0 += __shfl_xor_sync(0xFFFFFFFFu, s0, off);
                    s1 += __shfl_xor_sync(0xFFFFFFFFu, s1, off);
                    d0 += __shfl_xor_sync(0xFFFFFFFFu, d0, off);
                    d1 += __shfl_xor_sync(0xFFFFFFFFu, d1, off);
                }
                if (tg == 0) {
                    int r0 = bm + wm * 64 + mi * 16 + g;
                    if (r0 < M) { atomicAdd(&als[r0 * 4 + h], s0); atomicAdd(&ald[r0 * 4 + h], d0); }
                    if (r0 + 8 < M) { atomicAdd(&als[(r0 + 8) * 4 + h], s1); atomicAdd(&ald[(r0 + 8) * 4 + h], d1); }
                }
            }
        }
    } else {
#pragma unroll
        for (int mi = 0; mi < 4; mi++) {
            int r0 = bm + wm * 64 + mi * 16 + g;
#pragma unroll
            for (int nj = 0; nj < 4; nj++) {
                int col = bn + wn * 32 + nj * 8 + tg * 2;
#pragma unroll
                for (int q = 0; q < 4; q++) {
                    int row = r0 + (q >> 1) * 8;
                    int cc  = col + (q & 1);
                    if (row < M && cc < 121) {
                        float v = acc[mi][nj][q] + bias[cc];
                        ((float*)C)[(size_t)row * 121 + cc] = 1.f / (1.f + __expf(-v));
                    }
                }
            }
        }
    }
}

// ================= fused prep =================
#define N_X0  ((long)NN * 128)
#define N_W1  (256L * 128)
#define N_W2  (256L * 256)
#define N_BP  (128L * 1536)
#define N_WT  (2L * 256 * 6)
__global__ void prep_all(const float* __restrict__ x, const float* __restrict__ W1,
                         const float* __restrict__ W2, const float* __restrict__ Wres2,
                         const float* __restrict__ W3, const float* __restrict__ a3s,
                         const float* __restrict__ a3d,
                         __half* __restrict__ x0, __half* __restrict__ w1t,
                         __half* __restrict__ w2t, __half* __restrict__ bpt,
                         float* __restrict__ Wt) {
    long i = (long)blockIdx.x * blockDim.x + threadIdx.x;
    if (i < N_X0) { x0[i] = __float2half(x[i]); return; }
    i -= N_X0;
    if (i < N_W1) {
        int n = (int)(i / 128), k = (int)(i % 128);
        w1t[i] = __float2half(W1[(size_t)k * 256 + n]); return;
    }
    i -= N_W1;
    if (i < N_W2) {
        int n = (int)(i / 256), k = (int)(i % 256);
        w2t[i] = __float2half(W2[(size_t)k * 256 + n]); return;
    }
    i -= N_W2;
    if (i < N_W2) {
        int n = (int)(i / 256), k = (int)(i % 256);
        w2t[65536 + i] = __float2half(Wres2[(size_t)k * 256 + n]); return;
    }
    i -= N_W2;
    if (i < N_BP) {
        int n = (int)(i / 1536), kk = (int)(i % 1536);
        int h_ = kk >> 8, k = kk & 255;
        float v = (n < 121) ? W3[(size_t)k * 726 + h_ * 121 + n] * (1.f / 6.f) : 0.f;
        bpt[i] = __float2half(v); return;
    }
    i -= N_BP;
    if (i < N_WT) {
        int side = (int)(i / (256 * 6));
        int r = (int)(i % (256 * 6));
        int k = r / 6, h = r % 6;
        const float* av = side ? a3d : a3s;
        float s = 0.f;
        for (int o = 0; o < 121; o++)
            s += W3[(size_t)k * 726 + h * 121 + o] * av[h * 121 + o];
        Wt[(size_t)side * 1536 + k * 6 + h] = s;
    }
}
#define PREP_TOTAL (N_X0 + N_W1 + 2 * N_W2 + N_BP + N_WT)

// ================= zero =================
__global__ void zero_prep(int* __restrict__ cur, float* __restrict__ a1,
                          float* __restrict__ b1, float* __restrict__ a2,
                          float* __restrict__ b2) {
    int i = blockIdx.x * blockDim.x + threadIdx.x;
    if (i < NN) cur[i] = 0;
    if (i < NN * 4) { a1[i] = 0.f; b1[i] = 0.f; a2[i] = 0.f; b2[i] = 0.f; }
}

// ================= CSR build =================
__global__ void hist_k(const int* __restrict__ dst, int* __restrict__ cur) {
    int e = blockIdx.x * blockDim.x + threadIdx.x;
    if (e >= ET) return;
    int d = (e < EE) ? dst[e] : e - EE;
    atomicAdd(&cur[d], 1);
}
__global__ void scan1(const int* __restrict__ deg, int* __restrict__ bsum) {
    __shared__ int sh[256];
    int i = blockIdx.x * 256 + threadIdx.x;
    sh[threadIdx.x] = (i < NN) ? deg[i] : 0;
    __syncthreads();
    for (int o = 128; o; o >>= 1) {
        if (threadIdx.x < o) sh[threadIdx.x] += sh[threadIdx.x + o];
        __syncthreads();
    }
    if (threadIdx.x == 0) bsum[blockIdx.x] = sh[0];
}
__global__ void scan2(int* __restrict__ bsum, int nb) {
    __shared__ int sh[256];
    int t = threadIdx.x;
    int v = (t < nb) ? bsum[t] : 0;
    sh[t] = v;
    __syncthreads();
    for (int o = 1; o < 256; o <<= 1) {
        int x2 = (t >= o) ? sh[t - o] : 0;
        __syncthreads();
        sh[t] += x2;
        __syncthreads();
    }
    if (t < nb) bsum[t] = sh[t] - v;
}
__global__ void scan3(const int* __restrict__ deg, const int* __restrict__ bsum,
                      int* __restrict__ rowptr, int* __restrict__ cur) {
    __shared__ int sh[256];
    int i = blockIdx.x * 256 + threadIdx.x;
    int v = (i < NN) ? deg[i] : 0;
    sh[threadIdx.x] = v;
    __syncthreads();
    for (int o = 1; o < 256; o <<= 1) {
        int t = (threadIdx.x >= o) ? sh[threadIdx.x - o] : 0;
        __syncthreads();
        sh[threadIdx.x] += t;
        __syncthreads();
    }
    int excl = sh[threadIdx.x] - v + bsum[blockIdx.x];
    if (i < NN) { rowptr[i] = excl; cur[i] = excl; }
    if (i == NN - 1) rowptr[NN] = excl + v;
}
__global__ void scatter_k(const int* __restrict__ src, const int* __restrict__ dst,
                          int* __restrict__ cur, int* __restrict__ csr) {
    int e = blockIdx.x * blockDim.x + threadIdx.x;
    if (e >= ET) return;
    int s, d;
    if (e < EE) { s = src[e]; d = dst[e]; } else { s = e - EE; d = s; }
    int pos = atomicAdd(&cur[d], 1);
    csr[pos] = s;
}

// ================= layers 1/2: fused gather-aggregate (+optional L3 logits) =================
__global__ void __launch_bounds__(256) agg_fused12(
    const int* __restrict__ rowptr, const int* __restrict__ csr,
    const __half* __restrict__ feat, int fstride,
    const float* __restrict__ als, const float* __restrict__ ald,
    const float* __restrict__ bias, int has_res, __half* __restrict__ out,
    int do_l3, const float* __restrict__ Wt,
    float* __restrict__ als3, float* __restrict__ ald3) {
    int n    = blockIdx.x * 8 + (threadIdx.x >> 5);
    int lane = threadIdx.x & 31;
    if (n >= NN) return;
    int col = lane * 8;
    int hl  = lane >> 3;
    bool wlane = (lane & 7) == 0;
    float aldh = wlane ? ald[n * 4 + hl] : 0.f;
    int beg = rowptr[n], end = rowptr[n + 1];
    float acc[8] = {0.f, 0.f, 0.f, 0.f, 0.f, 0.f, 0.f, 0.f};
    float denom = 0.f;
    int p = beg;
    for (; p + 4 <= end; p += 4) {
        int s0 = __ldg(&csr[p]),     s1 = __ldg(&csr[p + 1]);
        int s2 = __ldg(&csr[p + 2]), s3 = __ldg(&csr[p + 3]);
        float wv0 = 0.f, wv1 = 0.f, wv2 = 0.f, wv3 = 0.f;
        if (wlane) {
            float v0 = als[s0 * 4 + hl] + aldh; v0 = v0 > 0.f ? v0 : 0.2f * v0;
            float v1 = als[s1 * 4 + hl] + aldh; v1 = v1 > 0.f ? v1 : 0.2f * v1;
            float v2 = als[s2 * 4 + hl] + aldh; v2 = v2 > 0.f ? v2 : 0.2f * v2;
            float v3 = als[s3 * 4 + hl] + aldh; v3 = v3 > 0.f ? v3 : 0.2f * v3;
            wv0 = __expf(v0); wv1 = __expf(v1); wv2 = __expf(v2); wv3 = __expf(v3);
        }
        uint4 r0 = *(const uint4*)(feat + (size_t)s0 * fstride + col);
        uint4 r1 = *(const uint4*)(feat + (size_t)s1 * fstride + col);
        uint4 r2 = *(const uint4*)(feat + (size_t)s2 * fstride + col);
        uint4 r3 = *(const uint4*)(feat + (size_t)s3 * fstride + col);
        float w0 = __shfl_sync(0xFFFFFFFFu, wv0, lane & 24);
        float w1 = __shfl_sync(0xFFFFFFFFu, wv1, lane & 24);
        float w2 = __shfl_sync(0xFFFFFFFFu, wv2, lane & 24);
        float w3 = __shfl_sync(0xFFFFFFFFu, wv3, lane & 24);
        uint32_t q0[4] = {r0.x, r0.y, r0.z, r0.w};
        uint32_t q1[4] = {r1.x, r1.y, r1.z, r1.w};
        uint32_t q2[4] = {r2.x, r2.y, r2.z, r2.w};
        uint32_t q3[4] = {r3.x, r3.y, r3.z, r3.w};
#pragma unroll
        for (int i = 0; i < 4; i++) {
            float2 f0 = __half22float2(*(__half2*)&q0[i]);
            float2 f1 = __half22float2(*(__half2*)&q1[i]);
            float2 f2 = __half22float2(*(__half2*)&q2[i]);
            float2 f3 = __half22float2(*(__half2*)&q3[i]);
            acc[2 * i]     += f0.x * w0 + f1.x * w1 + f2.x * w2 + f3.x * w3;
            acc[2 * i + 1] += f0.y * w0 + f1.y * w1 + f2.y * w2 + f3.y * w3;
        }
        denom += w0 + w1 + w2 + w3;
    }
    for (; p < end; p++) {
        int s = __ldg(&csr[p]);
        float wv = 0.f;
        if (wlane) {
            float v = als[s * 4 + hl] + aldh;
            v = v > 0.f ? v : 0.2f * v;
            wv = __expf(v);
        }
        float w = __shfl_sync(0xFFFFFFFFu, wv, lane & 24);
        uint4 r = *(const uint4*)(feat + (size_t)s * fstride + col);
        uint32_t q[4] = {r.x, r.y, r.z, r.w};
#pragma unroll
        for (int i = 0; i < 4; i++) {
            float2 f = __half22float2(*(__half2*)&q[i]);
            acc[2 * i] += f.x * w; acc[2 * i + 1] += f.y * w;
        }
        denom += w;
    }
    float inv = 1.f / (denom + 1e-16f);
    float4 b0 = *(const float4*)(bias + col), b1 = *(const float4*)(bias + col + 4);
    float bb[8] = {b0.x, b0.y, b0.z, b0.w, b1.x, b1.y, b1.z, b1.w};
    float rr[8] = {0.f, 0.f, 0.f, 0.f, 0.f, 0.f, 0.f, 0.f};
    if (has_res) {
        uint4 r = *(const uint4*)(feat + (size_t)n * fstride + 256 + col);
        uint32_t q[4] = {r.x, r.y, r.z, r.w};
#pragma unroll
        for (int i = 0; i < 4; i++) {
            float2 f = __half22float2(*(__half2*)&q[i]);
            rr[2 * i] = f.x; rr[2 * i + 1] = f.y;
        }
    }
    float v8[8];
    uint32_t o[4];
#pragma unroll
    for (int i = 0; i < 4; i++) {
        float vx = acc[2 * i] * inv + bb[2 * i] + rr[2 * i];
        float vy = acc[2 * i + 1] * inv + bb[2 * i + 1] + rr[2 * i + 1];
        vx = vx > 0.f ? vx : (__expf(vx) - 1.f);
        vy = vy > 0.f ? vy : (__expf(vy) - 1.f);
        v8[2 * i] = vx; v8[2 * i + 1] = vy;
        __half2 hv = __floats2half2_rn(vx, vy);
        o[i] = *(uint32_t*)&hv;
    }
    *(uint4*)(out + (size_t)n * 256 + col) = make_uint4(o[0], o[1], o[2], o[3]);

    if (do_l3) {
        float ps[12];
#pragma unroll
        for (int j = 0; j < 12; j++) ps[j] = 0.f;
#pragma unroll
        for (int i = 0; i < 8; i++) {
            const float* ws = Wt + (size_t)(col + i) * 6;
            const float* wd = ws + 1536;
            float xv = v8[i];
#pragma unroll
            for (int j = 0; j < 6; j++) {
                ps[j]     += xv * ws[j];
                ps[6 + j] += xv * wd[j];
            }
        }
#pragma unroll
        for (int j = 0; j < 12; j++)
#pragma unroll
            for (int off = 16; off; off >>= 1)
                ps[j] += __shfl_down_sync(0xFFFFFFFFu, ps[j], off);
        if (lane == 0) {
#pragma unroll
            for (int j = 0; j < 6; j++) {
                als3[n * 6 + j] = ps[j];
                ald3[n * 6 + j] = ps[6 + j];
            }
        }
    }
}

// ================= layer 3: fused gather, 1 warp per node =================
__global__ void __launch_bounds__(256) agg_fused3(
    const int* __restrict__ rowptr, const int* __restrict__ csr,
    const __half* __restrict__ x, const float* __restrict__ als,
    const float* __restrict__ ald, __half* __restrict__ y) {
    int n    = blockIdx.x * 8 + (threadIdx.x >> 5);
    int lane = threadIdx.x & 31;
    if (n >= NN) return;
    int col = lane * 8;
    float acc[6][8];
    float den[6];
#pragma unroll
    for (int h = 0; h < 6; h++) {
        den[h] = 0.f;
#pragma unroll
        for (int j = 0; j < 8; j++) acc[h][j] = 0.f;
    }
    float aldl = (lane < 6) ? ald[n * 6 + lane] : 0.f;
    int beg = rowptr[n], end = rowptr[n + 1];
    int p = beg;
    for (; p + 2 <= end; p += 2) {
        int s0 = __ldg(&csr[p]), s1 = __ldg(&csr[p + 1]);
        float wv0 = 0.f, wv1 = 0.f;
        if (lane < 6) {
            float v0 = als[s0 * 6 + lane] + aldl; v0 = v0 > 0.f ? v0 : 0.2f * v0;
            float v1 = als[s1 * 6 + lane] + aldl; v1 = v1 > 0.f ? v1 : 0.2f * v1;
            wv0 = __expf(v0); wv1 = __expf(v1);
        }
        uint4 r0 = *(const uint4*)(x + (size_t)s0 * 256 + col);
        uint4 r1 = *(const uint4*)(x + (size_t)s1 * 256 + col);
        uint32_t q0[4] = {r0.x, r0.y, r0.z, r0.w};
        uint32_t q1[4] = {r1.x, r1.y, r1.z, r1.w};
        float f0[8], f1[8];
#pragma unroll
        for (int i = 0; i < 4; i++) {
            float2 t0 = __half22float2(*(__half2*)&q0[i]);
            float2 t1 = __half22float2(*(__half2*)&q1[i]);
            f0[2 * i] = t0.x; f0[2 * i + 1] = t0.y;
            f1[2 * i] = t1.x; f1[2 * i + 1] = t1.y;
        }
#pragma unroll
        for (int h = 0; h < 6; h++) {
            float w0 = __shfl_sync(0xFFFFFFFFu, wv0, h);
            float w1 = __shfl_sync(0xFFFFFFFFu, wv1, h);
            den[h] += w0 + w1;
#pragma unroll
            for (int j = 0; j < 8; j++) acc[h][j] += f0[j] * w0 + f1[j] * w1;
        }
    }
    if (p < end) {
        int s = __ldg(&csr[p]);
        float wv = 0.f;
        if (lane < 6) {
            float v = als[s * 6 + lane] + aldl;
            v = v > 0.f ? v : 0.2f * v;
            wv = __expf(v);
        }
        uint4 r = *(const uint4*)(x + (size_t)s * 256 + col);
        uint32_t q[4] = {r.x, r.y, r.z, r.w};
        float f[8];
#pragma unroll
        for (int i = 0; i < 4; i++) {
            float2 t = __half22float2(*(__half2*)&q[i]);
            f[2 * i] = t.x; f[2 * i + 1] = t.y;
        }
#pragma unroll
        for (int h = 0; h < 6; h++) {
            float w = __shfl_sync(0xFFFFFFFFu, wv, h);
            den[h] += w;
#pragma unroll
            for (int j = 0; j < 8; j++) acc[h][j] += f[j] * w;
        }
    }
#pragma unroll
    for (int h = 0; h < 6; h++) {
        float inv = 1.f / (den[h] + 1e-16f);
        uint32_t o[4];
#pragma unroll
        for (int i = 0; i < 4; i++) {
            __half2 hv = __floats2half2_rn(acc[h][2 * i] * inv, acc[h][2 * i + 1] * inv);
            o[i] = *(uint32_t*)&hv;
        }
        *(uint4*)(y + ((size_t)n * 6 + h) * 256 + col) = make_uint4(o[0], o[1], o[2], o[3]);
    }
}

// ================= host driver =================
extern "C" void kernel_launch(void* const* d_in, const int* in_sizes, int n_in,
                              void* d_out, int out_size) {
    const float* x     = (const float*)d_in[0];
    const int*   src   = (const int*)  d_in[1];
    const int*   dst   = (const int*)  d_in[2];
    const float* W1    = (const float*)d_in[3];
    const float* a1s   = (const float*)d_in[4];
    const float* a1d   = (const float*)d_in[5];
    const float* b1    = (const float*)d_in[6];
    const float* W2    = (const float*)d_in[7];
    const float* a2s   = (const float*)d_in[8];
    const float* a2d   = (const float*)d_in[9];
    const float* b2    = (const float*)d_in[10];
    const float* Wres2 = (const float*)d_in[11];
    const float* W3    = (const float*)d_in[12];
    const float* a3s   = (const float*)d_in[13];
    const float* a3d   = (const float*)d_in[14];
    const float* b3    = (const float*)d_in[15];
    float* out = (float*)d_out;

    __half *p_x0, *p_feat, *p_x, *p_y, *w1t, *w2t, *bpt;
    float *p_als1, *p_ald1, *p_als2, *p_ald2, *p_als3, *p_ald3, *p_Wt;
    int *p_csr, *p_rowptr, *p_cur, *p_bsum;
    cudaGetSymbolAddress((void**)&p_x0,     g_x0);
    cudaGetSymbolAddress((void**)&p_feat,   g_feat);
    cudaGetSymbolAddress((void**)&p_x,      g_x);
    cudaGetSymbolAddress((void**)&p_y,      g_y);
    cudaGetSymbolAddress((void**)&p_als1,   g_als1);
    cudaGetSymbolAddress((void**)&p_ald1,   g_ald1);
    cudaGetSymbolAddress((void**)&p_als2,   g_als2);
    cudaGetSymbolAddress((void**)&p_ald2,   g_ald2);
    cudaGetSymbolAddress((void**)&p_als3,   g_als3);
    cudaGetSymbolAddress((void**)&p_ald3,   g_ald3);
    cudaGetSymbolAddress((void**)&p_Wt,     g_Wt);
    cudaGetSymbolAddress((void**)&p_csr,    g_csr);
    cudaGetSymbolAddress((void**)&p_rowptr, g_rowptr);
    cudaGetSymbolAddress((void**)&p_cur,    g_cur);
    cudaGetSymbolAddress((void**)&p_bsum,   g_bsum);
    cudaGetSymbolAddress((void**)&w1t, g_w1t);
    cudaGetSymbolAddress((void**)&w2t, g_w2t);
    cudaGetSymbolAddress((void**)&bpt, g_bpt);

    cudaFuncSetAttribute(mma_gemm<1, __half>, cudaFuncAttributeMaxDynamicSharedMemorySize, TCG_DSMEM);
    cudaFuncSetAttribute(mma_gemm<2, float>,  cudaFuncAttributeMaxDynamicSharedMemorySize, TCG_DSMEM);

    // 1-4: zero, hist, prep, GEMM L1 (launch #4 = ncu capture slot)
    zero_prep<<<(NN * 4 + 255) / 256, 256>>>(p_cur, p_als1, p_ald1, p_als2, p_ald2);
    hist_k<<<(ET + 255) / 256, 256>>>(dst, p_cur);
    prep_all<<<(unsigned)((PREP_TOTAL + 255) / 256), 256>>>(
        x, W1, W2, Wres2, W3, a3s, a3d, p_x0, w1t, w2t, bpt, p_Wt);
    {
        dim3 g(2, (NN + 127) / 128);
        mma_gemm<1, __half><<<g, 256, TCG_DSMEM>>>(p_x0, w1t, p_feat, NN, 128, 256,
                                                   a1s, a1d, p_als1, p_ald1, nullptr);
    }
    // 5-8: CSR build
    scan1<<<196, 256>>>(p_cur, p_bsum);
    scan2<<<1, 256>>>(p_bsum, 196);
    scan3<<<196, 256>>>(p_cur, p_bsum, p_rowptr, p_cur);
    scatter_k<<<(ET + 255) / 256, 256>>>(src, dst, p_cur, p_csr);

    // 9: Layer-1 gather
    agg_fused12<<<(NN + 7) / 8, 256>>>(p_rowptr, p_csr, p_feat, 256, p_als1, p_ald1,
                                       b1, 0, p_x, 0, nullptr, nullptr, nullptr);
    // 10-11: Layer 2
    {
        dim3 g(4, (NN + 127) / 128);
        mma_gemm<1, __half><<<g, 256, TCG_DSMEM>>>(p_x, w2t, p_feat, NN, 256, 512,
                                                   a2s, a2d, p_als2, p_ald2, nullptr);
        agg_fused12<<<(NN + 7) / 8, 256>>>(p_rowptr, p_csr, p_feat, 512, p_als2, p_ald2,
                                           b2, 1, p_x, 1, p_Wt, p_als3, p_ald3);
    }
    // 12-13: Layer 3
    {
        agg_fused3<<<(NN + 7) / 8, 256>>>(p_rowptr, p_csr, p_x, p_als3, p_ald3, p_y);
        dim3 g(1, (NN + 127) / 128);
        mma_gemm<2, float><<<g, 256, TCG_DSMEM>>>(p_y, bpt, out, NN, 1536, 128,
                                                  nullptr, nullptr, nullptr, nullptr, b3);
    }
}

// round 11
// speedup vs baseline: 6.5153x; 1.0233x over previous
#include <cuda_runtime.h>
#include <cuda_fp16.h>
#include <math.h>
#include <stdint.h>

#define NN 50000
#define EE 800000
#define ET (EE + NN)

// ---------------- device scratch (allocation-free) ----------------
__device__ __half g_x0  [(size_t)NN * 128];
__device__ __half g_feat[(size_t)NN * 512];
__device__ __half g_x   [(size_t)NN * 256];
__device__ __half g_y   [(size_t)NN * 1536];
__device__ float  g_als1[NN * 4], g_ald1[NN * 4];
__device__ float  g_als2[NN * 4], g_ald2[NN * 4];
__device__ float  g_als3[NN * 6], g_ald3[NN * 6];
__device__ float  g_Wt  [2 * 256 * 6];
__device__ int    g_csr [ET];
__device__ int    g_rowptr[NN + 1];
__device__ int    g_cur [NN];
__device__ int    g_bsum[256];
__device__ __half g_w1t[256 * 128];
__device__ __half g_w2t[512 * 256];
__device__ __half g_bpt[128 * 1536];

// ---------------- helpers ----------------
__device__ __forceinline__ void mma16816(float* c, const uint32_t* a, const uint32_t* b) {
    asm volatile(
        "mma.sync.aligned.m16n8k16.row.col.f32.f16.f16.f32 "
        "{%0,%1,%2,%3}, {%4,%5,%6,%7}, {%8,%9}, {%0,%1,%2,%3};"
        : "+f"(c[0]), "+f"(c[1]), "+f"(c[2]), "+f"(c[3])
        : "r"(a[0]), "r"(a[1]), "r"(a[2]), "r"(a[3]), "r"(b[0]), "r"(b[1]));
}
__device__ __forceinline__ void ldsm_x4(uint32_t* r, uint32_t addr) {
    asm volatile("ldmatrix.sync.aligned.m8n8.x4.shared.b16 {%0,%1,%2,%3}, [%4];"
                 : "=r"(r[0]), "=r"(r[1]), "=r"(r[2]), "=r"(r[3]) : "r"(addr));
}
__device__ __forceinline__ void ldsm_x2(uint32_t* r, uint32_t addr) {
    asm volatile("ldmatrix.sync.aligned.m8n8.x2.shared.b16 {%0,%1}, [%2];"
                 : "=r"(r[0]), "=r"(r[1]) : "r"(addr));
}
#define CP_ASYNC16(sa, gp) asm volatile("cp.async.ca.shared.global [%0], [%1], 16;" :: "r"(sa), "l"(gp))
#define CP_COMMIT()        asm volatile("cp.async.commit_group;" ::: "memory")
#define CP_WAIT(n)         asm volatile("cp.async.wait_group %0;" :: "n"(n) : "memory")

// ================= HMMA GEMM, 3-stage cp.async pipeline + ldmatrix =================
// MODE 1: CT=__half; store feat + fused attention-logit atomics (cols<256, H=4)
// MODE 2: CT=float;  store sigmoid(acc + bias[col]) to out[row*121+col], cols<121
#define SSTR2 20
#define STAGE_W (2 * 128 * SSTR2)
#define TCG_DSMEM (3 * STAGE_W * 4)
template <int MODE, typename CT>
__global__ void __launch_bounds__(256) mma_gemm(
    const __half* __restrict__ A, const __half* __restrict__ Bt,
    CT* __restrict__ C, int M, int K, int Nc,
    const float* __restrict__ a_src, const float* __restrict__ a_dst,
    float* __restrict__ als, float* __restrict__ ald,
    const float* __restrict__ bias) {
    extern __shared__ uint32_t sh[];
    const int tid = threadIdx.x, wid = tid >> 5, lane = tid & 31;
    const int wm = wid & 1, wn = wid >> 1;
    const int bm = blockIdx.y * 128, bn = blockIdx.x * 128;
    const int g = lane >> 2, tg = lane & 3;

    float acc[4][4][4];
#pragma unroll
    for (int i = 0; i < 4; i++)
#pragma unroll
        for (int j = 0; j < 4; j++)
#pragma unroll
            for (int q = 0; q < 4; q++) acc[i][j][q] = 0.f;

    const int crow = tid >> 1, csegb = (tid & 1) * 2;
    const int grc = min(bm + crow, M - 1);
    const int gn  = bn + crow;
    const __half* arow_p = A  + (size_t)grc * K;
    const __half* brow_p = Bt + (size_t)gn  * K;
    const int nch = K >> 5;
    const uint32_t shbase = (uint32_t)__cvta_generic_to_shared(sh);

    // ldmatrix per-lane byte offsets (relative to stage base)
    uint32_t a_off[4], b_off[4];
#pragma unroll
    for (int mi = 0; mi < 4; mi++) {
        int row = wm * 64 + mi * 16 + (lane & 7) + ((lane >> 3) & 1) * 8;
        a_off[mi] = (uint32_t)(row * SSTR2) * 4 + ((lane >> 4) & 1) * 16;
    }
#pragma unroll
    for (int nj = 0; nj < 4; nj++) {
        int l = lane & 15;
        int row = 128 + wn * 32 + nj * 8 + (l & 7);
        b_off[nj] = (uint32_t)(row * SSTR2) * 4 + ((l >> 3) & 1) * 16;
    }

    auto issue = [&](int st, int k0) {
        uint32_t sa = shbase + (st * STAGE_W + crow * SSTR2) * 4;
        uint32_t sb = sa + 128 * SSTR2 * 4;
        const __half* ap = arow_p + k0;
        const __half* bp = brow_p + k0;
#pragma unroll
        for (int i = 0; i < 2; i++) {
            int seg = csegb + i;
            CP_ASYNC16(sa + seg * 16, ap + seg * 8);
            CP_ASYNC16(sb + seg * 16, bp + seg * 8);
        }
        CP_COMMIT();
    };

    issue(0, 0);
    if (nch > 1) issue(1, 32);
    int wst = 2, rst = 0;
    for (int ch = 0; ch < nch; ch++) {
        if (ch + 1 < nch) CP_WAIT(1); else CP_WAIT(0);
        __syncthreads();
        if (ch + 2 < nch) {
            issue(wst, (ch + 2) << 5);
            if (++wst == 3) wst = 0;
        }
        const uint32_t stb = shbase + rst * STAGE_W * 4;
        if (++rst == 3) rst = 0;
#pragma unroll
        for (int ks = 0; ks < 2; ks++) {
            const uint32_t kbb = ks * 32;   // 8 words = 32 bytes
            uint32_t af[4][4], bf[4][2];
#pragma unroll
            for (int mi = 0; mi < 4; mi++)
                ldsm_x4(af[mi], stb + a_off[mi] + kbb);
#pragma unroll
            for (int nj = 0; nj < 4; nj++)
                ldsm_x2(bf[nj], stb + b_off[nj] + kbb);
#pragma unroll
            for (int mi = 0; mi < 4; mi++)
#pragma unroll
                for (int nj = 0; nj < 4; nj++)
                    mma16816(acc[mi][nj], af[mi], bf[nj]);
        }
    }

    if (MODE == 1) {
#pragma unroll
        for (int mi = 0; mi < 4; mi++) {
            int row = bm + wm * 64 + mi * 16 + g;
#pragma unroll
            for (int nj = 0; nj < 4; nj++) {
                int col = bn + wn * 32 + nj * 8 + tg * 2;
                if (row < M)
                    *(__half2*)((__half*)C + (size_t)row * Nc + col) = __floats2half2_rn(acc[mi][nj][0], acc[mi][nj][1]);
                if (row + 8 < M)
                    *(__half2*)((__half*)C + (size_t)(row + 8) * Nc + col) = __floats2half2_rn(acc[mi][nj][2], acc[mi][nj][3]);
            }
        }
        if (bn + wn * 32 < 256) {
            int h = (bn + wn * 32) >> 6;
            float asv[4][2], adv[4][2];
#pragma unroll
            for (int nj = 0; nj < 4; nj++) {
                int ac = (bn + wn * 32 + nj * 8 + tg * 2) & 63;
                asv[nj][0] = a_src[h * 64 + ac]; asv[nj][1] = a_src[h * 64 + ac + 1];
                adv[nj][0] = a_dst[h * 64 + ac]; adv[nj][1] = a_dst[h * 64 + ac + 1];
            }
#pragma unroll
            for (int mi = 0; mi < 4; mi++) {
                float s0 = 0.f, s1 = 0.f, d0 = 0.f, d1 = 0.f;
#pragma unroll
                for (int nj = 0; nj < 4; nj++) {
                    s0 += acc[mi][nj][0] * asv[nj][0] + acc[mi][nj][1] * asv[nj][1];
                    s1 += acc[mi][nj][2] * asv[nj][0] + acc[mi][nj][3] * asv[nj][1];
                    d0 += acc[mi][nj][0] * adv[nj][0] + acc[mi][nj][1] * adv[nj][1];
                    d1 += acc[mi][nj][2] * adv[nj][0] + acc[mi][nj][3] * adv[nj][1];
                }
#pragma unroll
                for (int off = 1; off < 4; off <<= 1) {
                    s0 += __shfl_xor_sync(0xFFFFFFFFu, s0, off);
                    s1 += __shfl_xor_sync(0xFFFFFFFFu, s1, off);
                    d0 += __shfl_xor_sync(0xFFFFFFFFu, d0, off);
                    d1 += __shfl_xor_sync(0xFFFFFFFFu, d1, off);
                }
                if (tg == 0) {
                    int r0 = bm + wm * 64 + mi * 16 + g;
                    if (r0 < M) { atomicAdd(&als[r0 * 4 + h], s0); atomicAdd(&ald[r0 * 4 + h], d0); }
                    if (r0 + 8 < M) { atomicAdd(&als[(r0 + 8) * 4 + h], s1); atomicAdd(&ald[(r0 + 8) * 4 + h], d1); }
                }
            }
        }
    } else {
#pragma unroll
        for (int mi = 0; mi < 4; mi++) {
            int r0 = bm + wm * 64 + mi * 16 + g;
#pragma unroll
            for (int nj = 0; nj < 4; nj++) {
                int col = bn + wn * 32 + nj * 8 + tg * 2;
#pragma unroll
                for (int q = 0; q < 4; q++) {
                    int row = r0 + (q >> 1) * 8;
                    int cc  = col + (q & 1);
                    if (row < M && cc < 121) {
                        float v = acc[mi][nj][q] + bias[cc];
                        ((float*)C)[(size_t)row * 121 + cc] = 1.f / (1.f + __expf(-v));
                    }
                }
            }
        }
    }
}

// ================= fused prep =================
#define N_X0  ((long)NN * 128)
#define N_W1  (256L * 128)
#define N_W2  (256L * 256)
#define N_BP  (128L * 1536)
#define N_WT  (2L * 256 * 6)
__global__ void prep_all(const float* __restrict__ x, const float* __restrict__ W1,
                         const float* __restrict__ W2, const float* __restrict__ Wres2,
                         const float* __restrict__ W3, const float* __restrict__ a3s,
                         const float* __restrict__ a3d,
                         __half* __restrict__ x0, __half* __restrict__ w1t,
                         __half* __restrict__ w2t, __half* __restrict__ bpt,
                         float* __restrict__ Wt) {
    long i = (long)blockIdx.x * blockDim.x + threadIdx.x;
    if (i < N_X0) { x0[i] = __float2half(x[i]); return; }
    i -= N_X0;
    if (i < N_W1) {
        int n = (int)(i / 128), k = (int)(i % 128);
        w1t[i] = __float2half(W1[(size_t)k * 256 + n]); return;
    }
    i -= N_W1;
    if (i < N_W2) {
        int n = (int)(i / 256), k = (int)(i % 256);
        w2t[i] = __float2half(W2[(size_t)k * 256 + n]); return;
    }
    i -= N_W2;
    if (i < N_W2) {
        int n = (int)(i / 256), k = (int)(i % 256);
        w2t[65536 + i] = __float2half(Wres2[(size_t)k * 256 + n]); return;
    }
    i -= N_W2;
    if (i < N_BP) {
        int n = (int)(i / 1536), kk = (int)(i % 1536);
        int h_ = kk >> 8, k = kk & 255;
        float v = (n < 121) ? W3[(size_t)k * 726 + h_ * 121 + n] * (1.f / 6.f) : 0.f;
        bpt[i] = __float2half(v); return;
    }
    i -= N_BP;
    if (i < N_WT) {
        int side = (int)(i / (256 * 6));
        int r = (int)(i % (256 * 6));
        int k = r / 6, h = r % 6;
        const float* av = side ? a3d : a3s;
        float s = 0.f;
        for (int o = 0; o < 121; o++)
            s += W3[(size_t)k * 726 + h * 121 + o] * av[h * 121 + o];
        Wt[(size_t)side * 1536 + k * 6 + h] = s;
    }
}
#define PREP_TOTAL (N_X0 + N_W1 + 2 * N_W2 + N_BP + N_WT)

// ================= zero =================
__global__ void zero_prep(int* __restrict__ cur, float* __restrict__ a1,
                          float* __restrict__ b1, float* __restrict__ a2,
                          float* __restrict__ b2) {
    int i = blockIdx.x * blockDim.x + threadIdx.x;
    if (i < NN) cur[i] = 0;
    if (i < NN * 4) { a1[i] = 0.f; b1[i] = 0.f; a2[i] = 0.f; b2[i] = 0.f; }
}

// ================= CSR build =================
__global__ void hist_k(const int* __restrict__ dst, int* __restrict__ cur) {
    int e = blockIdx.x * blockDim.x + threadIdx.x;
    if (e >= ET) return;
    int d = (e < EE) ? dst[e] : e - EE;
    atomicAdd(&cur[d], 1);
}
__global__ void scan1(const int* __restrict__ deg, int* __restrict__ bsum) {
    __shared__ int sh[256];
    int i = blockIdx.x * 256 + threadIdx.x;
    sh[threadIdx.x] = (i < NN) ? deg[i] : 0;
    __syncthreads();
    for (int o = 128; o; o >>= 1) {
        if (threadIdx.x < o) sh[threadIdx.x] += sh[threadIdx.x + o];
        __syncthreads();
    }
    if (threadIdx.x == 0) bsum[blockIdx.x] = sh[0];
}
__global__ void scan2(int* __restrict__ bsum, int nb) {
    __shared__ int sh[256];
    int t = threadIdx.x;
    int v = (t < nb) ? bsum[t] : 0;
    sh[t] = v;
    __syncthreads();
    for (int o = 1; o < 256; o <<= 1) {
        int x2 = (t >= o) ? sh[t - o] : 0;
        __syncthreads();
        sh[t] += x2;
        __syncthreads();
    }
    if (t < nb) bsum[t] = sh[t] - v;
}
__global__ void scan3(const int* __restrict__ deg, const int* __restrict__ bsum,
                      int* __restrict__ rowptr, int* __restrict__ cur) {
    __shared__ int sh[256];
    int i = blockIdx.x * 256 + threadIdx.x;
    int v = (i < NN) ? deg[i] : 0;
    sh[threadIdx.x] = v;
    __syncthreads();
    for (int o = 1; o < 256; o <<= 1) {
        int t = (threadIdx.x >= o) ? sh[threadIdx.x - o] : 0;
        __syncthreads();
        sh[threadIdx.x] += t;
        __syncthreads();
    }
    int excl = sh[threadIdx.x] - v + bsum[blockIdx.x];
    if (i < NN) { rowptr[i] = excl; cur[i] = excl; }
    if (i == NN - 1) rowptr[NN] = excl + v;
}
__global__ void scatter_k(const int* __restrict__ src, const int* __restrict__ dst,
                          int* __restrict__ cur, int* __restrict__ csr) {
    int e = blockIdx.x * blockDim.x + threadIdx.x;
    if (e >= ET) return;
    int s, d;
    if (e < EE) { s = src[e]; d = dst[e]; } else { s = e - EE; d = s; }
    int pos = atomicAdd(&cur[d], 1);
    csr[pos] = s;
}

// ================= layers 1/2: fused gather-aggregate (+optional L3 logits) =================
__global__ void __launch_bounds__(256) agg_fused12(
    const int* __restrict__ rowptr, const int* __restrict__ csr,
    const __half* __restrict__ feat, int fstride,
    const float* __restrict__ als, const float* __restrict__ ald,
    const float* __restrict__ bias, int has_res, __half* __restrict__ out,
    int do_l3, const float* __restrict__ Wt,
    float* __restrict__ als3, float* __restrict__ ald3) {
    int n    = blockIdx.x * 8 + (threadIdx.x >> 5);
    int lane = threadIdx.x & 31;
    if (n >= NN) return;
    int col = lane * 8;
    int hl  = lane >> 3;
    bool wlane = (lane & 7) == 0;
    float aldh = wlane ? ald[n * 4 + hl] : 0.f;
    int beg = rowptr[n], end = rowptr[n + 1];
    float acc[8] = {0.f, 0.f, 0.f, 0.f, 0.f, 0.f, 0.f, 0.f};
    float denom = 0.f;
    int p = beg;
    for (; p + 4 <= end; p += 4) {
        int s0 = __ldg(&csr[p]),     s1 = __ldg(&csr[p + 1]);
        int s2 = __ldg(&csr[p + 2]), s3 = __ldg(&csr[p + 3]);
        float wv0 = 0.f, wv1 = 0.f, wv2 = 0.f, wv3 = 0.f;
        if (wlane) {
            float v0 = als[s0 * 4 + hl] + aldh; v0 = v0 > 0.f ? v0 : 0.2f * v0;
            float v1 = als[s1 * 4 + hl] + aldh; v1 = v1 > 0.f ? v1 : 0.2f * v1;
            float v2 = als[s2 * 4 + hl] + aldh; v2 = v2 > 0.f ? v2 : 0.2f * v2;
            float v3 = als[s3 * 4 + hl] + aldh; v3 = v3 > 0.f ? v3 : 0.2f * v3;
            wv0 = __expf(v0); wv1 = __expf(v1); wv2 = __expf(v2); wv3 = __expf(v3);
        }
        uint4 r0 = *(const uint4*)(feat + (size_t)s0 * fstride + col);
        uint4 r1 = *(const uint4*)(feat + (size_t)s1 * fstride + col);
        uint4 r2 = *(const uint4*)(feat + (size_t)s2 * fstride + col);
        uint4 r3 = *(const uint4*)(feat + (size_t)s3 * fstride + col);
        float w0 = __shfl_sync(0xFFFFFFFFu, wv0, lane & 24);
        float w1 = __shfl_sync(0xFFFFFFFFu, wv1, lane & 24);
        float w2 = __shfl_sync(0xFFFFFFFFu, wv2, lane & 24);
        float w3 = __shfl_sync(0xFFFFFFFFu, wv3, lane & 24);
        uint32_t q0[4] = {r0.x, r0.y, r0.z, r0.w};
        uint32_t q1[4] = {r1.x, r1.y, r1.z, r1.w};
        uint32_t q2[4] = {r2.x, r2.y, r2.z, r2.w};
        uint32_t q3[4] = {r3.x, r3.y, r3.z, r3.w};
#pragma unroll
        for (int i = 0; i < 4; i++) {
            float2 f0 = __half22float2(*(__half2*)&q0[i]);
            float2 f1 = __half22float2(*(__half2*)&q1[i]);
            float2 f2 = __half22float2(*(__half2*)&q2[i]);
            float2 f3 = __half22float2(*(__half2*)&q3[i]);
            acc[2 * i]     += f0.x * w0 + f1.x * w1 + f2.x * w2 + f3.x * w3;
            acc[2 * i + 1] += f0.y * w0 + f1.y * w1 + f2.y * w2 + f3.y * w3;
        }
        denom += w0 + w1 + w2 + w3;
    }
    for (; p < end; p++) {
        int s = __ldg(&csr[p]);
        float wv = 0.f;
        if (wlane) {
            float v = als[s * 4 + hl] + aldh;
            v = v > 0.f ? v : 0.2f * v;
            wv = __expf(v);
        }
        float w = __shfl_sync(0xFFFFFFFFu, wv, lane & 24);
        uint4 r = *(const uint4*)(feat + (size_t)s * fstride + col);
        uint32_t q[4] = {r.x, r.y, r.z, r.w};
#pragma unroll
        for (int i = 0; i < 4; i++) {
            float2 f = __half22float2(*(__half2*)&q[i]);
            acc[2 * i] += f.x * w; acc[2 * i + 1] += f.y * w;
        }
        denom += w;
    }
    float inv = 1.f / (denom + 1e-16f);
    float4 b0 = *(const float4*)(bias + col), b1 = *(const float4*)(bias + col + 4);
    float bb[8] = {b0.x, b0.y, b0.z, b0.w, b1.x, b1.y, b1.z, b1.w};
    float rr[8] = {0.f, 0.f, 0.f, 0.f, 0.f, 0.f, 0.f, 0.f};
    if (has_res) {
        uint4 r = *(const uint4*)(feat + (size_t)n * fstride + 256 + col);
        uint32_t q[4] = {r.x, r.y, r.z, r.w};
#pragma unroll
        for (int i = 0; i < 4; i++) {
            float2 f = __half22float2(*(__half2*)&q[i]);
            rr[2 * i] = f.x; rr[2 * i + 1] = f.y;
        }
    }
    float v8[8];
    uint32_t o[4];
#pragma unroll
    for (int i = 0; i < 4; i++) {
        float vx = acc[2 * i] * inv + bb[2 * i] + rr[2 * i];
        float vy = acc[2 * i + 1] * inv + bb[2 * i + 1] + rr[2 * i + 1];
        vx = vx > 0.f ? vx : (__expf(vx) - 1.f);
        vy = vy > 0.f ? vy : (__expf(vy) - 1.f);
        v8[2 * i] = vx; v8[2 * i + 1] = vy;
        __half2 hv = __floats2half2_rn(vx, vy);
        o[i] = *(uint32_t*)&hv;
    }
    *(uint4*)(out + (size_t)n * 256 + col) = make_uint4(o[0], o[1], o[2], o[3]);

    if (do_l3) {
        float ps[12];
#pragma unroll
        for (int j = 0; j < 12; j++) ps[j] = 0.f;
#pragma unroll
        for (int i = 0; i < 8; i++) {
            const float* ws = Wt + (size_t)(col + i) * 6;
            const float* wd = ws + 1536;
            float xv = v8[i];
#pragma unroll
            for (int j = 0; j < 6; j++) {
                ps[j]     += xv * ws[j];
                ps[6 + j] += xv * wd[j];
            }
        }
#pragma unroll
        for (int j = 0; j < 12; j++)
#pragma unroll
            for (int off = 16; off; off >>= 1)
                ps[j] += __shfl_down_sync(0xFFFFFFFFu, ps[j], off);
        if (lane == 0) {
#pragma unroll
            for (int j = 0; j < 6; j++) {
                als3[n * 6 + j] = ps[j];
                ald3[n * 6 + j] = ps[6 + j];
            }
        }
    }
}

// ================= layer 3: fused gather, 1 warp per node =================
__global__ void __launch_bounds__(256) agg_fused3(
    const int* __restrict__ rowptr, const int* __restrict__ csr,
    const __half* __restrict__ x, const float* __restrict__ als,
    const float* __restrict__ ald, __half* __restrict__ y) {
    int n    = blockIdx.x * 8 + (threadIdx.x >> 5);
    int lane = threadIdx.x & 31;
    if (n >= NN) return;
    int col = lane * 8;
    float acc[6][8];
    float den[6];
#pragma unroll
    for (int h = 0; h < 6; h++) {
        den[h] = 0.f;
#pragma unroll
        for (int j = 0; j < 8; j++) acc[h][j] = 0.f;
    }
    float aldl = (lane < 6) ? ald[n * 6 + lane] : 0.f;
    int beg = rowptr[n], end = rowptr[n + 1];
    int p = beg;
    for (; p + 2 <= end; p += 2) {
        int s0 = __ldg(&csr[p]), s1 = __ldg(&csr[p + 1]);
        float wv0 = 0.f, wv1 = 0.f;
        if (lane < 6) {
            float v0 = als[s0 * 6 + lane] + aldl; v0 = v0 > 0.f ? v0 : 0.2f * v0;
            float v1 = als[s1 * 6 + lane] + aldl; v1 = v1 > 0.f ? v1 : 0.2f * v1;
            wv0 = __expf(v0); wv1 = __expf(v1);
        }
        uint4 r0 = *(const uint4*)(x + (size_t)s0 * 256 + col);
        uint4 r1 = *(const uint4*)(x + (size_t)s1 * 256 + col);
        uint32_t q0[4] = {r0.x, r0.y, r0.z, r0.w};
        uint32_t q1[4] = {r1.x, r1.y, r1.z, r1.w};
        float f0[8], f1[8];
#pragma unroll
        for (int i = 0; i < 4; i++) {
            float2 t0 = __half22float2(*(__half2*)&q0[i]);
            float2 t1 = __half22float2(*(__half2*)&q1[i]);
            f0[2 * i] = t0.x; f0[2 * i + 1] = t0.y;
            f1[2 * i] = t1.x; f1[2 * i + 1] = t1.y;
        }
#pragma unroll
        for (int h = 0; h < 6; h++) {
            float w0 = __shfl_sync(0xFFFFFFFFu, wv0, h);
            float w1 = __shfl_sync(0xFFFFFFFFu, wv1, h);
            den[h] += w0 + w1;
#pragma unroll
            for (int j = 0; j < 8; j++) acc[h][j] += f0[j] * w0 + f1[j] * w1;
        }
    }
    if (p < end) {
        int s = __ldg(&csr[p]);
        float wv = 0.f;
        if (lane < 6) {
            float v = als[s * 6 + lane] + aldl;
            v = v > 0.f ? v : 0.2f * v;
            wv = __expf(v);
        }
        uint4 r = *(const uint4*)(x + (size_t)s * 256 + col);
        uint32_t q[4] = {r.x, r.y, r.z, r.w};
        float f[8];
#pragma unroll
        for (int i = 0; i < 4; i++) {
            float2 t = __half22float2(*(__half2*)&q[i]);
            f[2 * i] = t.x; f[2 * i + 1] = t.y;
        }
#pragma unroll
        for (int h = 0; h < 6; h++) {
            float w = __shfl_sync(0xFFFFFFFFu, wv, h);
            den[h] += w;
#pragma unroll
            for (int j = 0; j < 8; j++) acc[h][j] += f[j] * w;
        }
    }
#pragma unroll
    for (int h = 0; h < 6; h++) {
        float inv = 1.f / (den[h] + 1e-16f);
        uint32_t o[4];
#pragma unroll
        for (int i = 0; i < 4; i++) {
            __half2 hv = __floats2half2_rn(acc[h][2 * i] * inv, acc[h][2 * i + 1] * inv);
            o[i] = *(uint32_t*)&hv;
        }
        *(uint4*)(y + ((size_t)n * 6 + h) * 256 + col) = make_uint4(o[0], o[1], o[2], o[3]);
    }
}

// ================= host driver =================
extern "C" void kernel_launch(void* const* d_in, const int* in_sizes, int n_in,
                              void* d_out, int out_size) {
    const float* x     = (const float*)d_in[0];
    const int*   src   = (const int*)  d_in[1];
    const int*   dst   = (const int*)  d_in[2];
    const float* W1    = (const float*)d_in[3];
    const float* a1s   = (const float*)d_in[4];
    const float* a1d   = (const float*)d_in[5];
    const float* b1    = (const float*)d_in[6];
    const float* W2    = (const float*)d_in[7];
    const float* a2s   = (const float*)d_in[8];
    const float* a2d   = (const float*)d_in[9];
    const float* b2    = (const float*)d_in[10];
    const float* Wres2 = (const float*)d_in[11];
    const float* W3    = (const float*)d_in[12];
    const float* a3s   = (const float*)d_in[13];
    const float* a3d   = (const float*)d_in[14];
    const float* b3    = (const float*)d_in[15];
    float* out = (float*)d_out;

    __half *p_x0, *p_feat, *p_x, *p_y, *w1t, *w2t, *bpt;
    float *p_als1, *p_ald1, *p_als2, *p_ald2, *p_als3, *p_ald3, *p_Wt;
    int *p_csr, *p_rowptr, *p_cur, *p_bsum;
    cudaGetSymbolAddress((void**)&p_x0,     g_x0);
    cudaGetSymbolAddress((void**)&p_feat,   g_feat);
    cudaGetSymbolAddress((void**)&p_x,      g_x);
    cudaGetSymbolAddress((void**)&p_y,      g_y);
    cudaGetSymbolAddress((void**)&p_als1,   g_als1);
    cudaGetSymbolAddress((void**)&p_ald1,   g_ald1);
    cudaGetSymbolAddress((void**)&p_als2,   g_als2);
    cudaGetSymbolAddress((void**)&p_ald2,   g_ald2);
    cudaGetSymbolAddress((void**)&p_als3,   g_als3);
    cudaGetSymbolAddress((void**)&p_ald3,   g_ald3);
    cudaGetSymbolAddress((void**)&p_Wt,     g_Wt);
    cudaGetSymbolAddress((void**)&p_csr,    g_csr);
    cudaGetSymbolAddress((void**)&p_rowptr, g_rowptr);
    cudaGetSymbolAddress((void**)&p_cur,    g_cur);
    cudaGetSymbolAddress((void**)&p_bsum,   g_bsum);
    cudaGetSymbolAddress((void**)&w1t, g_w1t);
    cudaGetSymbolAddress((void**)&w2t, g_w2t);
    cudaGetSymbolAddress((void**)&bpt, g_bpt);

    cudaFuncSetAttribute(mma_gemm<1, __half>, cudaFuncAttributeMaxDynamicSharedMemorySize, TCG_DSMEM);
    cudaFuncSetAttribute(mma_gemm<2, float>,  cudaFuncAttributeMaxDynamicSharedMemorySize, TCG_DSMEM);

    // 1-4: zero, hist, prep, GEMM L1 (launch #4 = ncu capture slot)
    zero_prep<<<(NN * 4 + 255) / 256, 256>>>(p_cur, p_als1, p_ald1, p_als2, p_ald2);
    hist_k<<<(ET + 255) / 256, 256>>>(dst, p_cur);
    prep_all<<<(unsigned)((PREP_TOTAL + 255) / 256), 256>>>(
        x, W1, W2, Wres2, W3, a3s, a3d, p_x0, w1t, w2t, bpt, p_Wt);
    {
        dim3 g(2, (NN + 127) / 128);
        mma_gemm<1, __half><<<g, 256, TCG_DSMEM>>>(p_x0, w1t, p_feat, NN, 128, 256,
                                                   a1s, a1d, p_als1, p_ald1, nullptr);
    }
    // 5-8: CSR build
    scan1<<<196, 256>>>(p_cur, p_bsum);
    scan2<<<1, 256>>>(p_bsum, 196);
    scan3<<<196, 256>>>(p_cur, p_bsum, p_rowptr, p_cur);
    scatter_k<<<(ET + 255) / 256, 256>>>(src, dst, p_cur, p_csr);

    // 9: Layer-1 gather
    agg_fused12<<<(NN + 7) / 8, 256>>>(p_rowptr, p_csr, p_feat, 256, p_als1, p_ald1,
                                       b1, 0, p_x, 0, nullptr, nullptr, nullptr);
    // 10-11: Layer 2
    {
        dim3 g(4, (NN + 127) / 128);
        mma_gemm<1, __half><<<g, 256, TCG_DSMEM>>>(p_x, w2t, p_feat, NN, 256, 512,
                                                   a2s, a2d, p_als2, p_ald2, nullptr);
        agg_fused12<<<(NN + 7) / 8, 256>>>(p_rowptr, p_csr, p_feat, 512, p_als2, p_ald2,
                                           b2, 1, p_x, 1, p_Wt, p_als3, p_ald3);
    }
    // 12-13: Layer 3
    {
        agg_fused3<<<(NN + 7) / 8, 256>>>(p_rowptr, p_csr, p_x, p_als3, p_ald3, p_y);
        dim3 g(1, (NN + 127) / 128);
        mma_gemm<2, float><<<g, 256, TCG_DSMEM>>>(p_y, bpt, out, NN, 1536, 128,
                                                  nullptr, nullptr, nullptr, nullptr, b3);
    }
}